// round 2
// baseline (speedup 1.0000x reference)
#include <cuda_runtime.h>

// Problem constants
#define HEADS 16
#define HD    64
#define SEQ   2048
#define BATCH 2
#define KDIM  1024
#define NTOT  3072   // 3 * HEADS * HD
#define MTOT  4096   // BATCH * SEQ

// Attention smem pitch (floats): 68 = 64 data + 4 pad -> lane stride 68 mod 32 == 4
#define PITCH  68
#define PITCH4 17
#define ATTN_SMEM_BYTES (3 * 64 * PITCH * 4)

// Scratch: Q/K/V in [b, h, n, d] layout
__device__ float g_q[BATCH * HEADS * SEQ * HD];
__device__ float g_k[BATCH * HEADS * SEQ * HD];
__device__ float g_v[BATCH * HEADS * SEQ * HD];

// ---------------------------------------------------------------------------
// Kernel 1: QKV projection. C[4096,3072] = X[4096,1024] @ W[1024,3072],
// scattered directly into g_q/g_k/g_v with [b,h,n,d] layout.
// Classic 128x128x8 SGEMM, 256 threads, 8x8 per-thread microtile.
// ---------------------------------------------------------------------------
__global__ __launch_bounds__(256) void qkv_gemm(const float* __restrict__ A,
                                                const float* __restrict__ B) {
    __shared__ float As[8 * 128];   // transposed: As[k][m]
    __shared__ float Bs[8 * 128];   // Bs[k][n]

    const int tid   = threadIdx.x;
    const int mBase = blockIdx.y * 128;
    const int nBase = blockIdx.x * 128;

    const int arow = tid >> 1;          // 0..127
    const int acol = (tid & 1) * 4;     // 0 or 4
    const int brow = tid >> 5;          // 0..7
    const int bcol = (tid & 31) * 4;    // 0..124
    const int ty   = tid >> 4;          // 0..15
    const int tx   = tid & 15;          // 0..15

    float c[8][8];
#pragma unroll
    for (int i = 0; i < 8; i++)
#pragma unroll
        for (int j = 0; j < 8; j++) c[i][j] = 0.0f;

    for (int k0 = 0; k0 < KDIM; k0 += 8) {
        float4 av = *(const float4*)(A + (size_t)(mBase + arow) * KDIM + k0 + acol);
        As[(acol + 0) * 128 + arow] = av.x;
        As[(acol + 1) * 128 + arow] = av.y;
        As[(acol + 2) * 128 + arow] = av.z;
        As[(acol + 3) * 128 + arow] = av.w;
        *(float4*)(Bs + brow * 128 + bcol) =
            *(const float4*)(B + (size_t)(k0 + brow) * NTOT + nBase + bcol);
        __syncthreads();

#pragma unroll
        for (int kk = 0; kk < 8; kk++) {
            float a[8], b[8];
#pragma unroll
            for (int i = 0; i < 8; i++) a[i] = As[kk * 128 + ty * 8 + i];
#pragma unroll
            for (int j = 0; j < 8; j++) b[j] = Bs[kk * 128 + tx * 8 + j];
#pragma unroll
            for (int i = 0; i < 8; i++)
#pragma unroll
                for (int j = 0; j < 8; j++) c[i][j] += a[i] * b[j];
        }
        __syncthreads();
    }

    // Epilogue: scatter into q/k/v with [b,h,n,d] layout.
    // col0 is a multiple of 8, so third/head/d-base are constant per thread
    // and the 8 columns are contiguous in d.
    const int col0  = nBase + tx * 8;
    const int third = col0 >> 10;             // 0=q, 1=k, 2=v
    const int h     = (col0 & 1023) >> 6;
    const int dbase = col0 & 63;
    float* dst = (third == 0) ? g_q : ((third == 1) ? g_k : g_v);

#pragma unroll
    for (int i = 0; i < 8; i++) {
        const int row = mBase + ty * 8 + i;
        const int b_  = row >> 11;            // /2048
        const int n_  = row & 2047;
        float* p = dst + ((size_t)((b_ * HEADS + h) * SEQ + n_)) * HD + dbase;
        float4 o0 = make_float4(c[i][0], c[i][1], c[i][2], c[i][3]);
        float4 o1 = make_float4(c[i][4], c[i][5], c[i][6], c[i][7]);
        *(float4*)(p)     = o0;
        *(float4*)(p + 4) = o1;
    }
}

// ---------------------------------------------------------------------------
// Kernel 2: flash attention. One block = one (b,h) x 64-query tile.
// Streams K/V in 64-key tiles; online softmax; P staged through smem
// (reusing the K tile region) for the PV GEMM.
// Thread map: ty=tid/16 owns query rows r0..r0+3; tx=tid%16.
//   S/P key columns owned interleaved: {tx, tx+16, tx+32, tx+48}
//   output d columns owned contiguous:  tx*4..tx*4+3
// ---------------------------------------------------------------------------
__global__ __launch_bounds__(256) void flash_attn(float* __restrict__ out) {
    extern __shared__ float smem[];
    float* Qs  = smem;                  // 64 rows x PITCH
    float* KPs = smem + 64 * PITCH;     // K tile, then reused for P
    float* Vs  = smem + 2 * 64 * PITCH;

    const int tid = threadIdx.x;
    const int bh  = blockIdx.y;         // b*HEADS + h
    const int q0  = blockIdx.x * 64;
    const int ty  = tid >> 4;
    const int tx  = tid & 15;
    const int r0  = ty * 4;

    // Load Q tile (contiguous 64x64 chunk), pre-scaled by 1/sqrt(d)
    {
        const float4* g = (const float4*)(g_q + ((size_t)bh * SEQ + q0) * HD);
        for (int i = tid; i < 1024; i += 256) {
            float4 v = g[i];
            v.x *= 0.125f; v.y *= 0.125f; v.z *= 0.125f; v.w *= 0.125f;
            ((float4*)Qs)[(i >> 4) * PITCH4 + (i & 15)] = v;
        }
    }

    float m[4], l[4], acc[4][4];
#pragma unroll
    for (int i = 0; i < 4; i++) {
        m[i] = -1e30f; l[i] = 0.0f;
#pragma unroll
        for (int j = 0; j < 4; j++) acc[i][j] = 0.0f;
    }

    for (int t = 0; t < 32; t++) {
        __syncthreads();   // previous tile fully consumed
        {
            const float4* gk = (const float4*)(g_k + ((size_t)bh * SEQ + t * 64) * HD);
            const float4* gv = (const float4*)(g_v + ((size_t)bh * SEQ + t * 64) * HD);
            for (int i = tid; i < 1024; i += 256) {
                const int off = (i >> 4) * PITCH4 + (i & 15);
                ((float4*)KPs)[off] = gk[i];
                ((float4*)Vs)[off]  = gv[i];
            }
        }
        __syncthreads();

        // S = Q K^T for this tile (Q already scaled)
        float s[4][4];
#pragma unroll
        for (int i = 0; i < 4; i++)
#pragma unroll
            for (int j = 0; j < 4; j++) s[i][j] = 0.0f;

#pragma unroll
        for (int d4 = 0; d4 < 16; d4++) {
            float4 qv[4], kv[4];
#pragma unroll
            for (int i = 0; i < 4; i++)
                qv[i] = ((const float4*)Qs)[(r0 + i) * PITCH4 + d4];
#pragma unroll
            for (int j = 0; j < 4; j++)
                kv[j] = ((const float4*)KPs)[(tx + 16 * j) * PITCH4 + d4];
#pragma unroll
            for (int i = 0; i < 4; i++)
#pragma unroll
                for (int j = 0; j < 4; j++)
                    s[i][j] += qv[i].x * kv[j].x + qv[i].y * kv[j].y +
                               qv[i].z * kv[j].z + qv[i].w * kv[j].w;
        }

        // Online softmax (per query row, reduced over 16 lanes of same ty)
        float p[4][4];
#pragma unroll
        for (int i = 0; i < 4; i++) {
            float mr = fmaxf(fmaxf(s[i][0], s[i][1]), fmaxf(s[i][2], s[i][3]));
#pragma unroll
            for (int off = 8; off; off >>= 1)
                mr = fmaxf(mr, __shfl_xor_sync(0xffffffffu, mr, off, 16));
            const float mn    = fmaxf(m[i], mr);
            const float alpha = __expf(m[i] - mn);
            m[i] = mn;
            float rs = 0.0f;
#pragma unroll
            for (int j = 0; j < 4; j++) { p[i][j] = __expf(s[i][j] - mn); rs += p[i][j]; }
#pragma unroll
            for (int off = 8; off; off >>= 1)
                rs += __shfl_xor_sync(0xffffffffu, rs, off, 16);
            l[i] = l[i] * alpha + rs;
#pragma unroll
            for (int j = 0; j < 4; j++) acc[i][j] *= alpha;
        }

        __syncthreads();   // all K reads done -> safe to overwrite with P
#pragma unroll
        for (int i = 0; i < 4; i++)
#pragma unroll
            for (int j = 0; j < 4; j++)
                KPs[(r0 + i) * PITCH + tx + 16 * j] = p[i][j];
        __syncthreads();

        // acc += P @ V   (acc columns = d = tx*4 + j)
#pragma unroll
        for (int k4 = 0; k4 < 16; k4++) {
            float4 pv[4];
#pragma unroll
            for (int i = 0; i < 4; i++)
                pv[i] = ((const float4*)KPs)[(r0 + i) * PITCH4 + k4];
#pragma unroll
            for (int kk = 0; kk < 4; kk++) {
                const float4 vv = ((const float4*)Vs)[(k4 * 4 + kk) * PITCH4 + tx];
#pragma unroll
                for (int i = 0; i < 4; i++) {
                    const float pk = ((const float*)&pv[i])[kk];
                    acc[i][0] += pk * vv.x;
                    acc[i][1] += pk * vv.y;
                    acc[i][2] += pk * vv.z;
                    acc[i][3] += pk * vv.w;
                }
            }
        }
    }

    // Normalize and store: out is [b, h, n, d] contiguous
#pragma unroll
    for (int i = 0; i < 4; i++) {
        const float inv = 1.0f / l[i];
        float4 o = make_float4(acc[i][0] * inv, acc[i][1] * inv,
                               acc[i][2] * inv, acc[i][3] * inv);
        ((float4*)out)[((size_t)bh * SEQ + q0 + r0 + i) * (HD / 4) + tx] = o;
    }
}

// ---------------------------------------------------------------------------
extern "C" void kernel_launch(void* const* d_in, const int* in_sizes, int n_in,
                              void* d_out, int out_size) {
    const float* x = (const float*)d_in[0];   // [2, 2048, 1024]
    const float* w = (const float*)d_in[1];   // [1024, 3072]
    float* out = (float*)d_out;               // [2, 16, 2048, 64]

    cudaFuncSetAttribute(flash_attn, cudaFuncAttributeMaxDynamicSharedMemorySize,
                         ATTN_SMEM_BYTES);

    qkv_gemm<<<dim3(NTOT / 128, MTOT / 128), 256>>>(x, w);
    flash_attn<<<dim3(SEQ / 64, BATCH * HEADS), 256, ATTN_SMEM_BYTES>>>(out);
}

// round 4
// speedup vs baseline: 1.4954x; 1.4954x over previous
#include <cuda_runtime.h>
#include <cuda_bf16.h>
#include <mma.h>
using namespace nvcuda;

#define HEADS 16
#define HD    64
#define SEQ   2048
#define BATCH 2
#define KDIM  1024
#define NTOT  3072
#define MTOT  4096

// Scratch: Q/K/V in [b, h, n, d] layout
__device__ float g_q[BATCH * HEADS * SEQ * HD];
__device__ float g_k[BATCH * HEADS * SEQ * HD];
__device__ float g_v[BATCH * HEADS * SEQ * HD];

typedef wmma::fragment<wmma::matrix_a, 16, 16, 16, __nv_bfloat16, wmma::row_major> FragA;
typedef wmma::fragment<wmma::matrix_b, 16, 16, 16, __nv_bfloat16, wmma::row_major> FragBR;
typedef wmma::fragment<wmma::matrix_b, 16, 16, 16, __nv_bfloat16, wmma::col_major> FragBC;
typedef wmma::fragment<wmma::accumulator, 16, 16, 16, float> FragC;

__device__ __forceinline__ void split_bf16(float x, __nv_bfloat16& hi, __nv_bfloat16& lo) {
    hi = __float2bfloat16(x);
    lo = __float2bfloat16(x - __bfloat162float(hi));
}

// ---------------------------------------------------------------------------
// Kernel 1: QKV projection with bf16x3 tensor cores.
// C[4096,3072] = X[4096,1024] @ W[1024,3072], tile 128x128, k-step 32,
// 8 warps (4m x 2n), warp tile 32x64, scattered into [b,h,n,d] q/k/v.
// ---------------------------------------------------------------------------
__global__ __launch_bounds__(256) void qkv_gemm(const float* __restrict__ A,
                                                const float* __restrict__ B) {
    __shared__ __nv_bfloat16 Ah[128 * 40], Al[128 * 40];
    __shared__ __nv_bfloat16 Bh[32 * 136], Bl[32 * 136];

    const int tid   = threadIdx.x;
    const int mBase = blockIdx.y * 128;
    const int nBase = blockIdx.x * 128;
    const int wid   = tid >> 5;
    const int wm    = wid >> 1;   // 0..3 -> m offset wm*32
    const int wn    = wid & 1;    // 0..1 -> n offset wn*64

    FragC c[2][4];
#pragma unroll
    for (int mi = 0; mi < 2; mi++)
#pragma unroll
        for (int ni = 0; ni < 4; ni++) wmma::fill_fragment(c[mi][ni], 0.0f);

    for (int k0 = 0; k0 < KDIM; k0 += 32) {
        // Load A tile 128x32 floats = 1024 float4: 4 per thread
#pragma unroll
        for (int i = 0; i < 4; i++) {
            const int e   = tid + i * 256;
            const int row = e >> 3, c4 = e & 7;     // row 0..127, c4 0..7
            float4 v = *(const float4*)(A + (size_t)(mBase + row) * KDIM + k0 + c4 * 4);
            __nv_bfloat16 h, l;
            split_bf16(v.x, h, l); Ah[row * 40 + c4 * 4 + 0] = h; Al[row * 40 + c4 * 4 + 0] = l;
            split_bf16(v.y, h, l); Ah[row * 40 + c4 * 4 + 1] = h; Al[row * 40 + c4 * 4 + 1] = l;
            split_bf16(v.z, h, l); Ah[row * 40 + c4 * 4 + 2] = h; Al[row * 40 + c4 * 4 + 2] = l;
            split_bf16(v.w, h, l); Ah[row * 40 + c4 * 4 + 3] = h; Al[row * 40 + c4 * 4 + 3] = l;
        }
        // Load B tile 32x128 floats = 1024 float4: 4 per thread
#pragma unroll
        for (int i = 0; i < 4; i++) {
            const int e   = tid + i * 256;
            const int row = e >> 5, c4 = e & 31;    // row 0..31, c4 0..31
            float4 v = *(const float4*)(B + (size_t)(k0 + row) * NTOT + nBase + c4 * 4);
            __nv_bfloat16 h, l;
            split_bf16(v.x, h, l); Bh[row * 136 + c4 * 4 + 0] = h; Bl[row * 136 + c4 * 4 + 0] = l;
            split_bf16(v.y, h, l); Bh[row * 136 + c4 * 4 + 1] = h; Bl[row * 136 + c4 * 4 + 1] = l;
            split_bf16(v.z, h, l); Bh[row * 136 + c4 * 4 + 2] = h; Bl[row * 136 + c4 * 4 + 2] = l;
            split_bf16(v.w, h, l); Bh[row * 136 + c4 * 4 + 3] = h; Bl[row * 136 + c4 * 4 + 3] = l;
        }
        __syncthreads();

#pragma unroll
        for (int ks = 0; ks < 32; ks += 16) {
            FragA ah[2], al[2];
#pragma unroll
            for (int mi = 0; mi < 2; mi++) {
                const int m0 = wm * 32 + mi * 16;
                wmma::load_matrix_sync(ah[mi], Ah + m0 * 40 + ks, 40);
                wmma::load_matrix_sync(al[mi], Al + m0 * 40 + ks, 40);
            }
#pragma unroll
            for (int ni = 0; ni < 4; ni++) {
                const int n0 = wn * 64 + ni * 16;
                FragBR bh, bl;
                wmma::load_matrix_sync(bh, Bh + ks * 136 + n0, 136);
                wmma::load_matrix_sync(bl, Bl + ks * 136 + n0, 136);
#pragma unroll
                for (int mi = 0; mi < 2; mi++) {
                    wmma::mma_sync(c[mi][ni], ah[mi], bh, c[mi][ni]);
                    wmma::mma_sync(c[mi][ni], ah[mi], bl, c[mi][ni]);
                    wmma::mma_sync(c[mi][ni], al[mi], bh, c[mi][ni]);
                }
            }
        }
        __syncthreads();
    }

    // Epilogue: each 16x16 tile maps to one q/k/v destination with contiguous d
#pragma unroll
    for (int mi = 0; mi < 2; mi++) {
#pragma unroll
        for (int ni = 0; ni < 4; ni++) {
            const int row0 = mBase + wm * 32 + mi * 16;
            const int col0 = nBase + wn * 64 + ni * 16;
            const int third = col0 >> 10;
            const int h     = (col0 & 1023) >> 6;
            const int dbase = col0 & 63;
            const int b_    = row0 >> 11;
            const int n_    = row0 & 2047;
            float* dst = (third == 0) ? g_q : ((third == 1) ? g_k : g_v);
            float* p = dst + ((size_t)((b_ * HEADS + h) * SEQ + n_)) * HD + dbase;
            wmma::store_matrix_sync(p, c[mi][ni], HD, wmma::mem_row_major);
        }
    }
}

// ---------------------------------------------------------------------------
// Kernel 2: flash attention with bf16x3 tensor cores.
// Block = (b,h) x 64-query tile, 256 threads = 8 warps (4m x 2n).
// K/V streamed in 64-key tiles. O/m/l state in registers (4 threads per row).
// ---------------------------------------------------------------------------
#define AP 72   // bf16/float smem pitch
#define SZB (64 * AP * 2)             // one bf16 tile: 9216 bytes
#define ATTN_SMEM (6 * SZB + 64 * AP * 4 + 2 * SZB)   // QhQl KhKl VhVl | S | PhPl

__global__ __launch_bounds__(256) void flash_attn(float* __restrict__ out) {
    extern __shared__ char smem[];
    __nv_bfloat16* Qh = (__nv_bfloat16*)(smem);
    __nv_bfloat16* Ql = (__nv_bfloat16*)(smem + SZB);
    __nv_bfloat16* Kh = (__nv_bfloat16*)(smem + 2 * SZB);
    __nv_bfloat16* Kl = (__nv_bfloat16*)(smem + 3 * SZB);
    __nv_bfloat16* Vh = (__nv_bfloat16*)(smem + 4 * SZB);
    __nv_bfloat16* Vl = (__nv_bfloat16*)(smem + 5 * SZB);
    float*         S  = (float*)(smem + 6 * SZB);     // also reused for PV partial
    __nv_bfloat16* Ph = (__nv_bfloat16*)(smem + 6 * SZB + 64 * AP * 4);
    __nv_bfloat16* Pl = (__nv_bfloat16*)(smem + 7 * SZB + 64 * AP * 4);

    const int tid = threadIdx.x;
    const int bh  = blockIdx.y;
    const int q0  = blockIdx.x * 64;
    const int wid = tid >> 5;
    const int wm  = wid >> 1;       // 0..3
    const int wn  = wid & 1;        // 0..1

    // Load Q tile (scaled), split hi/lo: 1024 float4, 4 per thread
    {
        const float4* g = (const float4*)(g_q + ((size_t)bh * SEQ + q0) * HD);
#pragma unroll
        for (int i = 0; i < 4; i++) {
            const int e = tid + i * 256;
            const int row = e >> 4, c4 = e & 15;
            float4 v = g[e];
            __nv_bfloat16 h, l;
            split_bf16(v.x * 0.125f, h, l); Qh[row * AP + c4 * 4 + 0] = h; Ql[row * AP + c4 * 4 + 0] = l;
            split_bf16(v.y * 0.125f, h, l); Qh[row * AP + c4 * 4 + 1] = h; Ql[row * AP + c4 * 4 + 1] = l;
            split_bf16(v.z * 0.125f, h, l); Qh[row * AP + c4 * 4 + 2] = h; Ql[row * AP + c4 * 4 + 2] = l;
            split_bf16(v.w * 0.125f, h, l); Qh[row * AP + c4 * 4 + 3] = h; Ql[row * AP + c4 * 4 + 3] = l;
        }
    }

    // Per-thread row state: row = tid>>2, this thread owns cols cb..cb+15
    const int srow = tid >> 2;
    const int cb   = (tid & 3) * 16;
    float mrow = -1e30f, lrow = 0.0f, oreg[16];
#pragma unroll
    for (int j = 0; j < 16; j++) oreg[j] = 0.0f;

    for (int t = 0; t < 32; t++) {
        __syncthreads();   // previous tile fully consumed
        {
            const float4* gk = (const float4*)(g_k + ((size_t)bh * SEQ + t * 64) * HD);
            const float4* gv = (const float4*)(g_v + ((size_t)bh * SEQ + t * 64) * HD);
#pragma unroll
            for (int i = 0; i < 4; i++) {
                const int e = tid + i * 256;
                const int row = e >> 4, c4 = e & 15;
                float4 vk = gk[e];
                float4 vv = gv[e];
                __nv_bfloat16 h, l;
                split_bf16(vk.x, h, l); Kh[row * AP + c4 * 4 + 0] = h; Kl[row * AP + c4 * 4 + 0] = l;
                split_bf16(vk.y, h, l); Kh[row * AP + c4 * 4 + 1] = h; Kl[row * AP + c4 * 4 + 1] = l;
                split_bf16(vk.z, h, l); Kh[row * AP + c4 * 4 + 2] = h; Kl[row * AP + c4 * 4 + 2] = l;
                split_bf16(vk.w, h, l); Kh[row * AP + c4 * 4 + 3] = h; Kl[row * AP + c4 * 4 + 3] = l;
                split_bf16(vv.x, h, l); Vh[row * AP + c4 * 4 + 0] = h; Vl[row * AP + c4 * 4 + 0] = l;
                split_bf16(vv.y, h, l); Vh[row * AP + c4 * 4 + 1] = h; Vl[row * AP + c4 * 4 + 1] = l;
                split_bf16(vv.z, h, l); Vh[row * AP + c4 * 4 + 2] = h; Vl[row * AP + c4 * 4 + 2] = l;
                split_bf16(vv.w, h, l); Vh[row * AP + c4 * 4 + 3] = h; Vl[row * AP + c4 * 4 + 3] = l;
            }
        }
        __syncthreads();

        // S = Q K^T  (warp tile: 16 q-rows x 32 key-cols)
        {
            FragC cs[2];
            wmma::fill_fragment(cs[0], 0.0f);
            wmma::fill_fragment(cs[1], 0.0f);
#pragma unroll
            for (int kd = 0; kd < 4; kd++) {
                FragA ah, al;
                wmma::load_matrix_sync(ah, Qh + (wm * 16) * AP + kd * 16, AP);
                wmma::load_matrix_sync(al, Ql + (wm * 16) * AP + kd * 16, AP);
#pragma unroll
                for (int ni = 0; ni < 2; ni++) {
                    const int key0 = wn * 32 + ni * 16;
                    FragBC bh, bl;
                    wmma::load_matrix_sync(bh, Kh + key0 * AP + kd * 16, AP);
                    wmma::load_matrix_sync(bl, Kl + key0 * AP + kd * 16, AP);
                    wmma::mma_sync(cs[ni], ah, bh, cs[ni]);
                    wmma::mma_sync(cs[ni], ah, bl, cs[ni]);
                    wmma::mma_sync(cs[ni], al, bh, cs[ni]);
                }
            }
            wmma::store_matrix_sync(S + (wm * 16) * AP + wn * 32,      cs[0], AP, wmma::mem_row_major);
            wmma::store_matrix_sync(S + (wm * 16) * AP + wn * 32 + 16, cs[1], AP, wmma::mem_row_major);
        }
        __syncthreads();

        // Online softmax: 4 threads per row, 16 cols each
        float alpha;
        {
            float sv[16];
            float tmax = -1e30f;
#pragma unroll
            for (int j = 0; j < 16; j++) { sv[j] = S[srow * AP + cb + j]; tmax = fmaxf(tmax, sv[j]); }
            tmax = fmaxf(tmax, __shfl_xor_sync(0xffffffffu, tmax, 1));
            tmax = fmaxf(tmax, __shfl_xor_sync(0xffffffffu, tmax, 2));
            const float mnew = fmaxf(mrow, tmax);
            alpha = __expf(mrow - mnew);
            mrow = mnew;
            float rs = 0.0f;
#pragma unroll
            for (int j = 0; j < 16; j++) {
                const float p = __expf(sv[j] - mnew);
                rs += p;
                __nv_bfloat16 h, l;
                split_bf16(p, h, l);
                Ph[srow * AP + cb + j] = h;
                Pl[srow * AP + cb + j] = l;
            }
            rs += __shfl_xor_sync(0xffffffffu, rs, 1);
            rs += __shfl_xor_sync(0xffffffffu, rs, 2);
            lrow = lrow * alpha + rs;
        }
        __syncthreads();

        // PV partial into S scratch (warp tile: 16 q-rows x 32 d-cols)
        {
            FragC co[2];
            wmma::fill_fragment(co[0], 0.0f);
            wmma::fill_fragment(co[1], 0.0f);
#pragma unroll
            for (int kk = 0; kk < 4; kk++) {
                FragA ah, al;
                wmma::load_matrix_sync(ah, Ph + (wm * 16) * AP + kk * 16, AP);
                wmma::load_matrix_sync(al, Pl + (wm * 16) * AP + kk * 16, AP);
#pragma unroll
                for (int ni = 0; ni < 2; ni++) {
                    const int d0 = wn * 32 + ni * 16;
                    FragBR bh, bl;
                    wmma::load_matrix_sync(bh, Vh + (kk * 16) * AP + d0, AP);
                    wmma::load_matrix_sync(bl, Vl + (kk * 16) * AP + d0, AP);
                    wmma::mma_sync(co[ni], ah, bh, co[ni]);
                    wmma::mma_sync(co[ni], ah, bl, co[ni]);
                    wmma::mma_sync(co[ni], al, bh, co[ni]);
                }
            }
            wmma::store_matrix_sync(S + (wm * 16) * AP + wn * 32,      co[0], AP, wmma::mem_row_major);
            wmma::store_matrix_sync(S + (wm * 16) * AP + wn * 32 + 16, co[1], AP, wmma::mem_row_major);
        }
        __syncthreads();

        // O = O * alpha + PV_partial (register accumulator)
#pragma unroll
        for (int j = 0; j < 16; j++)
            oreg[j] = oreg[j] * alpha + S[srow * AP + cb + j];
    }

    // Normalize and store
    const float inv = 1.0f / lrow;
    float* op = out + ((size_t)bh * SEQ + q0 + srow) * HD + cb;
#pragma unroll
    for (int j4 = 0; j4 < 4; j4++) {
        float4 o = make_float4(oreg[j4 * 4] * inv, oreg[j4 * 4 + 1] * inv,
                               oreg[j4 * 4 + 2] * inv, oreg[j4 * 4 + 3] * inv);
        *(float4*)(op + j4 * 4) = o;
    }
}

// ---------------------------------------------------------------------------
extern "C" void kernel_launch(void* const* d_in, const int* in_sizes, int n_in,
                              void* d_out, int out_size) {
    const float* x = (const float*)d_in[0];   // [2, 2048, 1024]
    const float* w = (const float*)d_in[1];   // [1024, 3072]
    float* out = (float*)d_out;               // [2, 16, 2048, 64]

    cudaFuncSetAttribute(flash_attn, cudaFuncAttributeMaxDynamicSharedMemorySize,
                         ATTN_SMEM);

    qkv_gemm<<<dim3(NTOT / 128, MTOT / 128), 256>>>(x, w);
    flash_attn<<<dim3(SEQ / 64, BATCH * HEADS), 256, ATTN_SMEM>>>(out);
}

// round 6
// speedup vs baseline: 1.5721x; 1.0512x over previous
#include <cuda_runtime.h>
#include <cuda_bf16.h>
#include <mma.h>
#include <stdint.h>
using namespace nvcuda;

#define HEADS 16
#define HD    64
#define SEQ   2048
#define BATCH 2
#define KDIM  1024
#define NTOT  3072
#define MTOT  4096
#define QKV_ELEMS (BATCH * HEADS * SEQ * HD)

// Pre-split operands (bf16 hi/lo)
__device__ __nv_bfloat16 g_xh[MTOT * KDIM], g_xl[MTOT * KDIM];
__device__ __nv_bfloat16 g_wh[KDIM * NTOT], g_wl[KDIM * NTOT];
// Pre-split Q/K/V in [b,h,n,d] layout (Q pre-scaled by 1/8)
__device__ __nv_bfloat16 g_qh[QKV_ELEMS], g_ql[QKV_ELEMS];
__device__ __nv_bfloat16 g_kh[QKV_ELEMS], g_kl[QKV_ELEMS];
__device__ __nv_bfloat16 g_vh[QKV_ELEMS], g_vl[QKV_ELEMS];

typedef wmma::fragment<wmma::matrix_a, 16, 16, 16, __nv_bfloat16, wmma::row_major> FragA;
typedef wmma::fragment<wmma::matrix_b, 16, 16, 16, __nv_bfloat16, wmma::row_major> FragBR;
typedef wmma::fragment<wmma::matrix_b, 16, 16, 16, __nv_bfloat16, wmma::col_major> FragBC;
typedef wmma::fragment<wmma::accumulator, 16, 16, 16, float> FragC;

__device__ __forceinline__ void split_bf16(float x, __nv_bfloat16& hi, __nv_bfloat16& lo) {
    hi = __float2bfloat16(x);
    lo = __float2bfloat16(x - __bfloat162float(hi));
}
__device__ __forceinline__ void cpa16(uint32_t dst, const void* src) {
    asm volatile("cp.async.cg.shared.global [%0], [%1], 16;\n" :: "r"(dst), "l"(src));
}
__device__ __forceinline__ void cpa_commit() { asm volatile("cp.async.commit_group;\n"); }
__device__ __forceinline__ void cpa_wait_all() { asm volatile("cp.async.wait_group 0;\n"); }

// ---------------------------------------------------------------------------
// Kernel 0: split X and W into bf16 hi/lo (one-time)
// ---------------------------------------------------------------------------
#define NX4 (MTOT * KDIM / 4)
#define NW4 (KDIM * NTOT / 4)
__global__ void presplit(const float* __restrict__ X, const float* __restrict__ W) {
    for (int i = blockIdx.x * blockDim.x + threadIdx.x; i < NX4 + NW4;
         i += gridDim.x * blockDim.x) {
        float4 v; __nv_bfloat16 *dh, *dl; size_t off;
        if (i < NX4) { v = ((const float4*)X)[i]; dh = g_xh; dl = g_xl; off = (size_t)i * 4; }
        else { v = ((const float4*)W)[i - NX4]; dh = g_wh; dl = g_wl; off = (size_t)(i - NX4) * 4; }
        __nv_bfloat16 h0,h1,h2,h3,l0,l1,l2,l3;
        split_bf16(v.x,h0,l0); split_bf16(v.y,h1,l1);
        split_bf16(v.z,h2,l2); split_bf16(v.w,h3,l3);
        ((__nv_bfloat162*)(dh+off))[0] = __halves2bfloat162(h0,h1);
        ((__nv_bfloat162*)(dh+off))[1] = __halves2bfloat162(h2,h3);
        ((__nv_bfloat162*)(dl+off))[0] = __halves2bfloat162(l0,l1);
        ((__nv_bfloat162*)(dl+off))[1] = __halves2bfloat162(l2,l3);
    }
}

// ---------------------------------------------------------------------------
// Kernel 1: QKV GEMM, bf16x3, cp.async double-buffered, k-step 32.
// Epilogue splits results and writes pre-split q/k/v (q scaled by 1/8).
// smem layout (bytes): AH0 0 AL0 10240 AH1 20480 AL1 30720
//                      BH0 40960 BL0 49664 BH1 58368 BL1 67072  (total 75776)
// ---------------------------------------------------------------------------
#define QKV_SMEM 75776

__device__ __forceinline__ void qkv_issue_stage(uint32_t sb, int st, int k0,
                                                int tid, int mBase, int nBase) {
    const uint32_t ab = sb + st * 20480;
#pragma unroll
    for (int i = 0; i < 4; i++) {
        const int e = tid + i * 256;                  // 0..1023
        const __nv_bfloat16* src = (e < 512) ? g_xh : g_xl;
        const int c = e & 511, row = c >> 2, cc = c & 3;
        cpa16(ab + (e < 512 ? 0 : 10240) + row * 80 + cc * 16,
              src + (size_t)(mBase + row) * KDIM + k0 + cc * 8);
    }
    const uint32_t bb = sb + 40960 + st * 17408;
#pragma unroll
    for (int i = 0; i < 4; i++) {
        const int e = tid + i * 256;
        const __nv_bfloat16* src = (e < 512) ? g_wh : g_wl;
        const int c = e & 511, row = c >> 4, cc = c & 15;
        cpa16(bb + (e < 512 ? 0 : 8704) + row * 272 + cc * 16,
              src + (size_t)(k0 + row) * NTOT + nBase + cc * 8);
    }
    cpa_commit();
}

__global__ __launch_bounds__(256) void qkv_gemm() {
    extern __shared__ char smem[];
    const uint32_t sb = (uint32_t)__cvta_generic_to_shared(smem);

    const int tid   = threadIdx.x;
    const int mBase = blockIdx.y * 128;
    const int nBase = blockIdx.x * 128;
    const int wid   = tid >> 5;
    const int lane  = tid & 31;
    const int wm    = wid >> 1;
    const int wn    = wid & 1;

    FragC c[2][4];
#pragma unroll
    for (int mi = 0; mi < 2; mi++)
#pragma unroll
        for (int ni = 0; ni < 4; ni++) wmma::fill_fragment(c[mi][ni], 0.0f);

    qkv_issue_stage(sb, 0, 0, tid, mBase, nBase);

    for (int kt = 0; kt < 32; kt++) {
        cpa_wait_all();
        __syncthreads();
        if (kt + 1 < 32) qkv_issue_stage(sb, (kt + 1) & 1, (kt + 1) * 32, tid, mBase, nBase);

        const int st = kt & 1;
        __nv_bfloat16* Ah = (__nv_bfloat16*)(smem + st * 20480);
        __nv_bfloat16* Al = (__nv_bfloat16*)(smem + st * 20480 + 10240);
        __nv_bfloat16* Bh = (__nv_bfloat16*)(smem + 40960 + st * 17408);
        __nv_bfloat16* Bl = (__nv_bfloat16*)(smem + 40960 + st * 17408 + 8704);

#pragma unroll
        for (int ks = 0; ks < 32; ks += 16) {
            FragA ah[2], al[2];
#pragma unroll
            for (int mi = 0; mi < 2; mi++) {
                const int m0 = wm * 32 + mi * 16;
                wmma::load_matrix_sync(ah[mi], Ah + m0 * 40 + ks, 40);
                wmma::load_matrix_sync(al[mi], Al + m0 * 40 + ks, 40);
            }
#pragma unroll
            for (int ni = 0; ni < 4; ni++) {
                const int n0 = wn * 64 + ni * 16;
                FragBR bh, bl;
                wmma::load_matrix_sync(bh, Bh + ks * 136 + n0, 136);
                wmma::load_matrix_sync(bl, Bl + ks * 136 + n0, 136);
#pragma unroll
                for (int mi = 0; mi < 2; mi++) {
                    wmma::mma_sync(c[mi][ni], ah[mi], bh, c[mi][ni]);
                    wmma::mma_sync(c[mi][ni], ah[mi], bl, c[mi][ni]);
                    wmma::mma_sync(c[mi][ni], al[mi], bh, c[mi][ni]);
                }
            }
        }
        __syncthreads();
    }

    // Epilogue: per-warp stage 16x16 fp32 (pitch 20 floats = 80B, 16B-multiple),
    // split to bf16 hi/lo, write pre-split q/k/v.
    float* stag = (float*)(smem + wid * 1280);   // 16x20 fp32 per warp
#pragma unroll
    for (int mi = 0; mi < 2; mi++) {
#pragma unroll
        for (int ni = 0; ni < 4; ni++) {
            wmma::store_matrix_sync(stag, c[mi][ni], 20, wmma::mem_row_major);
            __syncwarp();
            const int row0 = mBase + wm * 32 + mi * 16;
            const int col0 = nBase + wn * 64 + ni * 16;
            const int third = col0 >> 10;
            const int h     = (col0 & 1023) >> 6;
            const int dbase = col0 & 63;
            const int b_    = row0 >> 11;
            const int n_    = row0 & 2047;
            const float scale = (third == 0) ? 0.125f : 1.0f;
            __nv_bfloat16* dh = (third == 0) ? g_qh : ((third == 1) ? g_kh : g_vh);
            __nv_bfloat16* dl = (third == 0) ? g_ql : ((third == 1) ? g_kl : g_vl);
            const int r  = lane >> 1;
            const int c0 = (lane & 1) * 8;
            __nv_bfloat16 hv[8], lv[8];
#pragma unroll
            for (int j = 0; j < 8; j++)
                split_bf16(stag[r * 20 + c0 + j] * scale, hv[j], lv[j]);
            const size_t base = ((size_t)((b_ * HEADS + h) * SEQ + n_ + r)) * HD + dbase + c0;
#pragma unroll
            for (int jj = 0; jj < 4; jj++) {
                ((__nv_bfloat162*)(dh + base))[jj] = __halves2bfloat162(hv[2*jj], hv[2*jj+1]);
                ((__nv_bfloat162*)(dl + base))[jj] = __halves2bfloat162(lv[2*jj], lv[2*jj+1]);
            }
            __syncwarp();
        }
    }
}

// ---------------------------------------------------------------------------
// Kernel 2: flash attention, bf16x3, 128-row Q tile, 512 threads (16 warps),
// cp.async double-buffered K/V stages.
// smem layout (bytes):
//   QH 0  QL 18432
//   stage s (s=0,1) base 36864 + s*36864: KH +0, KL +9216, VH +18432, VL +27648
//   S  110592 (128x72 fp32)   PH 147456  PL 165888     total 184320
// ---------------------------------------------------------------------------
#define AP 72
#define ATTN_SMEM 184320

__device__ __forceinline__ void attn_issue_kv(uint32_t sb, int st, int bh, int t, int tid) {
    const uint32_t base = sb + 36864 + st * 36864;
    const __nv_bfloat16* srcs[4] = { g_kh, g_kl, g_vh, g_vl };
#pragma unroll
    for (int i = 0; i < 4; i++) {
        const int e   = tid + i * 512;       // 0..2047
        const int sel = e >> 9;
        const int c   = e & 511, row = c >> 3, cc = c & 7;
        cpa16(base + sel * 9216 + row * 144 + cc * 16,
              srcs[sel] + ((size_t)bh * SEQ + t * 64 + row) * HD + cc * 8);
    }
    cpa_commit();
}

__global__ __launch_bounds__(512) void flash_attn(float* __restrict__ out) {
    extern __shared__ char smem[];
    const uint32_t sb = (uint32_t)__cvta_generic_to_shared(smem);
    __nv_bfloat16* QH = (__nv_bfloat16*)(smem);
    __nv_bfloat16* QL = (__nv_bfloat16*)(smem + 18432);
    float*         S  = (float*)(smem + 110592);
    __nv_bfloat16* PH = (__nv_bfloat16*)(smem + 147456);
    __nv_bfloat16* PL = (__nv_bfloat16*)(smem + 165888);

    const int tid = threadIdx.x;
    const int bh  = blockIdx.y;
    const int q0  = blockIdx.x * 128;
    const int wid = tid >> 5;
    const int wm  = wid >> 1;     // 0..7: 16 q-rows each
    const int wn  = wid & 1;      // 0..1: 32 keys / 32 d-cols each

    // Issue Q loads (hi+lo) + KV stage 0 as one group
#pragma unroll
    for (int i = 0; i < 4; i++) {
        const int e = tid + i * 512;                  // 0..2047
        const __nv_bfloat16* src = (e < 1024) ? g_qh : g_ql;
        const int c = e & 1023, row = c >> 3, cc = c & 7;
        cpa16(sb + (e < 1024 ? 0 : 18432) + row * 144 + cc * 16,
              src + ((size_t)bh * SEQ + q0 + row) * HD + cc * 8);
    }
    attn_issue_kv(sb, 0, bh, 0, tid);

    const int srow = tid >> 2;         // 0..127
    const int cb   = (tid & 3) * 16;
    float mrow = -1e30f, lrow = 0.0f, oreg[16];
#pragma unroll
    for (int j = 0; j < 16; j++) oreg[j] = 0.0f;

    for (int t = 0; t < 32; t++) {
        cpa_wait_all();
        __syncthreads();
        if (t + 1 < 32) attn_issue_kv(sb, (t + 1) & 1, bh, t + 1, tid);

        const int st = t & 1;
        __nv_bfloat16* KH = (__nv_bfloat16*)(smem + 36864 + st * 36864);
        __nv_bfloat16* KL = KH + 4608;   // +9216 bytes
        __nv_bfloat16* VH = KH + 9216;
        __nv_bfloat16* VL = KH + 13824;

        // S = Q K^T  (warp: 16 q-rows x 32 keys)
        {
            FragC cs[2];
            wmma::fill_fragment(cs[0], 0.0f);
            wmma::fill_fragment(cs[1], 0.0f);
#pragma unroll
            for (int kd = 0; kd < 4; kd++) {
                FragA ah, al;
                wmma::load_matrix_sync(ah, QH + (wm * 16) * AP + kd * 16, AP);
                wmma::load_matrix_sync(al, QL + (wm * 16) * AP + kd * 16, AP);
#pragma unroll
                for (int ni = 0; ni < 2; ni++) {
                    const int key0 = wn * 32 + ni * 16;
                    FragBC bh, bl;
                    wmma::load_matrix_sync(bh, KH + key0 * AP + kd * 16, AP);
                    wmma::load_matrix_sync(bl, KL + key0 * AP + kd * 16, AP);
                    wmma::mma_sync(cs[ni], ah, bh, cs[ni]);
                    wmma::mma_sync(cs[ni], ah, bl, cs[ni]);
                    wmma::mma_sync(cs[ni], al, bh, cs[ni]);
                }
            }
            wmma::store_matrix_sync(S + (wm * 16) * AP + wn * 32,      cs[0], AP, wmma::mem_row_major);
            wmma::store_matrix_sync(S + (wm * 16) * AP + wn * 32 + 16, cs[1], AP, wmma::mem_row_major);
        }
        __syncthreads();

        // Online softmax (4 threads per row)
        float alpha;
        {
            float sv[16], tmax = -1e30f;
#pragma unroll
            for (int j = 0; j < 16; j++) { sv[j] = S[srow * AP + cb + j]; tmax = fmaxf(tmax, sv[j]); }
            tmax = fmaxf(tmax, __shfl_xor_sync(0xffffffffu, tmax, 1));
            tmax = fmaxf(tmax, __shfl_xor_sync(0xffffffffu, tmax, 2));
            const float mnew = fmaxf(mrow, tmax);
            alpha = __expf(mrow - mnew);
            mrow = mnew;
            float rs = 0.0f;
#pragma unroll
            for (int j = 0; j < 16; j++) {
                const float p = __expf(sv[j] - mnew);
                rs += p;
                __nv_bfloat16 h, l;
                split_bf16(p, h, l);
                PH[srow * AP + cb + j] = h;
                PL[srow * AP + cb + j] = l;
            }
            rs += __shfl_xor_sync(0xffffffffu, rs, 1);
            rs += __shfl_xor_sync(0xffffffffu, rs, 2);
            lrow = lrow * alpha + rs;
        }
        __syncthreads();

        // PV partial into S (warp: 16 q-rows x 32 d-cols)
        {
            FragC co[2];
            wmma::fill_fragment(co[0], 0.0f);
            wmma::fill_fragment(co[1], 0.0f);
#pragma unroll
            for (int kk = 0; kk < 4; kk++) {
                FragA ah, al;
                wmma::load_matrix_sync(ah, PH + (wm * 16) * AP + kk * 16, AP);
                wmma::load_matrix_sync(al, PL + (wm * 16) * AP + kk * 16, AP);
#pragma unroll
                for (int ni = 0; ni < 2; ni++) {
                    const int d0 = wn * 32 + ni * 16;
                    FragBR bh, bl;
                    wmma::load_matrix_sync(bh, VH + (kk * 16) * AP + d0, AP);
                    wmma::load_matrix_sync(bl, VL + (kk * 16) * AP + d0, AP);
                    wmma::mma_sync(co[ni], ah, bh, co[ni]);
                    wmma::mma_sync(co[ni], ah, bl, co[ni]);
                    wmma::mma_sync(co[ni], al, bh, co[ni]);
                }
            }
            wmma::store_matrix_sync(S + (wm * 16) * AP + wn * 32,      co[0], AP, wmma::mem_row_major);
            wmma::store_matrix_sync(S + (wm * 16) * AP + wn * 32 + 16, co[1], AP, wmma::mem_row_major);
        }
        __syncthreads();

        // O = O * alpha + PV_partial
#pragma unroll
        for (int j = 0; j < 16; j++)
            oreg[j] = oreg[j] * alpha + S[srow * AP + cb + j];
    }

    const float inv = 1.0f / lrow;
    float* op = out + ((size_t)bh * SEQ + q0 + srow) * HD + cb;
#pragma unroll
    for (int j4 = 0; j4 < 4; j4++) {
        float4 o = make_float4(oreg[j4*4] * inv, oreg[j4*4+1] * inv,
                               oreg[j4*4+2] * inv, oreg[j4*4+3] * inv);
        *(float4*)(op + j4 * 4) = o;
    }
}

// ---------------------------------------------------------------------------
extern "C" void kernel_launch(void* const* d_in, const int* in_sizes, int n_in,
                              void* d_out, int out_size) {
    const float* x = (const float*)d_in[0];
    const float* w = (const float*)d_in[1];
    float* out = (float*)d_out;

    cudaFuncSetAttribute(qkv_gemm, cudaFuncAttributeMaxDynamicSharedMemorySize, QKV_SMEM);
    cudaFuncSetAttribute(flash_attn, cudaFuncAttributeMaxDynamicSharedMemorySize, ATTN_SMEM);

    presplit<<<1024, 256>>>(x, w);
    qkv_gemm<<<dim3(NTOT / 128, MTOT / 128), 256, QKV_SMEM>>>();
    flash_attn<<<dim3(SEQ / 128, BATCH * HEADS), 512, ATTN_SMEM>>>(out);
}

// round 7
// speedup vs baseline: 1.5732x; 1.0007x over previous
#include <cuda_runtime.h>
#include <cuda_bf16.h>
#include <mma.h>
#include <stdint.h>
using namespace nvcuda;

#define HEADS 16
#define HD    64
#define SEQ   2048
#define BATCH 2
#define KDIM  1024
#define NTOT  3072
#define MTOT  4096
#define QKV_ELEMS (BATCH * HEADS * SEQ * HD)

// Pre-split operands (bf16 hi/lo)
__device__ __nv_bfloat16 g_xh[MTOT * KDIM], g_xl[MTOT * KDIM];
__device__ __nv_bfloat16 g_wh[KDIM * NTOT], g_wl[KDIM * NTOT];
// Pre-split Q/K/V in [b,h,n,d] layout (Q pre-scaled by 1/8)
__device__ __nv_bfloat16 g_qh[QKV_ELEMS], g_ql[QKV_ELEMS];
__device__ __nv_bfloat16 g_kh[QKV_ELEMS], g_kl[QKV_ELEMS];
__device__ __nv_bfloat16 g_vh[QKV_ELEMS], g_vl[QKV_ELEMS];

typedef wmma::fragment<wmma::matrix_a, 16, 16, 16, __nv_bfloat16, wmma::row_major> FragA;
typedef wmma::fragment<wmma::matrix_b, 16, 16, 16, __nv_bfloat16, wmma::row_major> FragBR;
typedef wmma::fragment<wmma::matrix_b, 16, 16, 16, __nv_bfloat16, wmma::col_major> FragBC;
typedef wmma::fragment<wmma::accumulator, 16, 16, 16, float> FragC;

__device__ __forceinline__ void split_bf16(float x, __nv_bfloat16& hi, __nv_bfloat16& lo) {
    hi = __float2bfloat16(x);
    lo = __float2bfloat16(x - __bfloat162float(hi));
}
__device__ __forceinline__ void cpa16(uint32_t dst, const void* src) {
    asm volatile("cp.async.cg.shared.global [%0], [%1], 16;\n" :: "r"(dst), "l"(src));
}
__device__ __forceinline__ void cpa_commit() { asm volatile("cp.async.commit_group;\n"); }
__device__ __forceinline__ void cpa_wait_all() { asm volatile("cp.async.wait_group 0;\n"); }

// ---------------------------------------------------------------------------
// Kernel 0: split X and W into bf16 hi/lo (one-time)
// ---------------------------------------------------------------------------
#define NX4 (MTOT * KDIM / 4)
#define NW4 (KDIM * NTOT / 4)
__global__ void presplit(const float* __restrict__ X, const float* __restrict__ W) {
    for (int i = blockIdx.x * blockDim.x + threadIdx.x; i < NX4 + NW4;
         i += gridDim.x * blockDim.x) {
        float4 v; __nv_bfloat16 *dh, *dl; size_t off;
        if (i < NX4) { v = ((const float4*)X)[i]; dh = g_xh; dl = g_xl; off = (size_t)i * 4; }
        else { v = ((const float4*)W)[i - NX4]; dh = g_wh; dl = g_wl; off = (size_t)(i - NX4) * 4; }
        __nv_bfloat16 h0,h1,h2,h3,l0,l1,l2,l3;
        split_bf16(v.x,h0,l0); split_bf16(v.y,h1,l1);
        split_bf16(v.z,h2,l2); split_bf16(v.w,h3,l3);
        ((__nv_bfloat162*)(dh+off))[0] = __halves2bfloat162(h0,h1);
        ((__nv_bfloat162*)(dh+off))[1] = __halves2bfloat162(h2,h3);
        ((__nv_bfloat162*)(dl+off))[0] = __halves2bfloat162(l0,l1);
        ((__nv_bfloat162*)(dl+off))[1] = __halves2bfloat162(l2,l3);
    }
}

// ---------------------------------------------------------------------------
// Kernel 1: QKV GEMM, bf16x3, cp.async double-buffered, k-step 32.
// Epilogue splits results and writes pre-split q/k/v (q scaled by 1/8).
// smem layout (bytes): AH0 0 AL0 10240 AH1 20480 AL1 30720
//                      BH0 40960 BL0 49664 BH1 58368 BL1 67072  (total 75776)
// ---------------------------------------------------------------------------
#define QKV_SMEM 75776

__device__ __forceinline__ void qkv_issue_stage(uint32_t sb, int st, int k0,
                                                int tid, int mBase, int nBase) {
    const uint32_t ab = sb + st * 20480;
#pragma unroll
    for (int i = 0; i < 4; i++) {
        const int e = tid + i * 256;                  // 0..1023
        const __nv_bfloat16* src = (e < 512) ? g_xh : g_xl;
        const int c = e & 511, row = c >> 2, cc = c & 3;
        cpa16(ab + (e < 512 ? 0 : 10240) + row * 80 + cc * 16,
              src + (size_t)(mBase + row) * KDIM + k0 + cc * 8);
    }
    const uint32_t bb = sb + 40960 + st * 17408;
#pragma unroll
    for (int i = 0; i < 4; i++) {
        const int e = tid + i * 256;
        const __nv_bfloat16* src = (e < 512) ? g_wh : g_wl;
        const int c = e & 511, row = c >> 4, cc = c & 15;
        cpa16(bb + (e < 512 ? 0 : 8704) + row * 272 + cc * 16,
              src + (size_t)(k0 + row) * NTOT + nBase + cc * 8);
    }
    cpa_commit();
}

__global__ __launch_bounds__(256) void qkv_gemm() {
    extern __shared__ char smem[];
    const uint32_t sb = (uint32_t)__cvta_generic_to_shared(smem);

    const int tid   = threadIdx.x;
    const int mBase = blockIdx.y * 128;
    const int nBase = blockIdx.x * 128;
    const int wid   = tid >> 5;
    const int lane  = tid & 31;
    const int wm    = wid >> 1;
    const int wn    = wid & 1;

    FragC c[2][4];
#pragma unroll
    for (int mi = 0; mi < 2; mi++)
#pragma unroll
        for (int ni = 0; ni < 4; ni++) wmma::fill_fragment(c[mi][ni], 0.0f);

    qkv_issue_stage(sb, 0, 0, tid, mBase, nBase);

    for (int kt = 0; kt < 32; kt++) {
        cpa_wait_all();
        __syncthreads();
        if (kt + 1 < 32) qkv_issue_stage(sb, (kt + 1) & 1, (kt + 1) * 32, tid, mBase, nBase);

        const int st = kt & 1;
        __nv_bfloat16* Ah = (__nv_bfloat16*)(smem + st * 20480);
        __nv_bfloat16* Al = (__nv_bfloat16*)(smem + st * 20480 + 10240);
        __nv_bfloat16* Bh = (__nv_bfloat16*)(smem + 40960 + st * 17408);
        __nv_bfloat16* Bl = (__nv_bfloat16*)(smem + 40960 + st * 17408 + 8704);

#pragma unroll
        for (int ks = 0; ks < 32; ks += 16) {
            FragA ah[2], al[2];
#pragma unroll
            for (int mi = 0; mi < 2; mi++) {
                const int m0 = wm * 32 + mi * 16;
                wmma::load_matrix_sync(ah[mi], Ah + m0 * 40 + ks, 40);
                wmma::load_matrix_sync(al[mi], Al + m0 * 40 + ks, 40);
            }
#pragma unroll
            for (int ni = 0; ni < 4; ni++) {
                const int n0 = wn * 64 + ni * 16;
                FragBR bh, bl;
                wmma::load_matrix_sync(bh, Bh + ks * 136 + n0, 136);
                wmma::load_matrix_sync(bl, Bl + ks * 136 + n0, 136);
#pragma unroll
                for (int mi = 0; mi < 2; mi++) {
                    wmma::mma_sync(c[mi][ni], ah[mi], bh, c[mi][ni]);
                    wmma::mma_sync(c[mi][ni], ah[mi], bl, c[mi][ni]);
                    wmma::mma_sync(c[mi][ni], al[mi], bh, c[mi][ni]);
                }
            }
        }
        __syncthreads();
    }

    // Epilogue: per-warp stage 16x16 fp32 (pitch 20 floats = 80B, 16B-multiple),
    // split to bf16 hi/lo, write pre-split q/k/v.
    float* stag = (float*)(smem + wid * 1280);   // 16x20 fp32 per warp
#pragma unroll
    for (int mi = 0; mi < 2; mi++) {
#pragma unroll
        for (int ni = 0; ni < 4; ni++) {
            wmma::store_matrix_sync(stag, c[mi][ni], 20, wmma::mem_row_major);
            __syncwarp();
            const int row0 = mBase + wm * 32 + mi * 16;
            const int col0 = nBase + wn * 64 + ni * 16;
            const int third = col0 >> 10;
            const int h     = (col0 & 1023) >> 6;
            const int dbase = col0 & 63;
            const int b_    = row0 >> 11;
            const int n_    = row0 & 2047;
            const float scale = (third == 0) ? 0.125f : 1.0f;
            __nv_bfloat16* dh = (third == 0) ? g_qh : ((third == 1) ? g_kh : g_vh);
            __nv_bfloat16* dl = (third == 0) ? g_ql : ((third == 1) ? g_kl : g_vl);
            const int r  = lane >> 1;
            const int c0 = (lane & 1) * 8;
            __nv_bfloat16 hv[8], lv[8];
#pragma unroll
            for (int j = 0; j < 8; j++)
                split_bf16(stag[r * 20 + c0 + j] * scale, hv[j], lv[j]);
            const size_t base = ((size_t)((b_ * HEADS + h) * SEQ + n_ + r)) * HD + dbase + c0;
#pragma unroll
            for (int jj = 0; jj < 4; jj++) {
                ((__nv_bfloat162*)(dh + base))[jj] = __halves2bfloat162(hv[2*jj], hv[2*jj+1]);
                ((__nv_bfloat162*)(dl + base))[jj] = __halves2bfloat162(lv[2*jj], lv[2*jj+1]);
            }
            __syncwarp();
        }
    }
}

// ---------------------------------------------------------------------------
// Kernel 2: flash attention, bf16x3, 128-row Q tile, 512 threads (16 warps),
// cp.async double-buffered K/V stages.
// smem layout (bytes):
//   QH 0  QL 18432
//   stage s (s=0,1) base 36864 + s*36864: KH +0, KL +9216, VH +18432, VL +27648
//   S  110592 (128x72 fp32)   PH 147456  PL 165888     total 184320
// ---------------------------------------------------------------------------
#define AP 72
#define ATTN_SMEM 184320

__device__ __forceinline__ void attn_issue_kv(uint32_t sb, int st, int bh, int t, int tid) {
    const uint32_t base = sb + 36864 + st * 36864;
    const __nv_bfloat16* srcs[4] = { g_kh, g_kl, g_vh, g_vl };
#pragma unroll
    for (int i = 0; i < 4; i++) {
        const int e   = tid + i * 512;       // 0..2047
        const int sel = e >> 9;
        const int c   = e & 511, row = c >> 3, cc = c & 7;
        cpa16(base + sel * 9216 + row * 144 + cc * 16,
              srcs[sel] + ((size_t)bh * SEQ + t * 64 + row) * HD + cc * 8);
    }
    cpa_commit();
}

__global__ __launch_bounds__(512) void flash_attn(float* __restrict__ out) {
    extern __shared__ char smem[];
    const uint32_t sb = (uint32_t)__cvta_generic_to_shared(smem);
    __nv_bfloat16* QH = (__nv_bfloat16*)(smem);
    __nv_bfloat16* QL = (__nv_bfloat16*)(smem + 18432);
    float*         S  = (float*)(smem + 110592);
    __nv_bfloat16* PH = (__nv_bfloat16*)(smem + 147456);
    __nv_bfloat16* PL = (__nv_bfloat16*)(smem + 165888);

    const int tid = threadIdx.x;
    const int bh  = blockIdx.y;
    const int q0  = blockIdx.x * 128;
    const int wid = tid >> 5;
    const int wm  = wid >> 1;     // 0..7: 16 q-rows each
    const int wn  = wid & 1;      // 0..1: 32 keys / 32 d-cols each

    // Issue Q loads (hi+lo) + KV stage 0 as one group
#pragma unroll
    for (int i = 0; i < 4; i++) {
        const int e = tid + i * 512;                  // 0..2047
        const __nv_bfloat16* src = (e < 1024) ? g_qh : g_ql;
        const int c = e & 1023, row = c >> 3, cc = c & 7;
        cpa16(sb + (e < 1024 ? 0 : 18432) + row * 144 + cc * 16,
              src + ((size_t)bh * SEQ + q0 + row) * HD + cc * 8);
    }
    attn_issue_kv(sb, 0, bh, 0, tid);

    const int srow = tid >> 2;         // 0..127
    const int cb   = (tid & 3) * 16;
    float mrow = -1e30f, lrow = 0.0f, oreg[16];
#pragma unroll
    for (int j = 0; j < 16; j++) oreg[j] = 0.0f;

    for (int t = 0; t < 32; t++) {
        cpa_wait_all();
        __syncthreads();
        if (t + 1 < 32) attn_issue_kv(sb, (t + 1) & 1, bh, t + 1, tid);

        const int st = t & 1;
        __nv_bfloat16* KH = (__nv_bfloat16*)(smem + 36864 + st * 36864);
        __nv_bfloat16* KL = KH + 4608;   // +9216 bytes
        __nv_bfloat16* VH = KH + 9216;
        __nv_bfloat16* VL = KH + 13824;

        // S = Q K^T  (warp: 16 q-rows x 32 keys)
        {
            FragC cs[2];
            wmma::fill_fragment(cs[0], 0.0f);
            wmma::fill_fragment(cs[1], 0.0f);
#pragma unroll
            for (int kd = 0; kd < 4; kd++) {
                FragA ah, al;
                wmma::load_matrix_sync(ah, QH + (wm * 16) * AP + kd * 16, AP);
                wmma::load_matrix_sync(al, QL + (wm * 16) * AP + kd * 16, AP);
#pragma unroll
                for (int ni = 0; ni < 2; ni++) {
                    const int key0 = wn * 32 + ni * 16;
                    FragBC bh, bl;
                    wmma::load_matrix_sync(bh, KH + key0 * AP + kd * 16, AP);
                    wmma::load_matrix_sync(bl, KL + key0 * AP + kd * 16, AP);
                    wmma::mma_sync(cs[ni], ah, bh, cs[ni]);
                    wmma::mma_sync(cs[ni], ah, bl, cs[ni]);
                    wmma::mma_sync(cs[ni], al, bh, cs[ni]);
                }
            }
            wmma::store_matrix_sync(S + (wm * 16) * AP + wn * 32,      cs[0], AP, wmma::mem_row_major);
            wmma::store_matrix_sync(S + (wm * 16) * AP + wn * 32 + 16, cs[1], AP, wmma::mem_row_major);
        }
        __syncthreads();

        // Online softmax (4 threads per row)
        float alpha;
        {
            float sv[16], tmax = -1e30f;
#pragma unroll
            for (int j = 0; j < 16; j++) { sv[j] = S[srow * AP + cb + j]; tmax = fmaxf(tmax, sv[j]); }
            tmax = fmaxf(tmax, __shfl_xor_sync(0xffffffffu, tmax, 1));
            tmax = fmaxf(tmax, __shfl_xor_sync(0xffffffffu, tmax, 2));
            const float mnew = fmaxf(mrow, tmax);
            alpha = __expf(mrow - mnew);
            mrow = mnew;
            float rs = 0.0f;
#pragma unroll
            for (int j = 0; j < 16; j++) {
                const float p = __expf(sv[j] - mnew);
                rs += p;
                __nv_bfloat16 h, l;
                split_bf16(p, h, l);
                PH[srow * AP + cb + j] = h;
                PL[srow * AP + cb + j] = l;
            }
            rs += __shfl_xor_sync(0xffffffffu, rs, 1);
            rs += __shfl_xor_sync(0xffffffffu, rs, 2);
            lrow = lrow * alpha + rs;
        }
        __syncthreads();

        // PV partial into S (warp: 16 q-rows x 32 d-cols)
        {
            FragC co[2];
            wmma::fill_fragment(co[0], 0.0f);
            wmma::fill_fragment(co[1], 0.0f);
#pragma unroll
            for (int kk = 0; kk < 4; kk++) {
                FragA ah, al;
                wmma::load_matrix_sync(ah, PH + (wm * 16) * AP + kk * 16, AP);
                wmma::load_matrix_sync(al, PL + (wm * 16) * AP + kk * 16, AP);
#pragma unroll
                for (int ni = 0; ni < 2; ni++) {
                    const int d0 = wn * 32 + ni * 16;
                    FragBR bh, bl;
                    wmma::load_matrix_sync(bh, VH + (kk * 16) * AP + d0, AP);
                    wmma::load_matrix_sync(bl, VL + (kk * 16) * AP + d0, AP);
                    wmma::mma_sync(co[ni], ah, bh, co[ni]);
                    wmma::mma_sync(co[ni], ah, bl, co[ni]);
                    wmma::mma_sync(co[ni], al, bh, co[ni]);
                }
            }
            wmma::store_matrix_sync(S + (wm * 16) * AP + wn * 32,      co[0], AP, wmma::mem_row_major);
            wmma::store_matrix_sync(S + (wm * 16) * AP + wn * 32 + 16, co[1], AP, wmma::mem_row_major);
        }
        __syncthreads();

        // O = O * alpha + PV_partial
#pragma unroll
        for (int j = 0; j < 16; j++)
            oreg[j] = oreg[j] * alpha + S[srow * AP + cb + j];
    }

    const float inv = 1.0f / lrow;
    float* op = out + ((size_t)bh * SEQ + q0 + srow) * HD + cb;
#pragma unroll
    for (int j4 = 0; j4 < 4; j4++) {
        float4 o = make_float4(oreg[j4*4] * inv, oreg[j4*4+1] * inv,
                               oreg[j4*4+2] * inv, oreg[j4*4+3] * inv);
        *(float4*)(op + j4 * 4) = o;
    }
}

// ---------------------------------------------------------------------------
extern "C" void kernel_launch(void* const* d_in, const int* in_sizes, int n_in,
                              void* d_out, int out_size) {
    const float* x = (const float*)d_in[0];
    const float* w = (const float*)d_in[1];
    float* out = (float*)d_out;

    cudaFuncSetAttribute(qkv_gemm, cudaFuncAttributeMaxDynamicSharedMemorySize, QKV_SMEM);
    cudaFuncSetAttribute(flash_attn, cudaFuncAttributeMaxDynamicSharedMemorySize, ATTN_SMEM);

    presplit<<<1024, 256>>>(x, w);
    qkv_gemm<<<dim3(NTOT / 128, MTOT / 128), 256, QKV_SMEM>>>();
    flash_attn<<<dim3(SEQ / 128, BATCH * HEADS), 512, ATTN_SMEM>>>(out);
}

// round 8
// speedup vs baseline: 2.2721x; 1.4442x over previous
#include <cuda_runtime.h>
#include <cuda_bf16.h>
#include <mma.h>
#include <stdint.h>
using namespace nvcuda;

#define HEADS 16
#define HD    64
#define SEQ   2048
#define BATCH 2
#define KDIM  1024
#define NTOT  3072
#define MTOT  4096
#define QKV_ELEMS (BATCH * HEADS * SEQ * HD)

__device__ __nv_bfloat16 g_xh[MTOT * KDIM], g_xl[MTOT * KDIM];
__device__ __nv_bfloat16 g_wh[KDIM * NTOT], g_wl[KDIM * NTOT];
__device__ __nv_bfloat16 g_qh[QKV_ELEMS], g_ql[QKV_ELEMS];
__device__ __nv_bfloat16 g_kh[QKV_ELEMS], g_kl[QKV_ELEMS];
__device__ __nv_bfloat16 g_vh[QKV_ELEMS], g_vl[QKV_ELEMS];

typedef wmma::fragment<wmma::matrix_a, 16, 16, 16, __nv_bfloat16, wmma::row_major> FragA;
typedef wmma::fragment<wmma::matrix_b, 16, 16, 16, __nv_bfloat16, wmma::row_major> FragBR;
typedef wmma::fragment<wmma::accumulator, 16, 16, 16, float> FragC;

__device__ __forceinline__ void split_bf16(float x, __nv_bfloat16& hi, __nv_bfloat16& lo) {
    hi = __float2bfloat16(x);
    lo = __float2bfloat16(x - __bfloat162float(hi));
}
__device__ __forceinline__ void cpa16(uint32_t dst, const void* src) {
    asm volatile("cp.async.cg.shared.global [%0], [%1], 16;\n" :: "r"(dst), "l"(src));
}
__device__ __forceinline__ void cpa_commit() { asm volatile("cp.async.commit_group;\n"); }
__device__ __forceinline__ void cpa_wait_all() { asm volatile("cp.async.wait_group 0;\n"); }

__device__ __forceinline__ void ldsm_x2(uint32_t& r0, uint32_t& r1, uint32_t addr) {
    asm volatile("ldmatrix.sync.aligned.m8n8.x2.shared.b16 {%0,%1}, [%2];"
                 : "=r"(r0), "=r"(r1) : "r"(addr));
}
__device__ __forceinline__ void ldsm_x2_t(uint32_t& r0, uint32_t& r1, uint32_t addr) {
    asm volatile("ldmatrix.sync.aligned.m8n8.x2.trans.shared.b16 {%0,%1}, [%2];"
                 : "=r"(r0), "=r"(r1) : "r"(addr));
}
__device__ __forceinline__ void mma16816(float* c, uint32_t a0, uint32_t a1, uint32_t a2,
                                         uint32_t a3, uint32_t b0, uint32_t b1) {
    asm volatile("mma.sync.aligned.m16n8k16.row.col.f32.bf16.bf16.f32 "
                 "{%0,%1,%2,%3}, {%4,%5,%6,%7}, {%8,%9}, {%0,%1,%2,%3};"
                 : "+f"(c[0]), "+f"(c[1]), "+f"(c[2]), "+f"(c[3])
                 : "r"(a0), "r"(a1), "r"(a2), "r"(a3), "r"(b0), "r"(b1));
}
__device__ __forceinline__ uint32_t packbf(float x, float y) {
    __nv_bfloat162 t = __floats2bfloat162_rn(x, y);
    return *(uint32_t*)&t;
}

// ---------------------------------------------------------------------------
// Kernel 0: split X and W into bf16 hi/lo
// ---------------------------------------------------------------------------
#define NX4 (MTOT * KDIM / 4)
#define NW4 (KDIM * NTOT / 4)
__global__ void presplit(const float* __restrict__ X, const float* __restrict__ W) {
    for (int i = blockIdx.x * blockDim.x + threadIdx.x; i < NX4 + NW4;
         i += gridDim.x * blockDim.x) {
        float4 v; __nv_bfloat16 *dh, *dl; size_t off;
        if (i < NX4) { v = ((const float4*)X)[i]; dh = g_xh; dl = g_xl; off = (size_t)i * 4; }
        else { v = ((const float4*)W)[i - NX4]; dh = g_wh; dl = g_wl; off = (size_t)(i - NX4) * 4; }
        __nv_bfloat16 h0,h1,h2,h3,l0,l1,l2,l3;
        split_bf16(v.x,h0,l0); split_bf16(v.y,h1,l1);
        split_bf16(v.z,h2,l2); split_bf16(v.w,h3,l3);
        ((__nv_bfloat162*)(dh+off))[0] = __halves2bfloat162(h0,h1);
        ((__nv_bfloat162*)(dh+off))[1] = __halves2bfloat162(h2,h3);
        ((__nv_bfloat162*)(dl+off))[0] = __halves2bfloat162(l0,l1);
        ((__nv_bfloat162*)(dl+off))[1] = __halves2bfloat162(l2,l3);
    }
}

// ---------------------------------------------------------------------------
// Kernel 1: QKV GEMM (unchanged from round 7)
// ---------------------------------------------------------------------------
#define QKV_SMEM 75776

__device__ __forceinline__ void qkv_issue_stage(uint32_t sb, int st, int k0,
                                                int tid, int mBase, int nBase) {
    const uint32_t ab = sb + st * 20480;
#pragma unroll
    for (int i = 0; i < 4; i++) {
        const int e = tid + i * 256;
        const __nv_bfloat16* src = (e < 512) ? g_xh : g_xl;
        const int c = e & 511, row = c >> 2, cc = c & 3;
        cpa16(ab + (e < 512 ? 0 : 10240) + row * 80 + cc * 16,
              src + (size_t)(mBase + row) * KDIM + k0 + cc * 8);
    }
    const uint32_t bb = sb + 40960 + st * 17408;
#pragma unroll
    for (int i = 0; i < 4; i++) {
        const int e = tid + i * 256;
        const __nv_bfloat16* src = (e < 512) ? g_wh : g_wl;
        const int c = e & 511, row = c >> 4, cc = c & 15;
        cpa16(bb + (e < 512 ? 0 : 8704) + row * 272 + cc * 16,
              src + (size_t)(k0 + row) * NTOT + nBase + cc * 8);
    }
    cpa_commit();
}

__global__ __launch_bounds__(256) void qkv_gemm() {
    extern __shared__ char smem[];
    const uint32_t sb = (uint32_t)__cvta_generic_to_shared(smem);

    const int tid   = threadIdx.x;
    const int mBase = blockIdx.y * 128;
    const int nBase = blockIdx.x * 128;
    const int wid   = tid >> 5;
    const int lane  = tid & 31;
    const int wm    = wid >> 1;
    const int wn    = wid & 1;

    FragC c[2][4];
#pragma unroll
    for (int mi = 0; mi < 2; mi++)
#pragma unroll
        for (int ni = 0; ni < 4; ni++) wmma::fill_fragment(c[mi][ni], 0.0f);

    qkv_issue_stage(sb, 0, 0, tid, mBase, nBase);

    for (int kt = 0; kt < 32; kt++) {
        cpa_wait_all();
        __syncthreads();
        if (kt + 1 < 32) qkv_issue_stage(sb, (kt + 1) & 1, (kt + 1) * 32, tid, mBase, nBase);

        const int st = kt & 1;
        __nv_bfloat16* Ah = (__nv_bfloat16*)(smem + st * 20480);
        __nv_bfloat16* Al = (__nv_bfloat16*)(smem + st * 20480 + 10240);
        __nv_bfloat16* Bh = (__nv_bfloat16*)(smem + 40960 + st * 17408);
        __nv_bfloat16* Bl = (__nv_bfloat16*)(smem + 40960 + st * 17408 + 8704);

#pragma unroll
        for (int ks = 0; ks < 32; ks += 16) {
            FragA ah[2], al[2];
#pragma unroll
            for (int mi = 0; mi < 2; mi++) {
                const int m0 = wm * 32 + mi * 16;
                wmma::load_matrix_sync(ah[mi], Ah + m0 * 40 + ks, 40);
                wmma::load_matrix_sync(al[mi], Al + m0 * 40 + ks, 40);
            }
#pragma unroll
            for (int ni = 0; ni < 4; ni++) {
                const int n0 = wn * 64 + ni * 16;
                FragBR bh, bl;
                wmma::load_matrix_sync(bh, Bh + ks * 136 + n0, 136);
                wmma::load_matrix_sync(bl, Bl + ks * 136 + n0, 136);
#pragma unroll
                for (int mi = 0; mi < 2; mi++) {
                    wmma::mma_sync(c[mi][ni], ah[mi], bh, c[mi][ni]);
                    wmma::mma_sync(c[mi][ni], ah[mi], bl, c[mi][ni]);
                    wmma::mma_sync(c[mi][ni], al[mi], bh, c[mi][ni]);
                }
            }
        }
        __syncthreads();
    }

    float* stag = (float*)(smem + wid * 1280);   // 16x20 fp32 per warp
#pragma unroll
    for (int mi = 0; mi < 2; mi++) {
#pragma unroll
        for (int ni = 0; ni < 4; ni++) {
            wmma::store_matrix_sync(stag, c[mi][ni], 20, wmma::mem_row_major);
            __syncwarp();
            const int row0 = mBase + wm * 32 + mi * 16;
            const int col0 = nBase + wn * 64 + ni * 16;
            const int third = col0 >> 10;
            const int h     = (col0 & 1023) >> 6;
            const int dbase = col0 & 63;
            const int b_    = row0 >> 11;
            const int n_    = row0 & 2047;
            const float scale = (third == 0) ? 0.125f : 1.0f;
            __nv_bfloat16* dh = (third == 0) ? g_qh : ((third == 1) ? g_kh : g_vh);
            __nv_bfloat16* dl = (third == 0) ? g_ql : ((third == 1) ? g_kl : g_vl);
            const int r  = lane >> 1;
            const int c0 = (lane & 1) * 8;
            __nv_bfloat16 hv[8], lv[8];
#pragma unroll
            for (int j = 0; j < 8; j++)
                split_bf16(stag[r * 20 + c0 + j] * scale, hv[j], lv[j]);
            const size_t base = ((size_t)((b_ * HEADS + h) * SEQ + n_ + r)) * HD + dbase + c0;
#pragma unroll
            for (int jj = 0; jj < 4; jj++) {
                ((__nv_bfloat162*)(dh + base))[jj] = __halves2bfloat162(hv[2*jj], hv[2*jj+1]);
                ((__nv_bfloat162*)(dl + base))[jj] = __halves2bfloat162(lv[2*jj], lv[2*jj+1]);
            }
            __syncwarp();
        }
    }
}

// ---------------------------------------------------------------------------
// Kernel 2: register-resident flash attention (FA2-style), bf16x3 mma.sync.
// Block = 256 threads (8 warps); warp w owns q-rows [q0+16w, q0+16w+16).
// smem: 2 KV stages only. Stage s at s*32768: KH +0, KL +8192, VH +16384,
// VL +24576; 64 rows x 128B, XOR-swizzled 16B chunks. Total 65536 B.
// ---------------------------------------------------------------------------
#define ATTN_SMEM 65536
#define SWC(r, c) (((c) ^ ((r) & 7)) * 16)

__device__ __forceinline__ void attn_issue_kv(uint32_t sb, int st, int bh, int t, int tid) {
    const uint32_t base = sb + st * 32768;
    const __nv_bfloat16* srcs[4] = { g_kh, g_kl, g_vh, g_vl };
#pragma unroll
    for (int i = 0; i < 8; i++) {
        const int e   = tid + i * 256;        // 0..2047
        const int sel = e >> 9;
        const int c   = e & 511, r = c >> 3, cc = c & 7;
        cpa16(base + sel * 8192 + r * 128 + SWC(r, cc),
              srcs[sel] + ((size_t)bh * SEQ + t * 64 + r) * HD + cc * 8);
    }
    cpa_commit();
}

__global__ __launch_bounds__(256, 2) void flash_attn(float* __restrict__ out) {
    extern __shared__ char smem[];
    const uint32_t sb = (uint32_t)__cvta_generic_to_shared(smem);

    const int tid  = threadIdx.x;
    const int bh   = blockIdx.y;
    const int q0   = blockIdx.x * 128;
    const int wid  = tid >> 5;
    const int lane = tid & 31;
    const int g    = lane >> 2;       // group row
    const int tig  = lane & 3;
    const int ln   = lane & 15;       // ldsm x2 address lanes
    const int lr   = ln & 7;
    const int lmat = ln >> 3;

    attn_issue_kv(sb, 0, bh, 0, tid);

    // Q fragments (hi+lo) straight from gmem; Q pre-scaled by 1/8.
    uint32_t qh[4][4], ql[4][4];
    {
        const size_t qb = ((size_t)bh * SEQ + q0 + wid * 16 + g) * HD;
#pragma unroll
        for (int kd = 0; kd < 4; kd++) {
            const int c0 = kd * 16 + 2 * tig;
            qh[kd][0] = *(const uint32_t*)(g_qh + qb + c0);
            qh[kd][1] = *(const uint32_t*)(g_qh + qb + 8 * HD + c0);
            qh[kd][2] = *(const uint32_t*)(g_qh + qb + c0 + 8);
            qh[kd][3] = *(const uint32_t*)(g_qh + qb + 8 * HD + c0 + 8);
            ql[kd][0] = *(const uint32_t*)(g_ql + qb + c0);
            ql[kd][1] = *(const uint32_t*)(g_ql + qb + 8 * HD + c0);
            ql[kd][2] = *(const uint32_t*)(g_ql + qb + c0 + 8);
            ql[kd][3] = *(const uint32_t*)(g_ql + qb + 8 * HD + c0 + 8);
        }
    }

    float o[8][4];
#pragma unroll
    for (int j = 0; j < 8; j++)
#pragma unroll
        for (int e = 0; e < 4; e++) o[j][e] = 0.0f;
    float m0 = -1e30f, m1 = -1e30f, l0 = 0.0f, l1 = 0.0f;

    for (int t = 0; t < 32; t++) {
        cpa_wait_all();
        __syncthreads();
        if (t + 1 < 32) attn_issue_kv(sb, (t + 1) & 1, bh, t + 1, tid);

        const uint32_t kb = sb + (t & 1) * 32768;

        // ---- S = Q K^T : 8 n8 key-groups, 4 k16 d-steps, 3 precision terms
        float s[8][4];
#pragma unroll
        for (int j = 0; j < 8; j++) {
            s[j][0] = s[j][1] = s[j][2] = s[j][3] = 0.0f;
            const int r = 8 * j + lr;
#pragma unroll
            for (int kd = 0; kd < 4; kd++) {
                uint32_t kh0, kh1, kl0, kl1;
                const uint32_t off = r * 128 + SWC(r, 2 * kd + lmat);
                ldsm_x2(kh0, kh1, kb + off);
                ldsm_x2(kl0, kl1, kb + 8192 + off);
                mma16816(s[j], qh[kd][0], qh[kd][1], qh[kd][2], qh[kd][3], kh0, kh1);
                mma16816(s[j], qh[kd][0], qh[kd][1], qh[kd][2], qh[kd][3], kl0, kl1);
                mma16816(s[j], ql[kd][0], ql[kd][1], ql[kd][2], ql[kd][3], kh0, kh1);
            }
        }

        // ---- online softmax (warp-local; rows g and g+8, quad-replicated)
        float mx0 = -1e30f, mx1 = -1e30f;
#pragma unroll
        for (int j = 0; j < 8; j++) {
            mx0 = fmaxf(mx0, fmaxf(s[j][0], s[j][1]));
            mx1 = fmaxf(mx1, fmaxf(s[j][2], s[j][3]));
        }
        mx0 = fmaxf(mx0, __shfl_xor_sync(0xffffffffu, mx0, 1));
        mx0 = fmaxf(mx0, __shfl_xor_sync(0xffffffffu, mx0, 2));
        mx1 = fmaxf(mx1, __shfl_xor_sync(0xffffffffu, mx1, 1));
        mx1 = fmaxf(mx1, __shfl_xor_sync(0xffffffffu, mx1, 2));
        const float mn0 = fmaxf(m0, mx0), mn1 = fmaxf(m1, mx1);
        const float a0 = __expf(m0 - mn0), a1 = __expf(m1 - mn1);
        m0 = mn0; m1 = mn1;

        float rs0 = 0.0f, rs1 = 0.0f;
#pragma unroll
        for (int j = 0; j < 8; j++) {
            s[j][0] = __expf(s[j][0] - mn0);
            s[j][1] = __expf(s[j][1] - mn0);
            s[j][2] = __expf(s[j][2] - mn1);
            s[j][3] = __expf(s[j][3] - mn1);
            rs0 += s[j][0] + s[j][1];
            rs1 += s[j][2] + s[j][3];
        }
        rs0 += __shfl_xor_sync(0xffffffffu, rs0, 1);
        rs0 += __shfl_xor_sync(0xffffffffu, rs0, 2);
        rs1 += __shfl_xor_sync(0xffffffffu, rs1, 1);
        rs1 += __shfl_xor_sync(0xffffffffu, rs1, 2);
        l0 = l0 * a0 + rs0;
        l1 = l1 * a1 + rs1;
#pragma unroll
        for (int j = 0; j < 8; j++) {
            o[j][0] *= a0; o[j][1] *= a0; o[j][2] *= a1; o[j][3] *= a1;
        }

        // ---- O += P V : per k16 key-block, build P frags (hi/lo) from s regs
#pragma unroll
        for (int kk = 0; kk < 4; kk++) {
            const float* p0 = s[2 * kk];
            const float* p1 = s[2 * kk + 1];
            float h[8];
            h[0] = __bfloat162float(__float2bfloat16(p0[0]));
            h[1] = __bfloat162float(__float2bfloat16(p0[1]));
            h[2] = __bfloat162float(__float2bfloat16(p0[2]));
            h[3] = __bfloat162float(__float2bfloat16(p0[3]));
            h[4] = __bfloat162float(__float2bfloat16(p1[0]));
            h[5] = __bfloat162float(__float2bfloat16(p1[1]));
            h[6] = __bfloat162float(__float2bfloat16(p1[2]));
            h[7] = __bfloat162float(__float2bfloat16(p1[3]));
            const uint32_t ah0 = packbf(h[0], h[1]), ah1 = packbf(h[2], h[3]);
            const uint32_t ah2 = packbf(h[4], h[5]), ah3 = packbf(h[6], h[7]);
            const uint32_t al0 = packbf(p0[0] - h[0], p0[1] - h[1]);
            const uint32_t al1 = packbf(p0[2] - h[2], p0[3] - h[3]);
            const uint32_t al2 = packbf(p1[0] - h[4], p1[1] - h[5]);
            const uint32_t al3 = packbf(p1[2] - h[6], p1[3] - h[7]);

            const int r = 16 * kk + 8 * lmat + lr;
#pragma unroll
            for (int n = 0; n < 8; n++) {
                uint32_t vh0, vh1, vl0, vl1;
                const uint32_t off = r * 128 + SWC(r, n);
                ldsm_x2_t(vh0, vh1, kb + 16384 + off);
                ldsm_x2_t(vl0, vl1, kb + 24576 + off);
                mma16816(o[n], ah0, ah1, ah2, ah3, vh0, vh1);
                mma16816(o[n], ah0, ah1, ah2, ah3, vl0, vl1);
                mma16816(o[n], al0, al1, al2, al3, vh0, vh1);
            }
        }
    }

    // ---- epilogue
    const float i0 = 1.0f / l0, i1 = 1.0f / l1;
    const size_t ob = ((size_t)bh * SEQ + q0 + wid * 16 + g) * HD;
#pragma unroll
    for (int j = 0; j < 8; j++) {
        const int c0 = 8 * j + 2 * tig;
        *(float2*)(out + ob + c0)          = make_float2(o[j][0] * i0, o[j][1] * i0);
        *(float2*)(out + ob + 8 * HD + c0) = make_float2(o[j][2] * i1, o[j][3] * i1);
    }
}

// ---------------------------------------------------------------------------
extern "C" void kernel_launch(void* const* d_in, const int* in_sizes, int n_in,
                              void* d_out, int out_size) {
    const float* x = (const float*)d_in[0];
    const float* w = (const float*)d_in[1];
    float* out = (float*)d_out;

    cudaFuncSetAttribute(qkv_gemm, cudaFuncAttributeMaxDynamicSharedMemorySize, QKV_SMEM);
    cudaFuncSetAttribute(flash_attn, cudaFuncAttributeMaxDynamicSharedMemorySize, ATTN_SMEM);

    presplit<<<1024, 256>>>(x, w);
    qkv_gemm<<<dim3(NTOT / 128, MTOT / 128), 256, QKV_SMEM>>>();
    flash_attn<<<dim3(SEQ / 128, BATCH * HEADS), 256, ATTN_SMEM>>>(out);
}

// round 10
// speedup vs baseline: 2.7845x; 1.2255x over previous
#include <cuda_runtime.h>
#include <cuda_bf16.h>
#include <stdint.h>

#define HEADS 16
#define HD    64
#define SEQ   2048
#define BATCH 2
#define KDIM  1024
#define NTOT  3072
#define MTOT  4096
#define QKV_ELEMS (BATCH * HEADS * SEQ * HD)

__device__ __nv_bfloat16 g_xh[MTOT * KDIM], g_xl[MTOT * KDIM];
__device__ __nv_bfloat16 g_wh[KDIM * NTOT], g_wl[KDIM * NTOT];
__device__ __nv_bfloat16 g_qh[QKV_ELEMS], g_ql[QKV_ELEMS];
__device__ __nv_bfloat16 g_kh[QKV_ELEMS], g_kl[QKV_ELEMS];
__device__ __nv_bfloat16 g_vh[QKV_ELEMS], g_vl[QKV_ELEMS];

__device__ __forceinline__ void split_bf16(float x, __nv_bfloat16& hi, __nv_bfloat16& lo) {
    hi = __float2bfloat16(x);
    lo = __float2bfloat16(x - __bfloat162float(hi));
}
__device__ __forceinline__ void cpa16(uint32_t dst, const void* src) {
    asm volatile("cp.async.cg.shared.global [%0], [%1], 16;\n" :: "r"(dst), "l"(src));
}
__device__ __forceinline__ void cpa_commit() { asm volatile("cp.async.commit_group;\n"); }
__device__ __forceinline__ void cpa_wait_all() { asm volatile("cp.async.wait_group 0;\n"); }

__device__ __forceinline__ void ldsm_x2(uint32_t& r0, uint32_t& r1, uint32_t addr) {
    asm volatile("ldmatrix.sync.aligned.m8n8.x2.shared.b16 {%0,%1}, [%2];"
                 : "=r"(r0), "=r"(r1) : "r"(addr));
}
__device__ __forceinline__ void ldsm_x4(uint32_t& r0, uint32_t& r1, uint32_t& r2,
                                        uint32_t& r3, uint32_t addr) {
    asm volatile("ldmatrix.sync.aligned.m8n8.x4.shared.b16 {%0,%1,%2,%3}, [%4];"
                 : "=r"(r0), "=r"(r1), "=r"(r2), "=r"(r3) : "r"(addr));
}
__device__ __forceinline__ void ldsm_x2_t(uint32_t& r0, uint32_t& r1, uint32_t addr) {
    asm volatile("ldmatrix.sync.aligned.m8n8.x2.trans.shared.b16 {%0,%1}, [%2];"
                 : "=r"(r0), "=r"(r1) : "r"(addr));
}
__device__ __forceinline__ void mma16816(float* c, uint32_t a0, uint32_t a1, uint32_t a2,
                                         uint32_t a3, uint32_t b0, uint32_t b1) {
    asm volatile("mma.sync.aligned.m16n8k16.row.col.f32.bf16.bf16.f32 "
                 "{%0,%1,%2,%3}, {%4,%5,%6,%7}, {%8,%9}, {%0,%1,%2,%3};"
                 : "+f"(c[0]), "+f"(c[1]), "+f"(c[2]), "+f"(c[3])
                 : "r"(a0), "r"(a1), "r"(a2), "r"(a3), "r"(b0), "r"(b1));
}
__device__ __forceinline__ uint32_t packbf(float x, float y) {
    __nv_bfloat162 t = __floats2bfloat162_rn(x, y);
    return *(uint32_t*)&t;
}

// ---------------------------------------------------------------------------
// Kernel 0: split X and W into bf16 hi/lo
// ---------------------------------------------------------------------------
#define NX4 (MTOT * KDIM / 4)
#define NW4 (KDIM * NTOT / 4)
__global__ void presplit(const float* __restrict__ X, const float* __restrict__ W) {
    for (int i = blockIdx.x * blockDim.x + threadIdx.x; i < NX4 + NW4;
         i += gridDim.x * blockDim.x) {
        float4 v; __nv_bfloat16 *dh, *dl; size_t off;
        if (i < NX4) { v = ((const float4*)X)[i]; dh = g_xh; dl = g_xl; off = (size_t)i * 4; }
        else { v = ((const float4*)W)[i - NX4]; dh = g_wh; dl = g_wl; off = (size_t)(i - NX4) * 4; }
        __nv_bfloat16 h0,h1,h2,h3,l0,l1,l2,l3;
        split_bf16(v.x,h0,l0); split_bf16(v.y,h1,l1);
        split_bf16(v.z,h2,l2); split_bf16(v.w,h3,l3);
        ((__nv_bfloat162*)(dh+off))[0] = __halves2bfloat162(h0,h1);
        ((__nv_bfloat162*)(dh+off))[1] = __halves2bfloat162(h2,h3);
        ((__nv_bfloat162*)(dl+off))[0] = __halves2bfloat162(l0,l1);
        ((__nv_bfloat162*)(dl+off))[1] = __halves2bfloat162(l2,l3);
    }
}

// ---------------------------------------------------------------------------
// Kernel 1: QKV GEMM, raw mma.sync bf16x3, cp.async double-buffered.
// Tile 128x128, k-step 32; 8 warps (4m x 2n), warp tile 32x64.
// smem per stage: AH row-pitch 40 bf16 (80B: ldmatrix conflict-free),
//                 BH row-pitch 136 bf16 (272B: conflict-free).
// Layout (bytes): st*20480: AH +0, AL +10240 | 40960 + st*17408: BH +0, BL +8704
// ---------------------------------------------------------------------------
#define QKV_SMEM 75776

__device__ __forceinline__ void qkv_issue_stage(uint32_t sb, int st, int k0,
                                                int tid, int mBase, int nBase) {
    const uint32_t ab = sb + st * 20480;
#pragma unroll
    for (int i = 0; i < 4; i++) {
        const int e = tid + i * 256;
        const __nv_bfloat16* src = (e < 512) ? g_xh : g_xl;
        const int c = e & 511, row = c >> 2, cc = c & 3;
        cpa16(ab + (e < 512 ? 0 : 10240) + row * 80 + cc * 16,
              src + (size_t)(mBase + row) * KDIM + k0 + cc * 8);
    }
    const uint32_t bb = sb + 40960 + st * 17408;
#pragma unroll
    for (int i = 0; i < 4; i++) {
        const int e = tid + i * 256;
        const __nv_bfloat16* src = (e < 512) ? g_wh : g_wl;
        const int c = e & 511, row = c >> 4, cc = c & 15;
        cpa16(bb + (e < 512 ? 0 : 8704) + row * 272 + cc * 16,
              src + (size_t)(k0 + row) * NTOT + nBase + cc * 8);
    }
    cpa_commit();
}

__global__ __launch_bounds__(256, 2) void qkv_gemm() {
    extern __shared__ char smem[];
    const uint32_t sb = (uint32_t)__cvta_generic_to_shared(smem);

    const int tid   = threadIdx.x;
    const int lane  = tid & 31;
    const int wid   = tid >> 5;
    const int wm    = wid >> 1;          // 0..3 -> m offset 32*wm
    const int wn    = wid & 1;           // 0..1 -> n offset 64*wn
    const int mBase = blockIdx.y * 128;
    const int nBase = blockIdx.x * 128;
    const int g     = lane >> 2;
    const int tig   = lane & 3;
    const int ln    = lane & 15;
    const int lr    = ln & 7;
    const int lmat  = ln >> 3;

    // ldmatrix x4 A-address components (per lane)
    const int arow_off = (lane & 7) + (lane & 8);   // row within 16-row tile
    const int acol_off = (lane & 16) ? 16 : 0;      // byte offset within k16 (2x8 cols)

    float acc[2][8][4];
#pragma unroll
    for (int mi = 0; mi < 2; mi++)
#pragma unroll
        for (int n = 0; n < 8; n++)
#pragma unroll
            for (int e = 0; e < 4; e++) acc[mi][n][e] = 0.0f;

    qkv_issue_stage(sb, 0, 0, tid, mBase, nBase);

    for (int kt = 0; kt < 32; kt++) {
        cpa_wait_all();
        __syncthreads();
        if (kt + 1 < 32) qkv_issue_stage(sb, (kt + 1) & 1, (kt + 1) * 32, tid, mBase, nBase);

        const int st = kt & 1;
        const uint32_t abase = sb + st * 20480;
        const uint32_t bbase = sb + 40960 + st * 17408;

#pragma unroll
        for (int kd = 0; kd < 2; kd++) {
            // A fragments: 2 m16 tiles, hi + lo
            uint32_t ah[2][4], al[2][4];
#pragma unroll
            for (int mi = 0; mi < 2; mi++) {
                const uint32_t ra = abase + (uint32_t)(wm * 32 + mi * 16 + arow_off) * 80
                                  + kd * 32 + acol_off;
                ldsm_x4(ah[mi][0], ah[mi][1], ah[mi][2], ah[mi][3], ra);
                ldsm_x4(al[mi][0], al[mi][1], al[mi][2], al[mi][3], ra + 10240);
            }
            // B: 8 n8 blocks (trans ldmatrix), hi + lo; 3-term mma
            const uint32_t rb = bbase + (uint32_t)(kd * 16 + 8 * lmat + lr) * 272;
#pragma unroll
            for (int n = 0; n < 8; n++) {
                const uint32_t cb = rb + (uint32_t)(wn * 64 + n * 8) * 2;
                uint32_t bh0, bh1, bl0, bl1;
                ldsm_x2_t(bh0, bh1, cb);
                ldsm_x2_t(bl0, bl1, cb + 8704);
#pragma unroll
                for (int mi = 0; mi < 2; mi++) {
                    mma16816(acc[mi][n], ah[mi][0], ah[mi][1], ah[mi][2], ah[mi][3], bh0, bh1);
                    mma16816(acc[mi][n], ah[mi][0], ah[mi][1], ah[mi][2], ah[mi][3], bl0, bl1);
                    mma16816(acc[mi][n], al[mi][0], al[mi][1], al[mi][2], al[mi][3], bh0, bh1);
                }
            }
        }
        __syncthreads();
    }

    // Epilogue: write split q/k/v straight from accumulators.
    // Thread holds rows (m0+g, m0+g+8), cols (c0, c0+1) per (mi, n).
#pragma unroll
    for (int mi = 0; mi < 2; mi++) {
        const int row0 = mBase + wm * 32 + mi * 16 + g;
        const int b_   = row0 >> 11;
        const int n0_  = row0 & 2047;
#pragma unroll
        for (int n = 0; n < 8; n++) {
            const int col0  = nBase + wn * 64 + n * 8 + tig * 2;
            const int third = col0 >> 10;
            const int h     = (col0 & 1023) >> 6;
            const int d     = col0 & 63;
            const float scale = (third == 0) ? 0.125f : 1.0f;
            __nv_bfloat16* dh = (third == 0) ? g_qh : ((third == 1) ? g_kh : g_vh);
            __nv_bfloat16* dl = (third == 0) ? g_ql : ((third == 1) ? g_kl : g_vl);
            const size_t base = ((size_t)((b_ * HEADS + h) * SEQ + n0_)) * HD + d;
            __nv_bfloat16 h0, l0v, h1, l1v;
            split_bf16(acc[mi][n][0] * scale, h0, l0v);
            split_bf16(acc[mi][n][1] * scale, h1, l1v);
            *(__nv_bfloat162*)(dh + base) = __halves2bfloat162(h0, h1);
            *(__nv_bfloat162*)(dl + base) = __halves2bfloat162(l0v, l1v);
            split_bf16(acc[mi][n][2] * scale, h0, l0v);
            split_bf16(acc[mi][n][3] * scale, h1, l1v);
            *(__nv_bfloat162*)(dh + base + 8 * HD) = __halves2bfloat162(h0, h1);
            *(__nv_bfloat162*)(dl + base + 8 * HD) = __halves2bfloat162(l0v, l1v);
        }
    }
}

// ---------------------------------------------------------------------------
// Kernel 2: register-resident flash attention (unchanged from round 8)
// ---------------------------------------------------------------------------
#define ATTN_SMEM 65536
#define SWC(r, c) (((c) ^ ((r) & 7)) * 16)

__device__ __forceinline__ void attn_issue_kv(uint32_t sb, int st, int bh, int t, int tid) {
    const uint32_t base = sb + st * 32768;
    const __nv_bfloat16* srcs[4] = { g_kh, g_kl, g_vh, g_vl };
#pragma unroll
    for (int i = 0; i < 8; i++) {
        const int e   = tid + i * 256;
        const int sel = e >> 9;
        const int c   = e & 511, r = c >> 3, cc = c & 7;
        cpa16(base + sel * 8192 + r * 128 + SWC(r, cc),
              srcs[sel] + ((size_t)bh * SEQ + t * 64 + r) * HD + cc * 8);
    }
    cpa_commit();
}

__global__ __launch_bounds__(256, 2) void flash_attn(float* __restrict__ out) {
    extern __shared__ char smem[];
    const uint32_t sb = (uint32_t)__cvta_generic_to_shared(smem);

    const int tid  = threadIdx.x;
    const int bh   = blockIdx.y;
    const int q0   = blockIdx.x * 128;
    const int wid  = tid >> 5;
    const int lane = tid & 31;
    const int g    = lane >> 2;
    const int tig  = lane & 3;
    const int ln   = lane & 15;
    const int lr   = ln & 7;
    const int lmat = ln >> 3;

    attn_issue_kv(sb, 0, bh, 0, tid);

    uint32_t qh[4][4], ql[4][4];
    {
        const size_t qb = ((size_t)bh * SEQ + q0 + wid * 16 + g) * HD;
#pragma unroll
        for (int kd = 0; kd < 4; kd++) {
            const int c0 = kd * 16 + 2 * tig;
            qh[kd][0] = *(const uint32_t*)(g_qh + qb + c0);
            qh[kd][1] = *(const uint32_t*)(g_qh + qb + 8 * HD + c0);
            qh[kd][2] = *(const uint32_t*)(g_qh + qb + c0 + 8);
            qh[kd][3] = *(const uint32_t*)(g_qh + qb + 8 * HD + c0 + 8);
            ql[kd][0] = *(const uint32_t*)(g_ql + qb + c0);
            ql[kd][1] = *(const uint32_t*)(g_ql + qb + 8 * HD + c0);
            ql[kd][2] = *(const uint32_t*)(g_ql + qb + c0 + 8);
            ql[kd][3] = *(const uint32_t*)(g_ql + qb + 8 * HD + c0 + 8);
        }
    }

    float o[8][4];
#pragma unroll
    for (int j = 0; j < 8; j++)
#pragma unroll
        for (int e = 0; e < 4; e++) o[j][e] = 0.0f;
    float m0 = -1e30f, m1 = -1e30f, l0 = 0.0f, l1 = 0.0f;

    for (int t = 0; t < 32; t++) {
        cpa_wait_all();
        __syncthreads();
        if (t + 1 < 32) attn_issue_kv(sb, (t + 1) & 1, bh, t + 1, tid);

        const uint32_t kb = sb + (t & 1) * 32768;

        float s[8][4];
#pragma unroll
        for (int j = 0; j < 8; j++) {
            s[j][0] = s[j][1] = s[j][2] = s[j][3] = 0.0f;
            const int r = 8 * j + lr;
#pragma unroll
            for (int kd = 0; kd < 4; kd++) {
                uint32_t kh0, kh1, kl0, kl1;
                const uint32_t off = r * 128 + SWC(r, 2 * kd + lmat);
                ldsm_x2(kh0, kh1, kb + off);
                ldsm_x2(kl0, kl1, kb + 8192 + off);
                mma16816(s[j], qh[kd][0], qh[kd][1], qh[kd][2], qh[kd][3], kh0, kh1);
                mma16816(s[j], qh[kd][0], qh[kd][1], qh[kd][2], qh[kd][3], kl0, kl1);
                mma16816(s[j], ql[kd][0], ql[kd][1], ql[kd][2], ql[kd][3], kh0, kh1);
            }
        }

        float mx0 = -1e30f, mx1 = -1e30f;
#pragma unroll
        for (int j = 0; j < 8; j++) {
            mx0 = fmaxf(mx0, fmaxf(s[j][0], s[j][1]));
            mx1 = fmaxf(mx1, fmaxf(s[j][2], s[j][3]));
        }
        mx0 = fmaxf(mx0, __shfl_xor_sync(0xffffffffu, mx0, 1));
        mx0 = fmaxf(mx0, __shfl_xor_sync(0xffffffffu, mx0, 2));
        mx1 = fmaxf(mx1, __shfl_xor_sync(0xffffffffu, mx1, 1));
        mx1 = fmaxf(mx1, __shfl_xor_sync(0xffffffffu, mx1, 2));
        const float mn0 = fmaxf(m0, mx0), mn1 = fmaxf(m1, mx1);
        const float a0 = __expf(m0 - mn0), a1 = __expf(m1 - mn1);
        m0 = mn0; m1 = mn1;

        float rs0 = 0.0f, rs1 = 0.0f;
#pragma unroll
        for (int j = 0; j < 8; j++) {
            s[j][0] = __expf(s[j][0] - mn0);
            s[j][1] = __expf(s[j][1] - mn0);
            s[j][2] = __expf(s[j][2] - mn1);
            s[j][3] = __expf(s[j][3] - mn1);
            rs0 += s[j][0] + s[j][1];
            rs1 += s[j][2] + s[j][3];
        }
        rs0 += __shfl_xor_sync(0xffffffffu, rs0, 1);
        rs0 += __shfl_xor_sync(0xffffffffu, rs0, 2);
        rs1 += __shfl_xor_sync(0xffffffffu, rs1, 1);
        rs1 += __shfl_xor_sync(0xffffffffu, rs1, 2);
        l0 = l0 * a0 + rs0;
        l1 = l1 * a1 + rs1;
#pragma unroll
        for (int j = 0; j < 8; j++) {
            o[j][0] *= a0; o[j][1] *= a0; o[j][2] *= a1; o[j][3] *= a1;
        }

#pragma unroll
        for (int kk = 0; kk < 4; kk++) {
            const float* p0 = s[2 * kk];
            const float* p1 = s[2 * kk + 1];
            float h[8];
            h[0] = __bfloat162float(__float2bfloat16(p0[0]));
            h[1] = __bfloat162float(__float2bfloat16(p0[1]));
            h[2] = __bfloat162float(__float2bfloat16(p0[2]));
            h[3] = __bfloat162float(__float2bfloat16(p0[3]));
            h[4] = __bfloat162float(__float2bfloat16(p1[0]));
            h[5] = __bfloat162float(__float2bfloat16(p1[1]));
            h[6] = __bfloat162float(__float2bfloat16(p1[2]));
            h[7] = __bfloat162float(__float2bfloat16(p1[3]));
            const uint32_t ah0 = packbf(h[0], h[1]), ah1 = packbf(h[2], h[3]);
            const uint32_t ah2 = packbf(h[4], h[5]), ah3 = packbf(h[6], h[7]);
            const uint32_t al0 = packbf(p0[0] - h[0], p0[1] - h[1]);
            const uint32_t al1 = packbf(p0[2] - h[2], p0[3] - h[3]);
            const uint32_t al2 = packbf(p1[0] - h[4], p1[1] - h[5]);
            const uint32_t al3 = packbf(p1[2] - h[6], p1[3] - h[7]);

            const int r = 16 * kk + 8 * lmat + lr;
#pragma unroll
            for (int n = 0; n < 8; n++) {
                uint32_t vh0, vh1, vl0, vl1;
                const uint32_t off = r * 128 + SWC(r, n);
                ldsm_x2_t(vh0, vh1, kb + 16384 + off);
                ldsm_x2_t(vl0, vl1, kb + 24576 + off);
                mma16816(o[n], ah0, ah1, ah2, ah3, vh0, vh1);
                mma16816(o[n], ah0, ah1, ah2, ah3, vl0, vl1);
                mma16816(o[n], al0, al1, al2, al3, vh0, vh1);
            }
        }
    }

    const float i0 = 1.0f / l0, i1 = 1.0f / l1;
    const size_t ob = ((size_t)bh * SEQ + q0 + wid * 16 + g) * HD;
#pragma unroll
    for (int j = 0; j < 8; j++) {
        const int c0 = 8 * j + 2 * tig;
        *(float2*)(out + ob + c0)          = make_float2(o[j][0] * i0, o[j][1] * i0);
        *(float2*)(out + ob + 8 * HD + c0) = make_float2(o[j][2] * i1, o[j][3] * i1);
    }
}

// ---------------------------------------------------------------------------
extern "C" void kernel_launch(void* const* d_in, const int* in_sizes, int n_in,
                              void* d_out, int out_size) {
    const float* x = (const float*)d_in[0];
    const float* w = (const float*)d_in[1];
    float* out = (float*)d_out;

    cudaFuncSetAttribute(qkv_gemm, cudaFuncAttributeMaxDynamicSharedMemorySize, QKV_SMEM);
    cudaFuncSetAttribute(flash_attn, cudaFuncAttributeMaxDynamicSharedMemorySize, ATTN_SMEM);

    presplit<<<1024, 256>>>(x, w);
    qkv_gemm<<<dim3(NTOT / 128, MTOT / 128), 256, QKV_SMEM>>>();
    flash_attn<<<dim3(SEQ / 128, BATCH * HEADS), 256, ATTN_SMEM>>>(out);
}

// round 12
// speedup vs baseline: 2.7939x; 1.0034x over previous
#include <cuda_runtime.h>
#include <cuda_bf16.h>
#include <stdint.h>

#define HEADS 16
#define HD    64
#define SEQ   2048
#define BATCH 2
#define KDIM  1024
#define NTOT  3072
#define MTOT  4096
#define QKV_ELEMS (BATCH * HEADS * SEQ * HD)

__device__ __nv_bfloat16 g_xh[MTOT * KDIM], g_xl[MTOT * KDIM];
__device__ __nv_bfloat16 g_wh[KDIM * NTOT], g_wl[KDIM * NTOT];
__device__ __nv_bfloat16 g_qh[QKV_ELEMS], g_ql[QKV_ELEMS];
__device__ __nv_bfloat16 g_kh[QKV_ELEMS], g_kl[QKV_ELEMS];
__device__ __nv_bfloat16 g_vh[QKV_ELEMS], g_vl[QKV_ELEMS];

__device__ __forceinline__ void split_bf16(float x, __nv_bfloat16& hi, __nv_bfloat16& lo) {
    hi = __float2bfloat16(x);
    lo = __float2bfloat16(x - __bfloat162float(hi));
}
__device__ __forceinline__ void cpa16(uint32_t dst, const void* src) {
    asm volatile("cp.async.cg.shared.global [%0], [%1], 16;\n" :: "r"(dst), "l"(src));
}
__device__ __forceinline__ void cpa_commit() { asm volatile("cp.async.commit_group;\n"); }
__device__ __forceinline__ void cpa_wait_all() { asm volatile("cp.async.wait_group 0;\n"); }

__device__ __forceinline__ void ldsm_x2(uint32_t& r0, uint32_t& r1, uint32_t addr) {
    asm volatile("ldmatrix.sync.aligned.m8n8.x2.shared.b16 {%0,%1}, [%2];"
                 : "=r"(r0), "=r"(r1) : "r"(addr));
}
__device__ __forceinline__ void ldsm_x4(uint32_t& r0, uint32_t& r1, uint32_t& r2,
                                        uint32_t& r3, uint32_t addr) {
    asm volatile("ldmatrix.sync.aligned.m8n8.x4.shared.b16 {%0,%1,%2,%3}, [%4];"
                 : "=r"(r0), "=r"(r1), "=r"(r2), "=r"(r3) : "r"(addr));
}
__device__ __forceinline__ void ldsm_x2_t(uint32_t& r0, uint32_t& r1, uint32_t addr) {
    asm volatile("ldmatrix.sync.aligned.m8n8.x2.trans.shared.b16 {%0,%1}, [%2];"
                 : "=r"(r0), "=r"(r1) : "r"(addr));
}
__device__ __forceinline__ void mma16816(float* c, uint32_t a0, uint32_t a1, uint32_t a2,
                                         uint32_t a3, uint32_t b0, uint32_t b1) {
    asm volatile("mma.sync.aligned.m16n8k16.row.col.f32.bf16.bf16.f32 "
                 "{%0,%1,%2,%3}, {%4,%5,%6,%7}, {%8,%9}, {%0,%1,%2,%3};"
                 : "+f"(c[0]), "+f"(c[1]), "+f"(c[2]), "+f"(c[3])
                 : "r"(a0), "r"(a1), "r"(a2), "r"(a3), "r"(b0), "r"(b1));
}
__device__ __forceinline__ uint32_t packbf(float x, float y) {
    __nv_bfloat162 t = __floats2bfloat162_rn(x, y);
    return *(uint32_t*)&t;
}

// ---------------------------------------------------------------------------
// Kernel 0: split X and W into bf16 hi/lo
// ---------------------------------------------------------------------------
#define NX4 (MTOT * KDIM / 4)
#define NW4 (KDIM * NTOT / 4)
__global__ void presplit(const float* __restrict__ X, const float* __restrict__ W) {
    for (int i = blockIdx.x * blockDim.x + threadIdx.x; i < NX4 + NW4;
         i += gridDim.x * blockDim.x) {
        float4 v; __nv_bfloat16 *dh, *dl; size_t off;
        if (i < NX4) { v = ((const float4*)X)[i]; dh = g_xh; dl = g_xl; off = (size_t)i * 4; }
        else { v = ((const float4*)W)[i - NX4]; dh = g_wh; dl = g_wl; off = (size_t)(i - NX4) * 4; }
        __nv_bfloat16 h0,h1,h2,h3,l0,l1,l2,l3;
        split_bf16(v.x,h0,l0); split_bf16(v.y,h1,l1);
        split_bf16(v.z,h2,l2); split_bf16(v.w,h3,l3);
        ((__nv_bfloat162*)(dh+off))[0] = __halves2bfloat162(h0,h1);
        ((__nv_bfloat162*)(dh+off))[1] = __halves2bfloat162(h2,h3);
        ((__nv_bfloat162*)(dl+off))[0] = __halves2bfloat162(l0,l1);
        ((__nv_bfloat162*)(dl+off))[1] = __halves2bfloat162(l2,l3);
    }
}

// ---------------------------------------------------------------------------
// Kernel 1: QKV GEMM, raw mma.sync bf16x3, cp.async double-buffered.
// ILP fix: n-pairs interleaved, term-major mma order (same-acc distance 4).
// ---------------------------------------------------------------------------
#define QKV_SMEM 75776

__device__ __forceinline__ void qkv_issue_stage(uint32_t sb, int st, int k0,
                                                int tid, int mBase, int nBase) {
    const uint32_t ab = sb + st * 20480;
#pragma unroll
    for (int i = 0; i < 4; i++) {
        const int e = tid + i * 256;
        const __nv_bfloat16* src = (e < 512) ? g_xh : g_xl;
        const int c = e & 511, row = c >> 2, cc = c & 3;
        cpa16(ab + (e < 512 ? 0 : 10240) + row * 80 + cc * 16,
              src + (size_t)(mBase + row) * KDIM + k0 + cc * 8);
    }
    const uint32_t bb = sb + 40960 + st * 17408;
#pragma unroll
    for (int i = 0; i < 4; i++) {
        const int e = tid + i * 256;
        const __nv_bfloat16* src = (e < 512) ? g_wh : g_wl;
        const int c = e & 511, row = c >> 4, cc = c & 15;
        cpa16(bb + (e < 512 ? 0 : 8704) + row * 272 + cc * 16,
              src + (size_t)(k0 + row) * NTOT + nBase + cc * 8);
    }
    cpa_commit();
}

__global__ __launch_bounds__(256, 2) void qkv_gemm() {
    extern __shared__ char smem[];
    const uint32_t sb = (uint32_t)__cvta_generic_to_shared(smem);

    const int tid   = threadIdx.x;
    const int lane  = tid & 31;
    const int wid   = tid >> 5;
    const int wm    = wid >> 1;
    const int wn    = wid & 1;
    const int mBase = blockIdx.y * 128;
    const int nBase = blockIdx.x * 128;
    const int g     = lane >> 2;
    const int tig   = lane & 3;
    const int ln    = lane & 15;
    const int lr    = ln & 7;
    const int lmat  = ln >> 3;

    const int arow_off = (lane & 7) + (lane & 8);
    const int acol_off = (lane & 16) ? 16 : 0;

    float acc[2][8][4];
#pragma unroll
    for (int mi = 0; mi < 2; mi++)
#pragma unroll
        for (int n = 0; n < 8; n++)
#pragma unroll
            for (int e = 0; e < 4; e++) acc[mi][n][e] = 0.0f;

    qkv_issue_stage(sb, 0, 0, tid, mBase, nBase);

    for (int kt = 0; kt < 32; kt++) {
        cpa_wait_all();
        __syncthreads();
        if (kt + 1 < 32) qkv_issue_stage(sb, (kt + 1) & 1, (kt + 1) * 32, tid, mBase, nBase);

        const int st = kt & 1;
        const uint32_t abase = sb + st * 20480;
        const uint32_t bbase = sb + 40960 + st * 17408;

#pragma unroll
        for (int kd = 0; kd < 2; kd++) {
            uint32_t ah[2][4], al[2][4];
#pragma unroll
            for (int mi = 0; mi < 2; mi++) {
                const uint32_t ra = abase + (uint32_t)(wm * 32 + mi * 16 + arow_off) * 80
                                  + kd * 32 + acol_off;
                ldsm_x4(ah[mi][0], ah[mi][1], ah[mi][2], ah[mi][3], ra);
                ldsm_x4(al[mi][0], al[mi][1], al[mi][2], al[mi][3], ra + 10240);
            }
            const uint32_t rb = bbase + (uint32_t)(kd * 16 + 8 * lmat + lr) * 272;
#pragma unroll
            for (int np = 0; np < 4; np++) {
                const int n0 = 2 * np, n1 = n0 + 1;
                const uint32_t cb0 = rb + (uint32_t)(wn * 64 + n0 * 8) * 2;
                const uint32_t cb1 = rb + (uint32_t)(wn * 64 + n1 * 8) * 2;
                uint32_t bh00, bh01, bl00, bl01, bh10, bh11, bl10, bl11;
                ldsm_x2_t(bh00, bh01, cb0);
                ldsm_x2_t(bl00, bl01, cb0 + 8704);
                ldsm_x2_t(bh10, bh11, cb1);
                ldsm_x2_t(bl10, bl11, cb1 + 8704);
                // term hh (4 independent accs)
                mma16816(acc[0][n0], ah[0][0], ah[0][1], ah[0][2], ah[0][3], bh00, bh01);
                mma16816(acc[1][n0], ah[1][0], ah[1][1], ah[1][2], ah[1][3], bh00, bh01);
                mma16816(acc[0][n1], ah[0][0], ah[0][1], ah[0][2], ah[0][3], bh10, bh11);
                mma16816(acc[1][n1], ah[1][0], ah[1][1], ah[1][2], ah[1][3], bh10, bh11);
                // term hl
                mma16816(acc[0][n0], ah[0][0], ah[0][1], ah[0][2], ah[0][3], bl00, bl01);
                mma16816(acc[1][n0], ah[1][0], ah[1][1], ah[1][2], ah[1][3], bl00, bl01);
                mma16816(acc[0][n1], ah[0][0], ah[0][1], ah[0][2], ah[0][3], bl10, bl11);
                mma16816(acc[1][n1], ah[1][0], ah[1][1], ah[1][2], ah[1][3], bl10, bl11);
                // term lh
                mma16816(acc[0][n0], al[0][0], al[0][1], al[0][2], al[0][3], bh00, bh01);
                mma16816(acc[1][n0], al[1][0], al[1][1], al[1][2], al[1][3], bh00, bh01);
                mma16816(acc[0][n1], al[0][0], al[0][1], al[0][2], al[0][3], bh10, bh11);
                mma16816(acc[1][n1], al[1][0], al[1][1], al[1][2], al[1][3], bh10, bh11);
            }
        }
        __syncthreads();
    }

#pragma unroll
    for (int mi = 0; mi < 2; mi++) {
        const int row0 = mBase + wm * 32 + mi * 16 + g;
        const int b_   = row0 >> 11;
        const int n0_  = row0 & 2047;
#pragma unroll
        for (int n = 0; n < 8; n++) {
            const int col0  = nBase + wn * 64 + n * 8 + tig * 2;
            const int third = col0 >> 10;
            const int h     = (col0 & 1023) >> 6;
            const int d     = col0 & 63;
            const float scale = (third == 0) ? 0.125f : 1.0f;
            __nv_bfloat16* dh = (third == 0) ? g_qh : ((third == 1) ? g_kh : g_vh);
            __nv_bfloat16* dl = (third == 0) ? g_ql : ((third == 1) ? g_kl : g_vl);
            const size_t base = ((size_t)((b_ * HEADS + h) * SEQ + n0_)) * HD + d;
            __nv_bfloat16 h0, l0v, h1, l1v;
            split_bf16(acc[mi][n][0] * scale, h0, l0v);
            split_bf16(acc[mi][n][1] * scale, h1, l1v);
            *(__nv_bfloat162*)(dh + base) = __halves2bfloat162(h0, h1);
            *(__nv_bfloat162*)(dl + base) = __halves2bfloat162(l0v, l1v);
            split_bf16(acc[mi][n][2] * scale, h0, l0v);
            split_bf16(acc[mi][n][3] * scale, h1, l1v);
            *(__nv_bfloat162*)(dh + base + 8 * HD) = __halves2bfloat162(h0, h1);
            *(__nv_bfloat162*)(dl + base + 8 * HD) = __halves2bfloat162(l0v, l1v);
        }
    }
}

// ---------------------------------------------------------------------------
// Kernel 2: register-resident flash attention; ILP fix: j-pairs / n-pairs
// interleaved so same-accumulator mma distance is 2 instead of 1.
// ---------------------------------------------------------------------------
#define ATTN_SMEM 65536
#define SWC(r, c) (((c) ^ ((r) & 7)) * 16)

__device__ __forceinline__ void attn_issue_kv(uint32_t sb, int st, int bh, int t, int tid) {
    const uint32_t base = sb + st * 32768;
    const __nv_bfloat16* srcs[4] = { g_kh, g_kl, g_vh, g_vl };
#pragma unroll
    for (int i = 0; i < 8; i++) {
        const int e   = tid + i * 256;
        const int sel = e >> 9;
        const int c   = e & 511, r = c >> 3, cc = c & 7;
        cpa16(base + sel * 8192 + r * 128 + SWC(r, cc),
              srcs[sel] + ((size_t)bh * SEQ + t * 64 + r) * HD + cc * 8);
    }
    cpa_commit();
}

__global__ __launch_bounds__(256, 2) void flash_attn(float* __restrict__ out) {
    extern __shared__ char smem[];
    const uint32_t sb = (uint32_t)__cvta_generic_to_shared(smem);

    const int tid  = threadIdx.x;
    const int bh   = blockIdx.y;
    const int q0   = blockIdx.x * 128;
    const int wid  = tid >> 5;
    const int lane = tid & 31;
    const int g    = lane >> 2;
    const int tig  = lane & 3;
    const int ln   = lane & 15;
    const int lr   = ln & 7;
    const int lmat = ln >> 3;

    attn_issue_kv(sb, 0, bh, 0, tid);

    uint32_t qh[4][4], ql[4][4];
    {
        const size_t qb = ((size_t)bh * SEQ + q0 + wid * 16 + g) * HD;
#pragma unroll
        for (int kd = 0; kd < 4; kd++) {
            const int c0 = kd * 16 + 2 * tig;
            qh[kd][0] = *(const uint32_t*)(g_qh + qb + c0);
            qh[kd][1] = *(const uint32_t*)(g_qh + qb + 8 * HD + c0);
            qh[kd][2] = *(const uint32_t*)(g_qh + qb + c0 + 8);
            qh[kd][3] = *(const uint32_t*)(g_qh + qb + 8 * HD + c0 + 8);
            ql[kd][0] = *(const uint32_t*)(g_ql + qb + c0);
            ql[kd][1] = *(const uint32_t*)(g_ql + qb + 8 * HD + c0);
            ql[kd][2] = *(const uint32_t*)(g_ql + qb + c0 + 8);
            ql[kd][3] = *(const uint32_t*)(g_ql + qb + 8 * HD + c0 + 8);
        }
    }

    float o[8][4];
#pragma unroll
    for (int j = 0; j < 8; j++)
#pragma unroll
        for (int e = 0; e < 4; e++) o[j][e] = 0.0f;
    float m0 = -1e30f, m1 = -1e30f, l0 = 0.0f, l1 = 0.0f;

    for (int t = 0; t < 32; t++) {
        cpa_wait_all();
        __syncthreads();
        if (t + 1 < 32) attn_issue_kv(sb, (t + 1) & 1, bh, t + 1, tid);

        const uint32_t kb = sb + (t & 1) * 32768;

        // ---- S = Q K^T : j-pairs, term-major interleave
        float s[8][4];
#pragma unroll
        for (int jp = 0; jp < 4; jp++) {
            const int j0 = 2 * jp, j1 = j0 + 1;
            s[j0][0] = s[j0][1] = s[j0][2] = s[j0][3] = 0.0f;
            s[j1][0] = s[j1][1] = s[j1][2] = s[j1][3] = 0.0f;
            const int r0 = 8 * j0 + lr, r1 = 8 * j1 + lr;
#pragma unroll
            for (int kd = 0; kd < 4; kd++) {
                uint32_t kh00, kh01, kl00, kl01, kh10, kh11, kl10, kl11;
                const uint32_t off0 = r0 * 128 + SWC(r0, 2 * kd + lmat);
                const uint32_t off1 = r1 * 128 + SWC(r1, 2 * kd + lmat);
                ldsm_x2(kh00, kh01, kb + off0);
                ldsm_x2(kl00, kl01, kb + 8192 + off0);
                ldsm_x2(kh10, kh11, kb + off1);
                ldsm_x2(kl10, kl11, kb + 8192 + off1);
                mma16816(s[j0], qh[kd][0], qh[kd][1], qh[kd][2], qh[kd][3], kh00, kh01);
                mma16816(s[j1], qh[kd][0], qh[kd][1], qh[kd][2], qh[kd][3], kh10, kh11);
                mma16816(s[j0], qh[kd][0], qh[kd][1], qh[kd][2], qh[kd][3], kl00, kl01);
                mma16816(s[j1], qh[kd][0], qh[kd][1], qh[kd][2], qh[kd][3], kl10, kl11);
                mma16816(s[j0], ql[kd][0], ql[kd][1], ql[kd][2], ql[kd][3], kh00, kh01);
                mma16816(s[j1], ql[kd][0], ql[kd][1], ql[kd][2], ql[kd][3], kh10, kh11);
            }
        }

        float mx0 = -1e30f, mx1 = -1e30f;
#pragma unroll
        for (int j = 0; j < 8; j++) {
            mx0 = fmaxf(mx0, fmaxf(s[j][0], s[j][1]));
            mx1 = fmaxf(mx1, fmaxf(s[j][2], s[j][3]));
        }
        mx0 = fmaxf(mx0, __shfl_xor_sync(0xffffffffu, mx0, 1));
        mx0 = fmaxf(mx0, __shfl_xor_sync(0xffffffffu, mx0, 2));
        mx1 = fmaxf(mx1, __shfl_xor_sync(0xffffffffu, mx1, 1));
        mx1 = fmaxf(mx1, __shfl_xor_sync(0xffffffffu, mx1, 2));
        const float mn0 = fmaxf(m0, mx0), mn1 = fmaxf(m1, mx1);
        const float a0 = __expf(m0 - mn0), a1 = __expf(m1 - mn1);
        m0 = mn0; m1 = mn1;

        float rs0 = 0.0f, rs1 = 0.0f;
#pragma unroll
        for (int j = 0; j < 8; j++) {
            s[j][0] = __expf(s[j][0] - mn0);
            s[j][1] = __expf(s[j][1] - mn0);
            s[j][2] = __expf(s[j][2] - mn1);
            s[j][3] = __expf(s[j][3] - mn1);
            rs0 += s[j][0] + s[j][1];
            rs1 += s[j][2] + s[j][3];
        }
        rs0 += __shfl_xor_sync(0xffffffffu, rs0, 1);
        rs0 += __shfl_xor_sync(0xffffffffu, rs0, 2);
        rs1 += __shfl_xor_sync(0xffffffffu, rs1, 1);
        rs1 += __shfl_xor_sync(0xffffffffu, rs1, 2);
        l0 = l0 * a0 + rs0;
        l1 = l1 * a1 + rs1;
#pragma unroll
        for (int j = 0; j < 8; j++) {
            o[j][0] *= a0; o[j][1] *= a0; o[j][2] *= a1; o[j][3] *= a1;
        }

        // ---- O += P V : n-pairs, term-major interleave
#pragma unroll
        for (int kk = 0; kk < 4; kk++) {
            const float* p0 = s[2 * kk];
            const float* p1 = s[2 * kk + 1];
            float h[8];
            h[0] = __bfloat162float(__float2bfloat16(p0[0]));
            h[1] = __bfloat162float(__float2bfloat16(p0[1]));
            h[2] = __bfloat162float(__float2bfloat16(p0[2]));
            h[3] = __bfloat162float(__float2bfloat16(p0[3]));
            h[4] = __bfloat162float(__float2bfloat16(p1[0]));
            h[5] = __bfloat162float(__float2bfloat16(p1[1]));
            h[6] = __bfloat162float(__float2bfloat16(p1[2]));
            h[7] = __bfloat162float(__float2bfloat16(p1[3]));
            const uint32_t ah0 = packbf(h[0], h[1]), ah1 = packbf(h[2], h[3]);
            const uint32_t ah2 = packbf(h[4], h[5]), ah3 = packbf(h[6], h[7]);
            const uint32_t al0 = packbf(p0[0] - h[0], p0[1] - h[1]);
            const uint32_t al1 = packbf(p0[2] - h[2], p0[3] - h[3]);
            const uint32_t al2 = packbf(p1[0] - h[4], p1[1] - h[5]);
            const uint32_t al3 = packbf(p1[2] - h[6], p1[3] - h[7]);

            const int r = 16 * kk + 8 * lmat + lr;
#pragma unroll
            for (int np = 0; np < 4; np++) {
                const int n0 = 2 * np, n1 = n0 + 1;
                uint32_t vh00, vh01, vl00, vl01, vh10, vh11, vl10, vl11;
                const uint32_t off0 = r * 128 + SWC(r, n0);
                const uint32_t off1 = r * 128 + SWC(r, n1);
                ldsm_x2_t(vh00, vh01, kb + 16384 + off0);
                ldsm_x2_t(vl00, vl01, kb + 24576 + off0);
                ldsm_x2_t(vh10, vh11, kb + 16384 + off1);
                ldsm_x2_t(vl10, vl11, kb + 24576 + off1);
                mma16816(o[n0], ah0, ah1, ah2, ah3, vh00, vh01);
                mma16816(o[n1], ah0, ah1, ah2, ah3, vh10, vh11);
                mma16816(o[n0], ah0, ah1, ah2, ah3, vl00, vl01);
                mma16816(o[n1], ah0, ah1, ah2, ah3, vl10, vl11);
                mma16816(o[n0], al0, al1, al2, al3, vh00, vh01);
                mma16816(o[n1], al0, al1, al2, al3, vh10, vh11);
            }
        }
    }

    const float i0 = 1.0f / l0, i1 = 1.0f / l1;
    const size_t ob = ((size_t)bh * SEQ + q0 + wid * 16 + g) * HD;
#pragma unroll
    for (int j = 0; j < 8; j++) {
        const int c0 = 8 * j + 2 * tig;
        *(float2*)(out + ob + c0)          = make_float2(o[j][0] * i0, o[j][1] * i0);
        *(float2*)(out + ob + 8 * HD + c0) = make_float2(o[j][2] * i1, o[j][3] * i1);
    }
}

// ---------------------------------------------------------------------------
extern "C" void kernel_launch(void* const* d_in, const int* in_sizes, int n_in,
                              void* d_out, int out_size) {
    const float* x = (const float*)d_in[0];
    const float* w = (const float*)d_in[1];
    float* out = (float*)d_out;

    cudaFuncSetAttribute(qkv_gemm, cudaFuncAttributeMaxDynamicSharedMemorySize, QKV_SMEM);
    cudaFuncSetAttribute(flash_attn, cudaFuncAttributeMaxDynamicSharedMemorySize, ATTN_SMEM);

    presplit<<<1024, 256>>>(x, w);
    qkv_gemm<<<dim3(NTOT / 128, MTOT / 128), 256, QKV_SMEM>>>();
    flash_attn<<<dim3(SEQ / 128, BATCH * HEADS), 256, ATTN_SMEM>>>(out);
}

// round 14
// speedup vs baseline: 3.9566x; 1.4162x over previous
#include <cuda_runtime.h>
#include <cuda_fp16.h>
#include <stdint.h>

#define HEADS 16
#define HD    64
#define SEQ   2048
#define BATCH 2
#define KDIM  1024
#define NTOT  3072
#define MTOT  4096
#define QKV_ELEMS (BATCH * HEADS * SEQ * HD)

// fp16 operands. A-side needs hi only (2-term scheme); B-side needs hi+lo.
__device__ __half g_xh[MTOT * KDIM];
__device__ __half g_wh[KDIM * NTOT], g_wl[KDIM * NTOT];
__device__ __half g_qh[QKV_ELEMS];                       // Q: A operand, hi only
__device__ __half g_kh[QKV_ELEMS], g_kl[QKV_ELEMS];      // K: B operand
__device__ __half g_vh[QKV_ELEMS], g_vl[QKV_ELEMS];      // V: B operand

__device__ __forceinline__ void split_h(float x, __half& hi, __half& lo) {
    hi = __float2half(x);
    lo = __float2half(x - __half2float(hi));
}
__device__ __forceinline__ void cpa16(uint32_t dst, const void* src) {
    asm volatile("cp.async.cg.shared.global [%0], [%1], 16;\n" :: "r"(dst), "l"(src));
}
__device__ __forceinline__ void cpa_commit() { asm volatile("cp.async.commit_group;\n"); }
__device__ __forceinline__ void cpa_wait_all() { asm volatile("cp.async.wait_group 0;\n"); }

__device__ __forceinline__ void ldsm_x2(uint32_t& r0, uint32_t& r1, uint32_t addr) {
    asm volatile("ldmatrix.sync.aligned.m8n8.x2.shared.b16 {%0,%1}, [%2];"
                 : "=r"(r0), "=r"(r1) : "r"(addr));
}
__device__ __forceinline__ void ldsm_x4(uint32_t& r0, uint32_t& r1, uint32_t& r2,
                                        uint32_t& r3, uint32_t addr) {
    asm volatile("ldmatrix.sync.aligned.m8n8.x4.shared.b16 {%0,%1,%2,%3}, [%4];"
                 : "=r"(r0), "=r"(r1), "=r"(r2), "=r"(r3) : "r"(addr));
}
__device__ __forceinline__ void ldsm_x2_t(uint32_t& r0, uint32_t& r1, uint32_t addr) {
    asm volatile("ldmatrix.sync.aligned.m8n8.x2.trans.shared.b16 {%0,%1}, [%2];"
                 : "=r"(r0), "=r"(r1) : "r"(addr));
}
__device__ __forceinline__ void mma16816(float* c, uint32_t a0, uint32_t a1, uint32_t a2,
                                         uint32_t a3, uint32_t b0, uint32_t b1) {
    asm volatile("mma.sync.aligned.m16n8k16.row.col.f32.f16.f16.f32 "
                 "{%0,%1,%2,%3}, {%4,%5,%6,%7}, {%8,%9}, {%0,%1,%2,%3};"
                 : "+f"(c[0]), "+f"(c[1]), "+f"(c[2]), "+f"(c[3])
                 : "r"(a0), "r"(a1), "r"(a2), "r"(a3), "r"(b0), "r"(b1));
}
__device__ __forceinline__ uint32_t packh(float x, float y) {
    __half2 t = __floats2half2_rn(x, y);
    return *(uint32_t*)&t;
}

// ---------------------------------------------------------------------------
// Kernel 0: X -> fp16 hi; W -> fp16 hi/lo
// ---------------------------------------------------------------------------
#define NX4 (MTOT * KDIM / 4)
#define NW4 (KDIM * NTOT / 4)
__global__ void presplit(const float* __restrict__ X, const float* __restrict__ W) {
    for (int i = blockIdx.x * blockDim.x + threadIdx.x; i < NX4 + NW4;
         i += gridDim.x * blockDim.x) {
        if (i < NX4) {
            float4 v = ((const float4*)X)[i];
            const size_t off = (size_t)i * 4;
            ((__half2*)(g_xh + off))[0] = __floats2half2_rn(v.x, v.y);
            ((__half2*)(g_xh + off))[1] = __floats2half2_rn(v.z, v.w);
        } else {
            float4 v = ((const float4*)W)[i - NX4];
            const size_t off = (size_t)(i - NX4) * 4;
            __half h0,h1,h2,h3,l0,l1,l2,l3;
            split_h(v.x,h0,l0); split_h(v.y,h1,l1);
            split_h(v.z,h2,l2); split_h(v.w,h3,l3);
            ((__half2*)(g_wh+off))[0] = __halves2half2(h0,h1);
            ((__half2*)(g_wh+off))[1] = __halves2half2(h2,h3);
            ((__half2*)(g_wl+off))[0] = __halves2half2(l0,l1);
            ((__half2*)(g_wl+off))[1] = __halves2half2(l2,l3);
        }
    }
}

// ---------------------------------------------------------------------------
// Kernel 1: QKV GEMM, fp16 2-term (Ah*Bh + Ah*Bl), cp.async double-buffered.
// smem layout (bytes): AH0 0, AH1 10240 | 20480 + st*17408: BH +0, BL +8704
// Total 55296.
// ---------------------------------------------------------------------------
#define QKV_SMEM 55296

__device__ __forceinline__ void qkv_issue_stage(uint32_t sb, int st, int k0,
                                                int tid, int mBase, int nBase) {
    const uint32_t ab = sb + st * 10240;
#pragma unroll
    for (int i = 0; i < 2; i++) {
        const int e = tid + i * 256;            // 0..511
        const int row = e >> 2, cc = e & 3;
        cpa16(ab + row * 80 + cc * 16,
              g_xh + (size_t)(mBase + row) * KDIM + k0 + cc * 8);
    }
    const uint32_t bb = sb + 20480 + st * 17408;
#pragma unroll
    for (int i = 0; i < 4; i++) {
        const int e = tid + i * 256;            // 0..1023
        const __half* src = (e < 512) ? g_wh : g_wl;
        const int c = e & 511, row = c >> 4, cc = c & 15;
        cpa16(bb + (e < 512 ? 0 : 8704) + row * 272 + cc * 16,
              src + (size_t)(k0 + row) * NTOT + nBase + cc * 8);
    }
    cpa_commit();
}

__global__ __launch_bounds__(256, 2) void qkv_gemm() {
    extern __shared__ char smem[];
    const uint32_t sb = (uint32_t)__cvta_generic_to_shared(smem);

    const int tid   = threadIdx.x;
    const int lane  = tid & 31;
    const int wid   = tid >> 5;
    const int wm    = wid >> 1;
    const int wn    = wid & 1;
    const int mBase = blockIdx.y * 128;
    const int nBase = blockIdx.x * 128;
    const int g     = lane >> 2;
    const int tig   = lane & 3;
    const int ln    = lane & 15;
    const int lr    = ln & 7;
    const int lmat  = ln >> 3;

    const int arow_off = (lane & 7) + (lane & 8);
    const int acol_off = (lane & 16) ? 16 : 0;

    float acc[2][8][4];
#pragma unroll
    for (int mi = 0; mi < 2; mi++)
#pragma unroll
        for (int n = 0; n < 8; n++)
#pragma unroll
            for (int e = 0; e < 4; e++) acc[mi][n][e] = 0.0f;

    qkv_issue_stage(sb, 0, 0, tid, mBase, nBase);

    for (int kt = 0; kt < 32; kt++) {
        cpa_wait_all();
        __syncthreads();
        if (kt + 1 < 32) qkv_issue_stage(sb, (kt + 1) & 1, (kt + 1) * 32, tid, mBase, nBase);

        const int st = kt & 1;
        const uint32_t abase = sb + st * 10240;
        const uint32_t bbase = sb + 20480 + st * 17408;

#pragma unroll
        for (int kd = 0; kd < 2; kd++) {
            uint32_t ah[2][4];
#pragma unroll
            for (int mi = 0; mi < 2; mi++) {
                const uint32_t ra = abase + (uint32_t)(wm * 32 + mi * 16 + arow_off) * 80
                                  + kd * 32 + acol_off;
                ldsm_x4(ah[mi][0], ah[mi][1], ah[mi][2], ah[mi][3], ra);
            }
            const uint32_t rb = bbase + (uint32_t)(kd * 16 + 8 * lmat + lr) * 272;
#pragma unroll
            for (int np = 0; np < 4; np++) {
                const int n0 = 2 * np, n1 = n0 + 1;
                const uint32_t cb0 = rb + (uint32_t)(wn * 64 + n0 * 8) * 2;
                const uint32_t cb1 = rb + (uint32_t)(wn * 64 + n1 * 8) * 2;
                uint32_t bh00, bh01, bl00, bl01, bh10, bh11, bl10, bl11;
                ldsm_x2_t(bh00, bh01, cb0);
                ldsm_x2_t(bl00, bl01, cb0 + 8704);
                ldsm_x2_t(bh10, bh11, cb1);
                ldsm_x2_t(bl10, bl11, cb1 + 8704);
                // term Ah*Bh
                mma16816(acc[0][n0], ah[0][0], ah[0][1], ah[0][2], ah[0][3], bh00, bh01);
                mma16816(acc[1][n0], ah[1][0], ah[1][1], ah[1][2], ah[1][3], bh00, bh01);
                mma16816(acc[0][n1], ah[0][0], ah[0][1], ah[0][2], ah[0][3], bh10, bh11);
                mma16816(acc[1][n1], ah[1][0], ah[1][1], ah[1][2], ah[1][3], bh10, bh11);
                // term Ah*Bl
                mma16816(acc[0][n0], ah[0][0], ah[0][1], ah[0][2], ah[0][3], bl00, bl01);
                mma16816(acc[1][n0], ah[1][0], ah[1][1], ah[1][2], ah[1][3], bl00, bl01);
                mma16816(acc[0][n1], ah[0][0], ah[0][1], ah[0][2], ah[0][3], bl10, bl11);
                mma16816(acc[1][n1], ah[1][0], ah[1][1], ah[1][2], ah[1][3], bl10, bl11);
            }
        }
        __syncthreads();
    }

    // Epilogue: Q -> hi only (scaled 1/8); K/V -> hi+lo.
#pragma unroll
    for (int mi = 0; mi < 2; mi++) {
        const int row0 = mBase + wm * 32 + mi * 16 + g;
        const int b_   = row0 >> 11;
        const int n0_  = row0 & 2047;
#pragma unroll
        for (int n = 0; n < 8; n++) {
            const int col0  = nBase + wn * 64 + n * 8 + tig * 2;
            const int third = col0 >> 10;
            const int h     = (col0 & 1023) >> 6;
            const int d     = col0 & 63;
            const size_t base = ((size_t)((b_ * HEADS + h) * SEQ + n0_)) * HD + d;
            if (third == 0) {
                *(__half2*)(g_qh + base) =
                    __floats2half2_rn(acc[mi][n][0] * 0.125f, acc[mi][n][1] * 0.125f);
                *(__half2*)(g_qh + base + 8 * HD) =
                    __floats2half2_rn(acc[mi][n][2] * 0.125f, acc[mi][n][3] * 0.125f);
            } else {
                __half* dh = (third == 1) ? g_kh : g_vh;
                __half* dl = (third == 1) ? g_kl : g_vl;
                __half h0, l0v, h1, l1v;
                split_h(acc[mi][n][0], h0, l0v);
                split_h(acc[mi][n][1], h1, l1v);
                *(__half2*)(dh + base) = __halves2half2(h0, h1);
                *(__half2*)(dl + base) = __halves2half2(l0v, l1v);
                split_h(acc[mi][n][2], h0, l0v);
                split_h(acc[mi][n][3], h1, l1v);
                *(__half2*)(dh + base + 8 * HD) = __halves2half2(h0, h1);
                *(__half2*)(dl + base + 8 * HD) = __halves2half2(l0v, l1v);
            }
        }
    }
}

// ---------------------------------------------------------------------------
// Kernel 2: register-resident flash attention, fp16 2-term.
// S = Qh*(Kh+Kl);  O += Ph*(Vh+Vl).  No A-side lo anywhere.
// ---------------------------------------------------------------------------
#define ATTN_SMEM 65536
#define SWC(r, c) (((c) ^ ((r) & 7)) * 16)

__device__ __forceinline__ void attn_issue_kv(uint32_t sb, int st, int bh, int t, int tid) {
    const uint32_t base = sb + st * 32768;
    const __half* srcs[4] = { g_kh, g_kl, g_vh, g_vl };
#pragma unroll
    for (int i = 0; i < 8; i++) {
        const int e   = tid + i * 256;
        const int sel = e >> 9;
        const int c   = e & 511, r = c >> 3, cc = c & 7;
        cpa16(base + sel * 8192 + r * 128 + SWC(r, cc),
              srcs[sel] + ((size_t)bh * SEQ + t * 64 + r) * HD + cc * 8);
    }
    cpa_commit();
}

__global__ __launch_bounds__(256, 2) void flash_attn(float* __restrict__ out) {
    extern __shared__ char smem[];
    const uint32_t sb = (uint32_t)__cvta_generic_to_shared(smem);

    const int tid  = threadIdx.x;
    const int bh   = blockIdx.y;
    const int q0   = blockIdx.x * 128;
    const int wid  = tid >> 5;
    const int lane = tid & 31;
    const int g    = lane >> 2;
    const int tig  = lane & 3;
    const int ln   = lane & 15;
    const int lr   = ln & 7;
    const int lmat = ln >> 3;

    attn_issue_kv(sb, 0, bh, 0, tid);

    uint32_t qh[4][4];
    {
        const size_t qb = ((size_t)bh * SEQ + q0 + wid * 16 + g) * HD;
#pragma unroll
        for (int kd = 0; kd < 4; kd++) {
            const int c0 = kd * 16 + 2 * tig;
            qh[kd][0] = *(const uint32_t*)(g_qh + qb + c0);
            qh[kd][1] = *(const uint32_t*)(g_qh + qb + 8 * HD + c0);
            qh[kd][2] = *(const uint32_t*)(g_qh + qb + c0 + 8);
            qh[kd][3] = *(const uint32_t*)(g_qh + qb + 8 * HD + c0 + 8);
        }
    }

    float o[8][4];
#pragma unroll
    for (int j = 0; j < 8; j++)
#pragma unroll
        for (int e = 0; e < 4; e++) o[j][e] = 0.0f;
    float m0 = -1e30f, m1 = -1e30f, l0 = 0.0f, l1 = 0.0f;

    for (int t = 0; t < 32; t++) {
        cpa_wait_all();
        __syncthreads();
        if (t + 1 < 32) attn_issue_kv(sb, (t + 1) & 1, bh, t + 1, tid);

        const uint32_t kb = sb + (t & 1) * 32768;

        // ---- S = Qh * (Kh + Kl)
        float s[8][4];
#pragma unroll
        for (int jp = 0; jp < 4; jp++) {
            const int j0 = 2 * jp, j1 = j0 + 1;
            s[j0][0] = s[j0][1] = s[j0][2] = s[j0][3] = 0.0f;
            s[j1][0] = s[j1][1] = s[j1][2] = s[j1][3] = 0.0f;
            const int r0 = 8 * j0 + lr, r1 = 8 * j1 + lr;
#pragma unroll
            for (int kd = 0; kd < 4; kd++) {
                uint32_t kh00, kh01, kl00, kl01, kh10, kh11, kl10, kl11;
                const uint32_t off0 = r0 * 128 + SWC(r0, 2 * kd + lmat);
                const uint32_t off1 = r1 * 128 + SWC(r1, 2 * kd + lmat);
                ldsm_x2(kh00, kh01, kb + off0);
                ldsm_x2(kl00, kl01, kb + 8192 + off0);
                ldsm_x2(kh10, kh11, kb + off1);
                ldsm_x2(kl10, kl11, kb + 8192 + off1);
                mma16816(s[j0], qh[kd][0], qh[kd][1], qh[kd][2], qh[kd][3], kh00, kh01);
                mma16816(s[j1], qh[kd][0], qh[kd][1], qh[kd][2], qh[kd][3], kh10, kh11);
                mma16816(s[j0], qh[kd][0], qh[kd][1], qh[kd][2], qh[kd][3], kl00, kl01);
                mma16816(s[j1], qh[kd][0], qh[kd][1], qh[kd][2], qh[kd][3], kl10, kl11);
            }
        }

        // ---- online softmax
        float mx0 = -1e30f, mx1 = -1e30f;
#pragma unroll
        for (int j = 0; j < 8; j++) {
            mx0 = fmaxf(mx0, fmaxf(s[j][0], s[j][1]));
            mx1 = fmaxf(mx1, fmaxf(s[j][2], s[j][3]));
        }
        mx0 = fmaxf(mx0, __shfl_xor_sync(0xffffffffu, mx0, 1));
        mx0 = fmaxf(mx0, __shfl_xor_sync(0xffffffffu, mx0, 2));
        mx1 = fmaxf(mx1, __shfl_xor_sync(0xffffffffu, mx1, 1));
        mx1 = fmaxf(mx1, __shfl_xor_sync(0xffffffffu, mx1, 2));
        const float mn0 = fmaxf(m0, mx0), mn1 = fmaxf(m1, mx1);
        const float a0 = __expf(m0 - mn0), a1 = __expf(m1 - mn1);
        m0 = mn0; m1 = mn1;

        float rs0 = 0.0f, rs1 = 0.0f;
#pragma unroll
        for (int j = 0; j < 8; j++) {
            s[j][0] = __expf(s[j][0] - mn0);
            s[j][1] = __expf(s[j][1] - mn0);
            s[j][2] = __expf(s[j][2] - mn1);
            s[j][3] = __expf(s[j][3] - mn1);
            rs0 += s[j][0] + s[j][1];
            rs1 += s[j][2] + s[j][3];
        }
        rs0 += __shfl_xor_sync(0xffffffffu, rs0, 1);
        rs0 += __shfl_xor_sync(0xffffffffu, rs0, 2);
        rs1 += __shfl_xor_sync(0xffffffffu, rs1, 1);
        rs1 += __shfl_xor_sync(0xffffffffu, rs1, 2);
        l0 = l0 * a0 + rs0;
        l1 = l1 * a1 + rs1;
#pragma unroll
        for (int j = 0; j < 8; j++) {
            o[j][0] *= a0; o[j][1] *= a0; o[j][2] *= a1; o[j][3] *= a1;
        }

        // ---- O += Ph * (Vh + Vl)
#pragma unroll
        for (int kk = 0; kk < 4; kk++) {
            const float* p0 = s[2 * kk];
            const float* p1 = s[2 * kk + 1];
            const uint32_t ah0 = packh(p0[0], p0[1]), ah1 = packh(p0[2], p0[3]);
            const uint32_t ah2 = packh(p1[0], p1[1]), ah3 = packh(p1[2], p1[3]);

            const int r = 16 * kk + 8 * lmat + lr;
#pragma unroll
            for (int np = 0; np < 4; np++) {
                const int n0 = 2 * np, n1 = n0 + 1;
                uint32_t vh00, vh01, vl00, vl01, vh10, vh11, vl10, vl11;
                const uint32_t off0 = r * 128 + SWC(r, n0);
                const uint32_t off1 = r * 128 + SWC(r, n1);
                ldsm_x2_t(vh00, vh01, kb + 16384 + off0);
                ldsm_x2_t(vl00, vl01, kb + 24576 + off0);
                ldsm_x2_t(vh10, vh11, kb + 16384 + off1);
                ldsm_x2_t(vl10, vl11, kb + 24576 + off1);
                mma16816(o[n0], ah0, ah1, ah2, ah3, vh00, vh01);
                mma16816(o[n1], ah0, ah1, ah2, ah3, vh10, vh11);
                mma16816(o[n0], ah0, ah1, ah2, ah3, vl00, vl01);
                mma16816(o[n1], ah0, ah1, ah2, ah3, vl10, vl11);
            }
        }
    }

    const float i0 = 1.0f / l0, i1 = 1.0f / l1;
    const size_t ob = ((size_t)bh * SEQ + q0 + wid * 16 + g) * HD;
#pragma unroll
    for (int j = 0; j < 8; j++) {
        const int c0 = 8 * j + 2 * tig;
        *(float2*)(out + ob + c0)          = make_float2(o[j][0] * i0, o[j][1] * i0);
        *(float2*)(out + ob + 8 * HD + c0) = make_float2(o[j][2] * i1, o[j][3] * i1);
    }
}

// ---------------------------------------------------------------------------
extern "C" void kernel_launch(void* const* d_in, const int* in_sizes, int n_in,
                              void* d_out, int out_size) {
    const float* x = (const float*)d_in[0];
    const float* w = (const float*)d_in[1];
    float* out = (float*)d_out;

    cudaFuncSetAttribute(qkv_gemm, cudaFuncAttributeMaxDynamicSharedMemorySize, QKV_SMEM);
    cudaFuncSetAttribute(flash_attn, cudaFuncAttributeMaxDynamicSharedMemorySize, ATTN_SMEM);

    presplit<<<1024, 256>>>(x, w);
    qkv_gemm<<<dim3(NTOT / 128, MTOT / 128), 256, QKV_SMEM>>>();
    flash_attn<<<dim3(SEQ / 128, BATCH * HEADS), 256, ATTN_SMEM>>>(out);
}

// round 15
// speedup vs baseline: 6.6702x; 1.6858x over previous
#include <cuda_runtime.h>
#include <cuda_fp16.h>
#include <stdint.h>

#define HEADS 16
#define HD    64
#define SEQ   2048
#define BATCH 2
#define KDIM  1024
#define NTOT  3072
#define MTOT  4096
#define QKV_ELEMS (BATCH * HEADS * SEQ * HD)

// Plain fp16 operands (fp32 accumulate in all GEMMs).
__device__ __half g_xh[MTOT * KDIM];
__device__ __half g_wh[KDIM * NTOT];
__device__ __half g_qh[QKV_ELEMS];     // Q pre-scaled by 1/8
__device__ __half g_kh[QKV_ELEMS];
__device__ __half g_vh[QKV_ELEMS];

__device__ __forceinline__ void cpa16(uint32_t dst, const void* src) {
    asm volatile("cp.async.cg.shared.global [%0], [%1], 16;\n" :: "r"(dst), "l"(src));
}
__device__ __forceinline__ void cpa_commit() { asm volatile("cp.async.commit_group;\n"); }
__device__ __forceinline__ void cpa_wait_all() { asm volatile("cp.async.wait_group 0;\n"); }

__device__ __forceinline__ void ldsm_x2(uint32_t& r0, uint32_t& r1, uint32_t addr) {
    asm volatile("ldmatrix.sync.aligned.m8n8.x2.shared.b16 {%0,%1}, [%2];"
                 : "=r"(r0), "=r"(r1) : "r"(addr));
}
__device__ __forceinline__ void ldsm_x4(uint32_t& r0, uint32_t& r1, uint32_t& r2,
                                        uint32_t& r3, uint32_t addr) {
    asm volatile("ldmatrix.sync.aligned.m8n8.x4.shared.b16 {%0,%1,%2,%3}, [%4];"
                 : "=r"(r0), "=r"(r1), "=r"(r2), "=r"(r3) : "r"(addr));
}
__device__ __forceinline__ void ldsm_x2_t(uint32_t& r0, uint32_t& r1, uint32_t addr) {
    asm volatile("ldmatrix.sync.aligned.m8n8.x2.trans.shared.b16 {%0,%1}, [%2];"
                 : "=r"(r0), "=r"(r1) : "r"(addr));
}
__device__ __forceinline__ void mma16816(float* c, uint32_t a0, uint32_t a1, uint32_t a2,
                                         uint32_t a3, uint32_t b0, uint32_t b1) {
    asm volatile("mma.sync.aligned.m16n8k16.row.col.f32.f16.f16.f32 "
                 "{%0,%1,%2,%3}, {%4,%5,%6,%7}, {%8,%9}, {%0,%1,%2,%3};"
                 : "+f"(c[0]), "+f"(c[1]), "+f"(c[2]), "+f"(c[3])
                 : "r"(a0), "r"(a1), "r"(a2), "r"(a3), "r"(b0), "r"(b1));
}
__device__ __forceinline__ uint32_t packh(float x, float y) {
    __half2 t = __floats2half2_rn(x, y);
    return *(uint32_t*)&t;
}

// ---------------------------------------------------------------------------
// Kernel 0: X, W -> fp16
// ---------------------------------------------------------------------------
#define NX4 (MTOT * KDIM / 4)
#define NW4 (KDIM * NTOT / 4)
__global__ void presplit(const float* __restrict__ X, const float* __restrict__ W) {
    for (int i = blockIdx.x * blockDim.x + threadIdx.x; i < NX4 + NW4;
         i += gridDim.x * blockDim.x) {
        float4 v; __half* dst; size_t off;
        if (i < NX4) { v = ((const float4*)X)[i]; dst = g_xh; off = (size_t)i * 4; }
        else { v = ((const float4*)W)[i - NX4]; dst = g_wh; off = (size_t)(i - NX4) * 4; }
        ((__half2*)(dst + off))[0] = __floats2half2_rn(v.x, v.y);
        ((__half2*)(dst + off))[1] = __floats2half2_rn(v.z, v.w);
    }
}

// ---------------------------------------------------------------------------
// Kernel 1: QKV GEMM, plain fp16 mma, cp.async double-buffered.
// smem (bytes): AH st at st*10240 (128 rows x 80B) ;
//               BH st at 20480 + st*8704 (32 rows x 272B).  Total 37888.
// ---------------------------------------------------------------------------
#define QKV_SMEM 37888

__device__ __forceinline__ void qkv_issue_stage(uint32_t sb, int st, int k0,
                                                int tid, int mBase, int nBase) {
    const uint32_t ab = sb + st * 10240;
#pragma unroll
    for (int i = 0; i < 2; i++) {
        const int e = tid + i * 256;            // 0..511
        const int row = e >> 2, cc = e & 3;
        cpa16(ab + row * 80 + cc * 16,
              g_xh + (size_t)(mBase + row) * KDIM + k0 + cc * 8);
    }
    const uint32_t bb = sb + 20480 + st * 8704;
#pragma unroll
    for (int i = 0; i < 2; i++) {
        const int e = tid + i * 256;            // 0..511
        const int row = e >> 4, cc = e & 15;
        cpa16(bb + row * 272 + cc * 16,
              g_wh + (size_t)(k0 + row) * NTOT + nBase + cc * 8);
    }
    cpa_commit();
}

__global__ __launch_bounds__(256, 2) void qkv_gemm() {
    extern __shared__ char smem[];
    const uint32_t sb = (uint32_t)__cvta_generic_to_shared(smem);

    const int tid   = threadIdx.x;
    const int lane  = tid & 31;
    const int wid   = tid >> 5;
    const int wm    = wid >> 1;
    const int wn    = wid & 1;
    const int mBase = blockIdx.y * 128;
    const int nBase = blockIdx.x * 128;
    const int g     = lane >> 2;
    const int tig   = lane & 3;
    const int ln    = lane & 15;
    const int lr    = ln & 7;
    const int lmat  = ln >> 3;

    const int arow_off = (lane & 7) + (lane & 8);
    const int acol_off = (lane & 16) ? 16 : 0;

    float acc[2][8][4];
#pragma unroll
    for (int mi = 0; mi < 2; mi++)
#pragma unroll
        for (int n = 0; n < 8; n++)
#pragma unroll
            for (int e = 0; e < 4; e++) acc[mi][n][e] = 0.0f;

    qkv_issue_stage(sb, 0, 0, tid, mBase, nBase);

    for (int kt = 0; kt < 32; kt++) {
        cpa_wait_all();
        __syncthreads();
        if (kt + 1 < 32) qkv_issue_stage(sb, (kt + 1) & 1, (kt + 1) * 32, tid, mBase, nBase);

        const int st = kt & 1;
        const uint32_t abase = sb + st * 10240;
        const uint32_t bbase = sb + 20480 + st * 8704;

#pragma unroll
        for (int kd = 0; kd < 2; kd++) {
            uint32_t ah[2][4];
#pragma unroll
            for (int mi = 0; mi < 2; mi++) {
                const uint32_t ra = abase + (uint32_t)(wm * 32 + mi * 16 + arow_off) * 80
                                  + kd * 32 + acol_off;
                ldsm_x4(ah[mi][0], ah[mi][1], ah[mi][2], ah[mi][3], ra);
            }
            const uint32_t rb = bbase + (uint32_t)(kd * 16 + 8 * lmat + lr) * 272;
#pragma unroll
            for (int np = 0; np < 4; np++) {
                const int n0 = 2 * np, n1 = n0 + 1;
                uint32_t bh00, bh01, bh10, bh11;
                ldsm_x2_t(bh00, bh01, rb + (uint32_t)(wn * 64 + n0 * 8) * 2);
                ldsm_x2_t(bh10, bh11, rb + (uint32_t)(wn * 64 + n1 * 8) * 2);
                mma16816(acc[0][n0], ah[0][0], ah[0][1], ah[0][2], ah[0][3], bh00, bh01);
                mma16816(acc[1][n0], ah[1][0], ah[1][1], ah[1][2], ah[1][3], bh00, bh01);
                mma16816(acc[0][n1], ah[0][0], ah[0][1], ah[0][2], ah[0][3], bh10, bh11);
                mma16816(acc[1][n1], ah[1][0], ah[1][1], ah[1][2], ah[1][3], bh10, bh11);
            }
        }
        __syncthreads();
    }

    // Epilogue: plain fp16 stores (Q scaled 1/8)
#pragma unroll
    for (int mi = 0; mi < 2; mi++) {
        const int row0 = mBase + wm * 32 + mi * 16 + g;
        const int b_   = row0 >> 11;
        const int n0_  = row0 & 2047;
#pragma unroll
        for (int n = 0; n < 8; n++) {
            const int col0  = nBase + wn * 64 + n * 8 + tig * 2;
            const int third = col0 >> 10;
            const int h     = (col0 & 1023) >> 6;
            const int d     = col0 & 63;
            const float scale = (third == 0) ? 0.125f : 1.0f;
            __half* dst = (third == 0) ? g_qh : ((third == 1) ? g_kh : g_vh);
            const size_t base = ((size_t)((b_ * HEADS + h) * SEQ + n0_)) * HD + d;
            *(__half2*)(dst + base) =
                __floats2half2_rn(acc[mi][n][0] * scale, acc[mi][n][1] * scale);
            *(__half2*)(dst + base + 8 * HD) =
                __floats2half2_rn(acc[mi][n][2] * scale, acc[mi][n][3] * scale);
        }
    }
}

// ---------------------------------------------------------------------------
// Kernel 2: register-resident flash attention, plain fp16 mma.
// smem: stage s at s*16384: KH +0, VH +8192; 64 rows x 128B XOR-swizzled.
// Total 32768 B.
// ---------------------------------------------------------------------------
#define ATTN_SMEM 32768
#define SWC(r, c) (((c) ^ ((r) & 7)) * 16)

__device__ __forceinline__ void attn_issue_kv(uint32_t sb, int st, int bh, int t, int tid) {
    const uint32_t base = sb + st * 16384;
    const __half* srcs[2] = { g_kh, g_vh };
#pragma unroll
    for (int i = 0; i < 4; i++) {
        const int e   = tid + i * 256;        // 0..1023
        const int sel = e >> 9;
        const int c   = e & 511, r = c >> 3, cc = c & 7;
        cpa16(base + sel * 8192 + r * 128 + SWC(r, cc),
              srcs[sel] + ((size_t)bh * SEQ + t * 64 + r) * HD + cc * 8);
    }
    cpa_commit();
}

__global__ __launch_bounds__(256, 2) void flash_attn(float* __restrict__ out) {
    extern __shared__ char smem[];
    const uint32_t sb = (uint32_t)__cvta_generic_to_shared(smem);

    const int tid  = threadIdx.x;
    const int bh   = blockIdx.y;
    const int q0   = blockIdx.x * 128;
    const int wid  = tid >> 5;
    const int lane = tid & 31;
    const int g    = lane >> 2;
    const int tig  = lane & 3;
    const int ln   = lane & 15;
    const int lr   = ln & 7;
    const int lmat = ln >> 3;

    attn_issue_kv(sb, 0, bh, 0, tid);

    uint32_t qh[4][4];
    {
        const size_t qb = ((size_t)bh * SEQ + q0 + wid * 16 + g) * HD;
#pragma unroll
        for (int kd = 0; kd < 4; kd++) {
            const int c0 = kd * 16 + 2 * tig;
            qh[kd][0] = *(const uint32_t*)(g_qh + qb + c0);
            qh[kd][1] = *(const uint32_t*)(g_qh + qb + 8 * HD + c0);
            qh[kd][2] = *(const uint32_t*)(g_qh + qb + c0 + 8);
            qh[kd][3] = *(const uint32_t*)(g_qh + qb + 8 * HD + c0 + 8);
        }
    }

    float o[8][4];
#pragma unroll
    for (int j = 0; j < 8; j++)
#pragma unroll
        for (int e = 0; e < 4; e++) o[j][e] = 0.0f;
    float m0 = -1e30f, m1 = -1e30f, l0 = 0.0f, l1 = 0.0f;

    for (int t = 0; t < 32; t++) {
        cpa_wait_all();
        __syncthreads();
        if (t + 1 < 32) attn_issue_kv(sb, (t + 1) & 1, bh, t + 1, tid);

        const uint32_t kb = sb + (t & 1) * 16384;

        // ---- S = Q K^T
        float s[8][4];
#pragma unroll
        for (int jp = 0; jp < 4; jp++) {
            const int j0 = 2 * jp, j1 = j0 + 1;
            s[j0][0] = s[j0][1] = s[j0][2] = s[j0][3] = 0.0f;
            s[j1][0] = s[j1][1] = s[j1][2] = s[j1][3] = 0.0f;
            const int r0 = 8 * j0 + lr, r1 = 8 * j1 + lr;
#pragma unroll
            for (int kd = 0; kd < 4; kd++) {
                uint32_t kh00, kh01, kh10, kh11;
                ldsm_x2(kh00, kh01, kb + r0 * 128 + SWC(r0, 2 * kd + lmat));
                ldsm_x2(kh10, kh11, kb + r1 * 128 + SWC(r1, 2 * kd + lmat));
                mma16816(s[j0], qh[kd][0], qh[kd][1], qh[kd][2], qh[kd][3], kh00, kh01);
                mma16816(s[j1], qh[kd][0], qh[kd][1], qh[kd][2], qh[kd][3], kh10, kh11);
            }
        }

        // ---- online softmax
        float mx0 = -1e30f, mx1 = -1e30f;
#pragma unroll
        for (int j = 0; j < 8; j++) {
            mx0 = fmaxf(mx0, fmaxf(s[j][0], s[j][1]));
            mx1 = fmaxf(mx1, fmaxf(s[j][2], s[j][3]));
        }
        mx0 = fmaxf(mx0, __shfl_xor_sync(0xffffffffu, mx0, 1));
        mx0 = fmaxf(mx0, __shfl_xor_sync(0xffffffffu, mx0, 2));
        mx1 = fmaxf(mx1, __shfl_xor_sync(0xffffffffu, mx1, 1));
        mx1 = fmaxf(mx1, __shfl_xor_sync(0xffffffffu, mx1, 2));
        const float mn0 = fmaxf(m0, mx0), mn1 = fmaxf(m1, mx1);
        const float a0 = __expf(m0 - mn0), a1 = __expf(m1 - mn1);
        m0 = mn0; m1 = mn1;

        float rs0 = 0.0f, rs1 = 0.0f;
#pragma unroll
        for (int j = 0; j < 8; j++) {
            s[j][0] = __expf(s[j][0] - mn0);
            s[j][1] = __expf(s[j][1] - mn0);
            s[j][2] = __expf(s[j][2] - mn1);
            s[j][3] = __expf(s[j][3] - mn1);
            rs0 += s[j][0] + s[j][1];
            rs1 += s[j][2] + s[j][3];
        }
        rs0 += __shfl_xor_sync(0xffffffffu, rs0, 1);
        rs0 += __shfl_xor_sync(0xffffffffu, rs0, 2);
        rs1 += __shfl_xor_sync(0xffffffffu, rs1, 1);
        rs1 += __shfl_xor_sync(0xffffffffu, rs1, 2);
        l0 = l0 * a0 + rs0;
        l1 = l1 * a1 + rs1;
#pragma unroll
        for (int j = 0; j < 8; j++) {
            o[j][0] *= a0; o[j][1] *= a0; o[j][2] *= a1; o[j][3] *= a1;
        }

        // ---- O += P V
#pragma unroll
        for (int kk = 0; kk < 4; kk++) {
            const float* p0 = s[2 * kk];
            const float* p1 = s[2 * kk + 1];
            const uint32_t ah0 = packh(p0[0], p0[1]), ah1 = packh(p0[2], p0[3]);
            const uint32_t ah2 = packh(p1[0], p1[1]), ah3 = packh(p1[2], p1[3]);

            const int r = 16 * kk + 8 * lmat + lr;
#pragma unroll
            for (int np = 0; np < 4; np++) {
                const int n0 = 2 * np, n1 = n0 + 1;
                uint32_t vh00, vh01, vh10, vh11;
                ldsm_x2_t(vh00, vh01, kb + 8192 + r * 128 + SWC(r, n0));
                ldsm_x2_t(vh10, vh11, kb + 8192 + r * 128 + SWC(r, n1));
                mma16816(o[n0], ah0, ah1, ah2, ah3, vh00, vh01);
                mma16816(o[n1], ah0, ah1, ah2, ah3, vh10, vh11);
            }
        }
    }

    const float i0 = 1.0f / l0, i1 = 1.0f / l1;
    const size_t ob = ((size_t)bh * SEQ + q0 + wid * 16 + g) * HD;
#pragma unroll
    for (int j = 0; j < 8; j++) {
        const int c0 = 8 * j + 2 * tig;
        *(float2*)(out + ob + c0)          = make_float2(o[j][0] * i0, o[j][1] * i0);
        *(float2*)(out + ob + 8 * HD + c0) = make_float2(o[j][2] * i1, o[j][3] * i1);
    }
}

// ---------------------------------------------------------------------------
extern "C" void kernel_launch(void* const* d_in, const int* in_sizes, int n_in,
                              void* d_out, int out_size) {
    const float* x = (const float*)d_in[0];
    const float* w = (const float*)d_in[1];
    float* out = (float*)d_out;

    cudaFuncSetAttribute(qkv_gemm, cudaFuncAttributeMaxDynamicSharedMemorySize, QKV_SMEM);
    cudaFuncSetAttribute(flash_attn, cudaFuncAttributeMaxDynamicSharedMemorySize, ATTN_SMEM);

    presplit<<<1024, 256>>>(x, w);
    qkv_gemm<<<dim3(NTOT / 128, MTOT / 128), 256, QKV_SMEM>>>();
    flash_attn<<<dim3(SEQ / 128, BATCH * HEADS), 256, ATTN_SMEM>>>(out);
}

// round 16
// speedup vs baseline: 6.7648x; 1.0142x over previous
#include <cuda_runtime.h>
#include <cuda_fp16.h>
#include <stdint.h>

#define HEADS 16
#define HD    64
#define SEQ   2048
#define BATCH 2
#define KDIM  1024
#define NTOT  3072
#define MTOT  4096
#define QKV_ELEMS (BATCH * HEADS * SEQ * HD)

// fp16 operands (fp32 accumulate everywhere).
__device__ __half g_xh[MTOT * KDIM];
__device__ __half g_wh[KDIM * NTOT];
__device__ __half g_qh[QKV_ELEMS];     // Q pre-scaled by log2(e)/8
__device__ __half g_kh[QKV_ELEMS];
__device__ __half g_vh[QKV_ELEMS];

// Work queue + per-(ncol,batch) completion counters
__device__ int g_work;
__device__ int g_cnt[48];

#define QSCALE 0.18033688011111793f   // 0.125 * log2(e)

__device__ __forceinline__ float ex2f(float x) {
    float y; asm("ex2.approx.f32 %0, %1;" : "=f"(y) : "f"(x)); return y;
}
__device__ __forceinline__ void cpa16(uint32_t dst, const void* src) {
    asm volatile("cp.async.cg.shared.global [%0], [%1], 16;\n" :: "r"(dst), "l"(src));
}
__device__ __forceinline__ void cpa_commit() { asm volatile("cp.async.commit_group;\n"); }
__device__ __forceinline__ void cpa_wait_all() { asm volatile("cp.async.wait_group 0;\n"); }

__device__ __forceinline__ void ldsm_x2(uint32_t& r0, uint32_t& r1, uint32_t addr) {
    asm volatile("ldmatrix.sync.aligned.m8n8.x2.shared.b16 {%0,%1}, [%2];"
                 : "=r"(r0), "=r"(r1) : "r"(addr));
}
__device__ __forceinline__ void ldsm_x4(uint32_t& r0, uint32_t& r1, uint32_t& r2,
                                        uint32_t& r3, uint32_t addr) {
    asm volatile("ldmatrix.sync.aligned.m8n8.x4.shared.b16 {%0,%1,%2,%3}, [%4];"
                 : "=r"(r0), "=r"(r1), "=r"(r2), "=r"(r3) : "r"(addr));
}
__device__ __forceinline__ void ldsm_x2_t(uint32_t& r0, uint32_t& r1, uint32_t addr) {
    asm volatile("ldmatrix.sync.aligned.m8n8.x2.trans.shared.b16 {%0,%1}, [%2];"
                 : "=r"(r0), "=r"(r1) : "r"(addr));
}
__device__ __forceinline__ void mma16816(float* c, uint32_t a0, uint32_t a1, uint32_t a2,
                                         uint32_t a3, uint32_t b0, uint32_t b1) {
    asm volatile("mma.sync.aligned.m16n8k16.row.col.f32.f16.f16.f32 "
                 "{%0,%1,%2,%3}, {%4,%5,%6,%7}, {%8,%9}, {%0,%1,%2,%3};"
                 : "+f"(c[0]), "+f"(c[1]), "+f"(c[2]), "+f"(c[3])
                 : "r"(a0), "r"(a1), "r"(a2), "r"(a3), "r"(b0), "r"(b1));
}
__device__ __forceinline__ uint32_t packh(float x, float y) {
    __half2 t = __floats2half2_rn(x, y);
    return *(uint32_t*)&t;
}

#define SWC(r, c) (((c) ^ ((r) & 7)) * 16)
#define FUSED_SMEM 37888

// ---------------------------------------------------------------------------
// Kernel 0: X, W -> fp16; also resets work queue + counters (every replay)
// ---------------------------------------------------------------------------
#define NX4 (MTOT * KDIM / 4)
#define NW4 (KDIM * NTOT / 4)
__global__ void presplit(const float* __restrict__ X, const float* __restrict__ W) {
    if (blockIdx.x == 0 && threadIdx.x < 49) {
        if (threadIdx.x < 48) g_cnt[threadIdx.x] = 0;
        else g_work = 0;
    }
    for (int i = blockIdx.x * blockDim.x + threadIdx.x; i < NX4 + NW4;
         i += gridDim.x * blockDim.x) {
        float4 v; __half* dst; size_t off;
        if (i < NX4) { v = ((const float4*)X)[i]; dst = g_xh; off = (size_t)i * 4; }
        else { v = ((const float4*)W)[i - NX4]; dst = g_wh; off = (size_t)(i - NX4) * 4; }
        ((__half2*)(dst + off))[0] = __floats2half2_rn(v.x, v.y);
        ((__half2*)(dst + off))[1] = __floats2half2_rn(v.z, v.w);
    }
}

// ---------------------------------------------------------------------------
// QKV tile worker. smem: AH st at st*10240 (128x80B); BH st at 20480+st*8704.
// ---------------------------------------------------------------------------
__device__ __forceinline__ void qkv_issue_stage(uint32_t sb, int st, int k0,
                                                int tid, int mBase, int nBase) {
    const uint32_t ab = sb + st * 10240;
#pragma unroll
    for (int i = 0; i < 2; i++) {
        const int e = tid + i * 256;
        const int row = e >> 2, cc = e & 3;
        cpa16(ab + row * 80 + cc * 16,
              g_xh + (size_t)(mBase + row) * KDIM + k0 + cc * 8);
    }
    const uint32_t bb = sb + 20480 + st * 8704;
#pragma unroll
    for (int i = 0; i < 2; i++) {
        const int e = tid + i * 256;
        const int row = e >> 4, cc = e & 15;
        cpa16(bb + row * 272 + cc * 16,
              g_wh + (size_t)(k0 + row) * NTOT + nBase + cc * 8);
    }
    cpa_commit();
}

__device__ void qkv_tile(uint32_t sb, int w, int tid) {
    const int ncol = w >> 5;                       // dispense order 0..23
    const int n_t  = (ncol % 3) * 8 + (ncol / 3); // actual n-tile (0,8,16,1,9,17,...)
    const int m_t  = w & 31;
    const int mBase = m_t * 128;
    const int nBase = n_t * 128;

    const int lane = tid & 31;
    const int wid  = tid >> 5;
    const int wm   = wid >> 1;
    const int wn   = wid & 1;
    const int g    = lane >> 2;
    const int tig  = lane & 3;
    const int ln   = lane & 15;
    const int lr   = ln & 7;
    const int lmat = ln >> 3;
    const int arow_off = (lane & 7) + (lane & 8);
    const int acol_off = (lane & 16) ? 16 : 0;

    float acc[2][8][4];
#pragma unroll
    for (int mi = 0; mi < 2; mi++)
#pragma unroll
        for (int n = 0; n < 8; n++)
#pragma unroll
            for (int e = 0; e < 4; e++) acc[mi][n][e] = 0.0f;

    qkv_issue_stage(sb, 0, 0, tid, mBase, nBase);

    for (int kt = 0; kt < 32; kt++) {
        cpa_wait_all();
        __syncthreads();
        if (kt + 1 < 32) qkv_issue_stage(sb, (kt + 1) & 1, (kt + 1) * 32, tid, mBase, nBase);

        const int st = kt & 1;
        const uint32_t abase = sb + st * 10240;
        const uint32_t bbase = sb + 20480 + st * 8704;

#pragma unroll
        for (int kd = 0; kd < 2; kd++) {
            uint32_t ah[2][4];
#pragma unroll
            for (int mi = 0; mi < 2; mi++) {
                const uint32_t ra = abase + (uint32_t)(wm * 32 + mi * 16 + arow_off) * 80
                                  + kd * 32 + acol_off;
                ldsm_x4(ah[mi][0], ah[mi][1], ah[mi][2], ah[mi][3], ra);
            }
            const uint32_t rb = bbase + (uint32_t)(kd * 16 + 8 * lmat + lr) * 272;
#pragma unroll
            for (int np = 0; np < 4; np++) {
                const int n0 = 2 * np, n1 = n0 + 1;
                uint32_t bh00, bh01, bh10, bh11;
                ldsm_x2_t(bh00, bh01, rb + (uint32_t)(wn * 64 + n0 * 8) * 2);
                ldsm_x2_t(bh10, bh11, rb + (uint32_t)(wn * 64 + n1 * 8) * 2);
                mma16816(acc[0][n0], ah[0][0], ah[0][1], ah[0][2], ah[0][3], bh00, bh01);
                mma16816(acc[1][n0], ah[1][0], ah[1][1], ah[1][2], ah[1][3], bh00, bh01);
                mma16816(acc[0][n1], ah[0][0], ah[0][1], ah[0][2], ah[0][3], bh10, bh11);
                mma16816(acc[1][n1], ah[1][0], ah[1][1], ah[1][2], ah[1][3], bh10, bh11);
            }
        }
        __syncthreads();
    }

    // Epilogue (Q scaled by log2(e)/8 for exp2 softmax)
#pragma unroll
    for (int mi = 0; mi < 2; mi++) {
        const int row0 = mBase + wm * 32 + mi * 16 + g;
        const int b_   = row0 >> 11;
        const int n0_  = row0 & 2047;
#pragma unroll
        for (int n = 0; n < 8; n++) {
            const int col0  = nBase + wn * 64 + n * 8 + tig * 2;
            const int third = col0 >> 10;
            const int h     = (col0 & 1023) >> 6;
            const int d     = col0 & 63;
            const float scale = (third == 0) ? QSCALE : 1.0f;
            __half* dst = (third == 0) ? g_qh : ((third == 1) ? g_kh : g_vh);
            const size_t base = ((size_t)((b_ * HEADS + h) * SEQ + n0_)) * HD + d;
            *(__half2*)(dst + base) =
                __floats2half2_rn(acc[mi][n][0] * scale, acc[mi][n][1] * scale);
            *(__half2*)(dst + base + 8 * HD) =
                __floats2half2_rn(acc[mi][n][2] * scale, acc[mi][n][3] * scale);
        }
    }

    __threadfence();
    __syncthreads();
    if (tid == 0) atomicAdd(&g_cnt[n_t * 2 + (m_t >> 4)], 1);
}

// ---------------------------------------------------------------------------
// Flash tile worker. smem: stage s at s*16384: KH +0, VH +8192 (64x128B swz).
// ---------------------------------------------------------------------------
__device__ __forceinline__ void attn_issue_kv(uint32_t sb, int st, int bh, int t, int tid) {
    const uint32_t base = sb + st * 16384;
    const __half* srcs[2] = { g_kh, g_vh };
#pragma unroll
    for (int i = 0; i < 4; i++) {
        const int e   = tid + i * 256;
        const int sel = e >> 9;
        const int c   = e & 511, r = c >> 3, cc = c & 7;
        cpa16(base + sel * 8192 + r * 128 + SWC(r, cc),
              srcs[sel] + ((size_t)bh * SEQ + t * 64 + r) * HD + cc * 8);
    }
    cpa_commit();
}

__device__ void flash_tile(uint32_t sb, int phi, float* __restrict__ out, int tid) {
    const int h  = phi >> 5;             // h-major: ready earliest
    const int b  = (phi >> 4) & 1;
    const int q0 = (phi & 15) * 128;
    const int bh = b * HEADS + h;

    // Wait for Q / K / V columns of this head+batch
    if (tid == 0) {
        const int c = h >> 1;
        while (atomicAdd(&g_cnt[c * 2 + b], 0) < 16) __nanosleep(64);
        while (atomicAdd(&g_cnt[(8 + c) * 2 + b], 0) < 16) __nanosleep(64);
        while (atomicAdd(&g_cnt[(16 + c) * 2 + b], 0) < 16) __nanosleep(64);
    }
    __syncthreads();
    __threadfence();

    const int wid  = tid >> 5;
    const int lane = tid & 31;
    const int g    = lane >> 2;
    const int tig  = lane & 3;
    const int ln   = lane & 15;
    const int lr   = ln & 7;
    const int lmat = ln >> 3;

    attn_issue_kv(sb, 0, bh, 0, tid);

    uint32_t qh[4][4];
    {
        const size_t qb = ((size_t)bh * SEQ + q0 + wid * 16 + g) * HD;
#pragma unroll
        for (int kd = 0; kd < 4; kd++) {
            const int c0 = kd * 16 + 2 * tig;
            qh[kd][0] = *(const uint32_t*)(g_qh + qb + c0);
            qh[kd][1] = *(const uint32_t*)(g_qh + qb + 8 * HD + c0);
            qh[kd][2] = *(const uint32_t*)(g_qh + qb + c0 + 8);
            qh[kd][3] = *(const uint32_t*)(g_qh + qb + 8 * HD + c0 + 8);
        }
    }

    float o[8][4];
#pragma unroll
    for (int j = 0; j < 8; j++)
#pragma unroll
        for (int e = 0; e < 4; e++) o[j][e] = 0.0f;
    float m0 = -1e30f, m1 = -1e30f, l0 = 0.0f, l1 = 0.0f;

    for (int t = 0; t < 32; t++) {
        cpa_wait_all();
        __syncthreads();
        if (t + 1 < 32) attn_issue_kv(sb, (t + 1) & 1, bh, t + 1, tid);

        const uint32_t kb = sb + (t & 1) * 16384;

        // S = Q K^T (log2 domain)
        float s[8][4];
#pragma unroll
        for (int jp = 0; jp < 4; jp++) {
            const int j0 = 2 * jp, j1 = j0 + 1;
            s[j0][0] = s[j0][1] = s[j0][2] = s[j0][3] = 0.0f;
            s[j1][0] = s[j1][1] = s[j1][2] = s[j1][3] = 0.0f;
            const int r0 = 8 * j0 + lr, r1 = 8 * j1 + lr;
#pragma unroll
            for (int kd = 0; kd < 4; kd++) {
                uint32_t kh00, kh01, kh10, kh11;
                ldsm_x2(kh00, kh01, kb + r0 * 128 + SWC(r0, 2 * kd + lmat));
                ldsm_x2(kh10, kh11, kb + r1 * 128 + SWC(r1, 2 * kd + lmat));
                mma16816(s[j0], qh[kd][0], qh[kd][1], qh[kd][2], qh[kd][3], kh00, kh01);
                mma16816(s[j1], qh[kd][0], qh[kd][1], qh[kd][2], qh[kd][3], kh10, kh11);
            }
        }

        // online softmax via exp2
        float mx0 = -1e30f, mx1 = -1e30f;
#pragma unroll
        for (int j = 0; j < 8; j++) {
            mx0 = fmaxf(mx0, fmaxf(s[j][0], s[j][1]));
            mx1 = fmaxf(mx1, fmaxf(s[j][2], s[j][3]));
        }
        mx0 = fmaxf(mx0, __shfl_xor_sync(0xffffffffu, mx0, 1));
        mx0 = fmaxf(mx0, __shfl_xor_sync(0xffffffffu, mx0, 2));
        mx1 = fmaxf(mx1, __shfl_xor_sync(0xffffffffu, mx1, 1));
        mx1 = fmaxf(mx1, __shfl_xor_sync(0xffffffffu, mx1, 2));
        const float mn0 = fmaxf(m0, mx0), mn1 = fmaxf(m1, mx1);
        const float a0 = ex2f(m0 - mn0), a1 = ex2f(m1 - mn1);
        m0 = mn0; m1 = mn1;

        float rs0 = 0.0f, rs1 = 0.0f;
#pragma unroll
        for (int j = 0; j < 8; j++) {
            s[j][0] = ex2f(s[j][0] - mn0);
            s[j][1] = ex2f(s[j][1] - mn0);
            s[j][2] = ex2f(s[j][2] - mn1);
            s[j][3] = ex2f(s[j][3] - mn1);
            rs0 += s[j][0] + s[j][1];
            rs1 += s[j][2] + s[j][3];
        }
        rs0 += __shfl_xor_sync(0xffffffffu, rs0, 1);
        rs0 += __shfl_xor_sync(0xffffffffu, rs0, 2);
        rs1 += __shfl_xor_sync(0xffffffffu, rs1, 1);
        rs1 += __shfl_xor_sync(0xffffffffu, rs1, 2);
        l0 = l0 * a0 + rs0;
        l1 = l1 * a1 + rs1;
#pragma unroll
        for (int j = 0; j < 8; j++) {
            o[j][0] *= a0; o[j][1] *= a0; o[j][2] *= a1; o[j][3] *= a1;
        }

        // O += P V
#pragma unroll
        for (int kk = 0; kk < 4; kk++) {
            const float* p0 = s[2 * kk];
            const float* p1 = s[2 * kk + 1];
            const uint32_t ah0 = packh(p0[0], p0[1]), ah1 = packh(p0[2], p0[3]);
            const uint32_t ah2 = packh(p1[0], p1[1]), ah3 = packh(p1[2], p1[3]);

            const int r = 16 * kk + 8 * lmat + lr;
#pragma unroll
            for (int np = 0; np < 4; np++) {
                const int n0 = 2 * np, n1 = n0 + 1;
                uint32_t vh00, vh01, vh10, vh11;
                ldsm_x2_t(vh00, vh01, kb + 8192 + r * 128 + SWC(r, n0));
                ldsm_x2_t(vh10, vh11, kb + 8192 + r * 128 + SWC(r, n1));
                mma16816(o[n0], ah0, ah1, ah2, ah3, vh00, vh01);
                mma16816(o[n1], ah0, ah1, ah2, ah3, vh10, vh11);
            }
        }
    }

    const float i0 = 1.0f / l0, i1 = 1.0f / l1;
    const size_t ob = ((size_t)bh * SEQ + q0 + wid * 16 + g) * HD;
#pragma unroll
    for (int j = 0; j < 8; j++) {
        const int c0 = 8 * j + 2 * tig;
        *(float2*)(out + ob + c0)          = make_float2(o[j][0] * i0, o[j][1] * i0);
        *(float2*)(out + ob + 8 * HD + c0) = make_float2(o[j][2] * i1, o[j][3] * i1);
    }
    __syncthreads();   // smem safe for next work item
}

// ---------------------------------------------------------------------------
// Fused persistent kernel: work items 0..767 = qkv tiles, 768..1279 = flash.
// ---------------------------------------------------------------------------
__global__ __launch_bounds__(256, 2) void fused(float* __restrict__ out) {
    extern __shared__ char smem[];
    __shared__ int s_w;
    const uint32_t sb = (uint32_t)__cvta_generic_to_shared(smem);
    const int tid = threadIdx.x;

    for (;;) {
        if (tid == 0) s_w = atomicAdd(&g_work, 1);
        __syncthreads();
        const int w = s_w;
        if (w >= 1280) return;
        if (w < 768) qkv_tile(sb, w, tid);
        else         flash_tile(sb, w - 768, out, tid);
    }
}

// ---------------------------------------------------------------------------
extern "C" void kernel_launch(void* const* d_in, const int* in_sizes, int n_in,
                              void* d_out, int out_size) {
    const float* x = (const float*)d_in[0];
    const float* w = (const float*)d_in[1];
    float* out = (float*)d_out;

    cudaFuncSetAttribute(fused, cudaFuncAttributeMaxDynamicSharedMemorySize, FUSED_SMEM);

    presplit<<<1024, 256>>>(x, w);
    fused<<<296, 256, FUSED_SMEM>>>(out);
}

// round 17
// speedup vs baseline: 7.0873x; 1.0477x over previous
#include <cuda_runtime.h>
#include <cuda_fp16.h>
#include <stdint.h>

#define HEADS 16
#define HD    64
#define SEQ   2048
#define BATCH 2
#define KDIM  1024
#define NTOT  3072
#define MTOT  4096
#define QKV_ELEMS (BATCH * HEADS * SEQ * HD)

// fp16 operands (fp32 accumulate everywhere).
__device__ __half g_xh[MTOT * KDIM];
__device__ __half g_wh[KDIM * NTOT];
__device__ __half g_qh[QKV_ELEMS];     // Q pre-scaled by log2(e)/8
__device__ __half g_kh[QKV_ELEMS];
__device__ __half g_vh[QKV_ELEMS];

// Work queue + per-(ncol,batch) completion counters
__device__ int g_work;
__device__ int g_cnt[48];

#define QSCALE 0.18033688011111793f   // 0.125 * log2(e)

__device__ __forceinline__ float ex2f(float x) {
    float y; asm("ex2.approx.f32 %0, %1;" : "=f"(y) : "f"(x)); return y;
}
__device__ __forceinline__ void cpa16(uint32_t dst, const void* src) {
    asm volatile("cp.async.cg.shared.global [%0], [%1], 16;\n" :: "r"(dst), "l"(src));
}
__device__ __forceinline__ void cpa_commit() { asm volatile("cp.async.commit_group;\n"); }
__device__ __forceinline__ void cpa_wait_all() { asm volatile("cp.async.wait_group 0;\n"); }

// Full-lane ldmatrix x4: quarter q of the warp addresses matrix q.
__device__ __forceinline__ void ldsm_x4(uint32_t& r0, uint32_t& r1, uint32_t& r2,
                                        uint32_t& r3, uint32_t addr) {
    asm volatile("ldmatrix.sync.aligned.m8n8.x4.shared.b16 {%0,%1,%2,%3}, [%4];"
                 : "=r"(r0), "=r"(r1), "=r"(r2), "=r"(r3) : "r"(addr));
}
__device__ __forceinline__ void ldsm_x4_t(uint32_t& r0, uint32_t& r1, uint32_t& r2,
                                          uint32_t& r3, uint32_t addr) {
    asm volatile("ldmatrix.sync.aligned.m8n8.x4.trans.shared.b16 {%0,%1,%2,%3}, [%4];"
                 : "=r"(r0), "=r"(r1), "=r"(r2), "=r"(r3) : "r"(addr));
}
__device__ __forceinline__ void mma16816(float* c, uint32_t a0, uint32_t a1, uint32_t a2,
                                         uint32_t a3, uint32_t b0, uint32_t b1) {
    asm volatile("mma.sync.aligned.m16n8k16.row.col.f32.f16.f16.f32 "
                 "{%0,%1,%2,%3}, {%4,%5,%6,%7}, {%8,%9}, {%0,%1,%2,%3};"
                 : "+f"(c[0]), "+f"(c[1]), "+f"(c[2]), "+f"(c[3])
                 : "r"(a0), "r"(a1), "r"(a2), "r"(a3), "r"(b0), "r"(b1));
}
__device__ __forceinline__ uint32_t packh(float x, float y) {
    __half2 t = __floats2half2_rn(x, y);
    return *(uint32_t*)&t;
}

#define SWC(r, c) (((c) ^ ((r) & 7)) * 16)
#define FUSED_SMEM 37888

// ---------------------------------------------------------------------------
// Kernel 0: X, W -> fp16; also resets work queue + counters (every replay)
// ---------------------------------------------------------------------------
#define NX4 (MTOT * KDIM / 4)
#define NW4 (KDIM * NTOT / 4)
__global__ void presplit(const float* __restrict__ X, const float* __restrict__ W) {
    if (blockIdx.x == 0 && threadIdx.x < 49) {
        if (threadIdx.x < 48) g_cnt[threadIdx.x] = 0;
        else g_work = 0;
    }
    for (int i = blockIdx.x * blockDim.x + threadIdx.x; i < NX4 + NW4;
         i += gridDim.x * blockDim.x) {
        float4 v; __half* dst; size_t off;
        if (i < NX4) { v = ((const float4*)X)[i]; dst = g_xh; off = (size_t)i * 4; }
        else { v = ((const float4*)W)[i - NX4]; dst = g_wh; off = (size_t)(i - NX4) * 4; }
        ((__half2*)(dst + off))[0] = __floats2half2_rn(v.x, v.y);
        ((__half2*)(dst + off))[1] = __floats2half2_rn(v.z, v.w);
    }
}

// ---------------------------------------------------------------------------
// QKV tile worker. smem: AH st at st*10240 (128x80B); BH st at 20480+st*8704.
// ---------------------------------------------------------------------------
__device__ __forceinline__ void qkv_issue_stage(uint32_t sb, int st, int k0,
                                                int tid, int mBase, int nBase) {
    const uint32_t ab = sb + st * 10240;
#pragma unroll
    for (int i = 0; i < 2; i++) {
        const int e = tid + i * 256;
        const int row = e >> 2, cc = e & 3;
        cpa16(ab + row * 80 + cc * 16,
              g_xh + (size_t)(mBase + row) * KDIM + k0 + cc * 8);
    }
    const uint32_t bb = sb + 20480 + st * 8704;
#pragma unroll
    for (int i = 0; i < 2; i++) {
        const int e = tid + i * 256;
        const int row = e >> 4, cc = e & 15;
        cpa16(bb + row * 272 + cc * 16,
              g_wh + (size_t)(k0 + row) * NTOT + nBase + cc * 8);
    }
    cpa_commit();
}

__device__ void qkv_tile(uint32_t sb, int w, int tid) {
    const int ncol = w >> 5;                       // dispense order 0..23
    const int n_t  = (ncol % 3) * 8 + (ncol / 3); // actual n-tile (0,8,16,1,9,17,...)
    const int m_t  = w & 31;
    const int mBase = m_t * 128;
    const int nBase = n_t * 128;

    const int lane = tid & 31;
    const int wid  = tid >> 5;
    const int wm   = wid >> 1;
    const int wn   = wid & 1;
    const int g    = lane >> 2;
    const int tig  = lane & 3;
    const int lr8  = lane & 7;
    const int kq   = (lane >> 3) & 1;   // k-half quarter
    const int nq   = lane >> 4;         // n-pair quarter
    const int arow_off = (lane & 7) + (lane & 8);
    const int acol_off = (lane & 16) ? 16 : 0;
    const int bq = 8 * kq + lr8;                     // B row within k16
    const uint32_t bcol = (uint32_t)(wn * 128 + nq * 16);

    float acc[2][8][4];
#pragma unroll
    for (int mi = 0; mi < 2; mi++)
#pragma unroll
        for (int n = 0; n < 8; n++)
#pragma unroll
            for (int e = 0; e < 4; e++) acc[mi][n][e] = 0.0f;

    qkv_issue_stage(sb, 0, 0, tid, mBase, nBase);

    for (int kt = 0; kt < 32; kt++) {
        cpa_wait_all();
        __syncthreads();
        if (kt + 1 < 32) qkv_issue_stage(sb, (kt + 1) & 1, (kt + 1) * 32, tid, mBase, nBase);

        const int st = kt & 1;
        const uint32_t abase = sb + st * 10240;
        const uint32_t bbase = sb + 20480 + st * 8704;

#pragma unroll
        for (int kd = 0; kd < 2; kd++) {
            uint32_t ah[2][4];
#pragma unroll
            for (int mi = 0; mi < 2; mi++) {
                const uint32_t ra = abase + (uint32_t)(wm * 32 + mi * 16 + arow_off) * 80
                                  + kd * 32 + acol_off;
                ldsm_x4(ah[mi][0], ah[mi][1], ah[mi][2], ah[mi][3], ra);
            }
            const uint32_t rb = bbase + (uint32_t)(kd * 16 + bq) * 272 + bcol;
#pragma unroll
            for (int np = 0; np < 4; np++) {
                const int n0 = 2 * np, n1 = n0 + 1;
                uint32_t b00, b01, b10, b11;   // n0:(klo,khi), n1:(klo,khi)
                ldsm_x4_t(b00, b01, b10, b11, rb + np * 32);
                mma16816(acc[0][n0], ah[0][0], ah[0][1], ah[0][2], ah[0][3], b00, b01);
                mma16816(acc[1][n0], ah[1][0], ah[1][1], ah[1][2], ah[1][3], b00, b01);
                mma16816(acc[0][n1], ah[0][0], ah[0][1], ah[0][2], ah[0][3], b10, b11);
                mma16816(acc[1][n1], ah[1][0], ah[1][1], ah[1][2], ah[1][3], b10, b11);
            }
        }
        __syncthreads();
    }

    // Epilogue (Q scaled by log2(e)/8 for exp2 softmax)
#pragma unroll
    for (int mi = 0; mi < 2; mi++) {
        const int row0 = mBase + wm * 32 + mi * 16 + g;
        const int b_   = row0 >> 11;
        const int n0_  = row0 & 2047;
#pragma unroll
        for (int n = 0; n < 8; n++) {
            const int col0  = nBase + wn * 64 + n * 8 + tig * 2;
            const int third = col0 >> 10;
            const int h     = (col0 & 1023) >> 6;
            const int d     = col0 & 63;
            const float scale = (third == 0) ? QSCALE : 1.0f;
            __half* dst = (third == 0) ? g_qh : ((third == 1) ? g_kh : g_vh);
            const size_t base = ((size_t)((b_ * HEADS + h) * SEQ + n0_)) * HD + d;
            *(__half2*)(dst + base) =
                __floats2half2_rn(acc[mi][n][0] * scale, acc[mi][n][1] * scale);
            *(__half2*)(dst + base + 8 * HD) =
                __floats2half2_rn(acc[mi][n][2] * scale, acc[mi][n][3] * scale);
        }
    }

    __threadfence();
    __syncthreads();
    if (tid == 0) atomicAdd(&g_cnt[n_t * 2 + (m_t >> 4)], 1);
}

// ---------------------------------------------------------------------------
// Flash tile worker. smem: stage s at s*16384: KH +0, VH +8192 (64x128B swz).
// ---------------------------------------------------------------------------
__device__ __forceinline__ void attn_issue_kv(uint32_t sb, int st, int bh, int t, int tid) {
    const uint32_t base = sb + st * 16384;
    const __half* srcs[2] = { g_kh, g_vh };
#pragma unroll
    for (int i = 0; i < 4; i++) {
        const int e   = tid + i * 256;
        const int sel = e >> 9;
        const int c   = e & 511, r = c >> 3, cc = c & 7;
        cpa16(base + sel * 8192 + r * 128 + SWC(r, cc),
              srcs[sel] + ((size_t)bh * SEQ + t * 64 + r) * HD + cc * 8);
    }
    cpa_commit();
}

__device__ void flash_tile(uint32_t sb, int phi, float* __restrict__ out, int tid) {
    const int h  = phi >> 5;             // h-major: ready earliest
    const int b  = (phi >> 4) & 1;
    const int q0 = (phi & 15) * 128;
    const int bh = b * HEADS + h;

    // Wait for Q / K / V columns of this head+batch
    if (tid == 0) {
        const int c = h >> 1;
        while (atomicAdd(&g_cnt[c * 2 + b], 0) < 16) __nanosleep(64);
        while (atomicAdd(&g_cnt[(8 + c) * 2 + b], 0) < 16) __nanosleep(64);
        while (atomicAdd(&g_cnt[(16 + c) * 2 + b], 0) < 16) __nanosleep(64);
    }
    __syncthreads();
    __threadfence();

    const int wid  = tid >> 5;
    const int lane = tid & 31;
    const int g    = lane >> 2;
    const int tig  = lane & 3;
    const int lr8  = lane & 7;
    const int kq   = (lane >> 3) & 1;    // matrix within pair (k-half / V-row-half)
    const int jq   = lane >> 4;          // pair selector (j1 / n1)
    const int rbase_s = 8 * jq + lr8;    // S-phase K row base
    const int vrow    = 8 * kq + lr8;    // PV-phase V row base within k16

    attn_issue_kv(sb, 0, bh, 0, tid);

    uint32_t qh[4][4];
    {
        const size_t qb = ((size_t)bh * SEQ + q0 + wid * 16 + g) * HD;
#pragma unroll
        for (int kd = 0; kd < 4; kd++) {
            const int c0 = kd * 16 + 2 * tig;
            qh[kd][0] = *(const uint32_t*)(g_qh + qb + c0);
            qh[kd][1] = *(const uint32_t*)(g_qh + qb + 8 * HD + c0);
            qh[kd][2] = *(const uint32_t*)(g_qh + qb + c0 + 8);
            qh[kd][3] = *(const uint32_t*)(g_qh + qb + 8 * HD + c0 + 8);
        }
    }

    float o[8][4];
#pragma unroll
    for (int j = 0; j < 8; j++)
#pragma unroll
        for (int e = 0; e < 4; e++) o[j][e] = 0.0f;
    float m0 = -1e30f, m1 = -1e30f, l0 = 0.0f, l1 = 0.0f;

    for (int t = 0; t < 32; t++) {
        cpa_wait_all();
        __syncthreads();
        if (t + 1 < 32) attn_issue_kv(sb, (t + 1) & 1, bh, t + 1, tid);

        const uint32_t kb = sb + (t & 1) * 16384;

        // ---- S = Q K^T (log2 domain); x4 loads fetch K for j-pair at once
        float s[8][4];
#pragma unroll
        for (int jp = 0; jp < 4; jp++) {
            const int j0 = 2 * jp, j1 = j0 + 1;
            s[j0][0] = s[j0][1] = s[j0][2] = s[j0][3] = 0.0f;
            s[j1][0] = s[j1][1] = s[j1][2] = s[j1][3] = 0.0f;
            const uint32_t rrow = kb + (uint32_t)(16 * jp + rbase_s) * 128;
#pragma unroll
            for (int kd = 0; kd < 4; kd++) {
                uint32_t k00, k01, k10, k11;
                ldsm_x4(k00, k01, k10, k11, rrow + (((2 * kd + kq) ^ lr8) << 4));
                mma16816(s[j0], qh[kd][0], qh[kd][1], qh[kd][2], qh[kd][3], k00, k01);
                mma16816(s[j1], qh[kd][0], qh[kd][1], qh[kd][2], qh[kd][3], k10, k11);
            }
        }

        // ---- online softmax via exp2 (row max + exponentials)
        float mx0 = -1e30f, mx1 = -1e30f;
#pragma unroll
        for (int j = 0; j < 8; j++) {
            mx0 = fmaxf(mx0, fmaxf(s[j][0], s[j][1]));
            mx1 = fmaxf(mx1, fmaxf(s[j][2], s[j][3]));
        }
        mx0 = fmaxf(mx0, __shfl_xor_sync(0xffffffffu, mx0, 1));
        mx0 = fmaxf(mx0, __shfl_xor_sync(0xffffffffu, mx0, 2));
        mx1 = fmaxf(mx1, __shfl_xor_sync(0xffffffffu, mx1, 1));
        mx1 = fmaxf(mx1, __shfl_xor_sync(0xffffffffu, mx1, 2));
        const float mn0 = fmaxf(m0, mx0), mn1 = fmaxf(m1, mx1);
        const float a0 = ex2f(m0 - mn0), a1 = ex2f(m1 - mn1);
        m0 = mn0; m1 = mn1;

        float rs0 = 0.0f, rs1 = 0.0f;
#pragma unroll
        for (int j = 0; j < 8; j++) {
            s[j][0] = ex2f(s[j][0] - mn0);
            s[j][1] = ex2f(s[j][1] - mn0);
            s[j][2] = ex2f(s[j][2] - mn1);
            s[j][3] = ex2f(s[j][3] - mn1);
            rs0 += s[j][0] + s[j][1];
            rs1 += s[j][2] + s[j][3];
        }
#pragma unroll
        for (int j = 0; j < 8; j++) {
            o[j][0] *= a0; o[j][1] *= a0; o[j][2] *= a1; o[j][3] *= a1;
        }

        // ---- O += P V  (x4 trans loads fetch V for n-pair at once)
#pragma unroll
        for (int kk = 0; kk < 4; kk++) {
            const float* p0 = s[2 * kk];
            const float* p1 = s[2 * kk + 1];
            const uint32_t ah0 = packh(p0[0], p0[1]), ah1 = packh(p0[2], p0[3]);
            const uint32_t ah2 = packh(p1[0], p1[1]), ah3 = packh(p1[2], p1[3]);

            const uint32_t vro = kb + 8192 + (uint32_t)(16 * kk + vrow) * 128;
#pragma unroll
            for (int np = 0; np < 4; np++) {
                const int n0 = 2 * np, n1 = n0 + 1;
                uint32_t v00, v01, v10, v11;
                ldsm_x4_t(v00, v01, v10, v11, vro + (((2 * np + jq) ^ lr8) << 4));
                mma16816(o[n0], ah0, ah1, ah2, ah3, v00, v01);
                mma16816(o[n1], ah0, ah1, ah2, ah3, v10, v11);
            }
        }

        // ---- deferred l-reduction (overlaps with PV tensor work above)
        rs0 += __shfl_xor_sync(0xffffffffu, rs0, 1);
        rs0 += __shfl_xor_sync(0xffffffffu, rs0, 2);
        rs1 += __shfl_xor_sync(0xffffffffu, rs1, 1);
        rs1 += __shfl_xor_sync(0xffffffffu, rs1, 2);
        l0 = l0 * a0 + rs0;
        l1 = l1 * a1 + rs1;
    }

    const float i0 = 1.0f / l0, i1 = 1.0f / l1;
    const size_t ob = ((size_t)bh * SEQ + q0 + wid * 16 + g) * HD;
#pragma unroll
    for (int j = 0; j < 8; j++) {
        const int c0 = 8 * j + 2 * tig;
        *(float2*)(out + ob + c0)          = make_float2(o[j][0] * i0, o[j][1] * i0);
        *(float2*)(out + ob + 8 * HD + c0) = make_float2(o[j][2] * i1, o[j][3] * i1);
    }
    __syncthreads();   // smem safe for next work item
}

// ---------------------------------------------------------------------------
// Fused persistent kernel: work items 0..767 = qkv tiles, 768..1279 = flash.
// ---------------------------------------------------------------------------
__global__ __launch_bounds__(256, 2) void fused(float* __restrict__ out) {
    extern __shared__ char smem[];
    __shared__ int s_w;
    const uint32_t sb = (uint32_t)__cvta_generic_to_shared(smem);
    const int tid = threadIdx.x;

    for (;;) {
        if (tid == 0) s_w = atomicAdd(&g_work, 1);
        __syncthreads();
        const int w = s_w;
        if (w >= 1280) return;
        if (w < 768) qkv_tile(sb, w, tid);
        else         flash_tile(sb, w - 768, out, tid);
    }
}

// ---------------------------------------------------------------------------
extern "C" void kernel_launch(void* const* d_in, const int* in_sizes, int n_in,
                              void* d_out, int out_size) {
    const float* x = (const float*)d_in[0];
    const float* w = (const float*)d_in[1];
    float* out = (float*)d_out;

    cudaFuncSetAttribute(fused, cudaFuncAttributeMaxDynamicSharedMemorySize, FUSED_SMEM);

    presplit<<<1024, 256>>>(x, w);
    fused<<<296, 256, FUSED_SMEM>>>(out);
}